// round 6
// baseline (speedup 1.0000x reference)
#include <cuda_runtime.h>
#include <math.h>
#include <stdint.h>

// ---------------------------------------------------------------------------
// Problem constants
// ---------------------------------------------------------------------------
#define T_ 512
#define B_ 128
#define D_ 256
#define H_ 1024      // main hidden
#define HHYP 256     // hyper hidden
#define H4 4096      // 4*H
#define HH4 1024     // 4*HHYP
#define NOUT 128
#define MODN 12288   // 8*H (sc) + 4*H (badj)
#define NREC 5120    // 4096 main rows + 1024 hyper rows
#define RECK 1280    // state length = H + HHYP
#define EPSLN 1e-3f

#define G_ 296       // launched CTAs; design does NOT require co-residency
#define NT_ 256

// phase tiling (BM=128, BN=64, K-chunk 64 -> 4 BK iters of 16)
#define P1_TILES 1280          // 80 n-tiles * 16 k-splits  (K=1024)
#define P1S 16                 // slabs
#define P3_MODT 768            // 192 n-tiles * 4 k-splits  (K=256)
#define MODS 4
#define P3_RHHT 64             // 16 n-tiles * 4 k-splits   (K=256)
#define RHHS 4
#define P3_TILES (P3_MODT + P3_RHHT)
#define NPH 4

#define RECSLAB ((size_t)B_ * NREC)
#define MODSLAB ((size_t)B_ * MODN)

// ---------------------------------------------------------------------------
// Device scratch (static __device__ arrays: allocation-free kernel_launch)
// ---------------------------------------------------------------------------
__device__ alignas(16) float g_XW[(size_t)T_ * B_ * H4];     // 1 GiB
__device__ alignas(16) float g_hypX[(size_t)T_ * B_ * HH4];  // 256 MiB
__device__ alignas(16) float g_Mcat[(size_t)HHYP * MODN];
__device__ alignas(16) float g_csc[8 * H_];
__device__ alignas(16) float g_state[B_ * RECK];             // [h | hyp]
__device__ alignas(16) float g_c[B_ * H_];
__device__ alignas(16) float g_ch[B_ * HHYP];
__device__ alignas(16) float g_recP1[(size_t)P1S * RECSLAB]; // 42 MiB
__device__ alignas(16) float g_modS[(size_t)MODS * MODSLAB]; // 25 MiB
__device__ alignas(16) float g_recHH[2 * RHHS * B_ * HH4];   // parity double buffer

// dataflow state: per-(step,phase) ticket + done counters, +1 slot for FC
__device__ unsigned g_tix[T_ * NPH + 1];
__device__ unsigned g_done[T_ * NPH + 1];

// ---------------------------------------------------------------------------
// Generic tiled SGEMM for SETUP only (big parallel GEMMs, separate launches)
// ---------------------------------------------------------------------------
template <int BM, int BN, int BK, int TM, int TN, bool BT>
__global__ __launch_bounds__(256) void gemm_k(
    int K, const float* __restrict__ A, int lda,
    const float* __restrict__ Bm, int ldb,
    float* __restrict__ C, int ldc)
{
    const int n0 = blockIdx.x * BN;
    const int m0 = blockIdx.y * BM;
    A += (size_t)m0 * lda;
    if (BT) Bm += (size_t)n0 * ldb;
    else    Bm += n0;
    C += (size_t)m0 * ldc + n0;

    __shared__ float As[BK][BM + 4];
    __shared__ float Bs[BK][BN + 4];
    const int tid = threadIdx.x;
    const int tx = tid % (BN / TN);
    const int ty = tid / (BN / TN);

    float acc[TM][TN];
#pragma unroll
    for (int i = 0; i < TM; i++)
#pragma unroll
        for (int j = 0; j < TN; j++) acc[i][j] = 0.f;

    for (int kt = 0; kt < K; kt += BK) {
#pragma unroll
        for (int l = 0; l < (BM * BK) / (256 * 4); l++) {
            int idx = tid + l * 256;
            int r = idx / (BK / 4);
            int c4 = idx % (BK / 4);
            float4 v = *(const float4*)(A + (size_t)r * lda + c4 * 4);
            As[c4 * 4 + 0][r] = v.x; As[c4 * 4 + 1][r] = v.y;
            As[c4 * 4 + 2][r] = v.z; As[c4 * 4 + 3][r] = v.w;
        }
        if (BT) {
#pragma unroll
            for (int l = 0; l < (BN * BK) / (256 * 4); l++) {
                int idx = tid + l * 256;
                int r = idx / (BK / 4);
                int c4 = idx % (BK / 4);
                float4 v = *(const float4*)(Bm + (size_t)r * ldb + c4 * 4);
                Bs[c4 * 4 + 0][r] = v.x; Bs[c4 * 4 + 1][r] = v.y;
                Bs[c4 * 4 + 2][r] = v.z; Bs[c4 * 4 + 3][r] = v.w;
            }
        } else {
#pragma unroll
            for (int l = 0; l < (BN * BK) / (256 * 4); l++) {
                int idx = tid + l * 256;
                int r = idx / (BN / 4);
                int c4 = idx % (BN / 4);
                float4 v = *(const float4*)(Bm + (size_t)r * ldb + c4 * 4);
                *(float4*)&Bs[r][c4 * 4] = v;
            }
        }
        __syncthreads();
#pragma unroll
        for (int k = 0; k < BK; k++) {
            float a[TM], bv[TN];
#pragma unroll
            for (int i = 0; i < TM; i += 4) {
                float4 v = *(const float4*)&As[k][ty * TM + i];
                a[i] = v.x; a[i + 1] = v.y; a[i + 2] = v.z; a[i + 3] = v.w;
            }
#pragma unroll
            for (int j = 0; j < TN; j += 4) {
                float4 v = *(const float4*)&Bs[k][tx * TN + j];
                bv[j] = v.x; bv[j + 1] = v.y; bv[j + 2] = v.z; bv[j + 3] = v.w;
            }
#pragma unroll
            for (int i = 0; i < TM; i++)
#pragma unroll
                for (int j = 0; j < TN; j++)
                    acc[i][j] = fmaf(a[i], bv[j], acc[i][j]);
        }
        __syncthreads();
        A += BK;
        if (BT) Bm += BK; else Bm += (size_t)BK * ldb;
    }
#pragma unroll
    for (int i = 0; i < TM; i++) {
        float4 o; o.x = acc[i][0]; o.y = acc[i][1]; o.z = acc[i][2]; o.w = acc[i][3];
        *(float4*)(C + (size_t)(ty * TM + i) * ldc + tx * TN) = o;
    }
}

// ---------------------------------------------------------------------------
// Setup kernels
// ---------------------------------------------------------------------------
__global__ void init_k()
{
    size_t i = (size_t)blockIdx.x * 256 + threadIdx.x;
    if (i < (size_t)B_ * RECK) g_state[i] = 0.f;
    if (i < (size_t)B_ * H_)   g_c[i] = 0.f;
    if (i < (size_t)B_ * HHYP) g_ch[i] = 0.f;
    if (i < (size_t)2 * RHHS * B_ * HH4) g_recHH[i] = 0.f;
    if (i < (size_t)(T_ * NPH + 1)) { g_tix[i] = 0u; g_done[i] = 0u; }
}

__global__ void csc_k(const float* __restrict__ zw_b, const float* __restrict__ alpha)
{
    int k = blockIdx.x;                       // 0..7
    int h = blockIdx.y * 256 + threadIdx.x;   // 0..1023
    float s = 0.f;
    const float* zb = zw_b + (size_t)k * HHYP;
    const float* al = alpha + (size_t)k * HHYP * H_;
    for (int p = 0; p < HHYP; p++) s = fmaf(zb[p], al[(size_t)p * H_ + h], s);
    g_csc[k * H_ + h] = s;
}

// ---------------------------------------------------------------------------
// Persistent-kernel helpers
// ---------------------------------------------------------------------------
__device__ __forceinline__ float sigf(float x) { return 1.f / (1.f + expf(-x)); }

__device__ __forceinline__ float block_sum256(float v, float* sbuf)
{
    const int tid = threadIdx.x;
#pragma unroll
    for (int o = 16; o > 0; o >>= 1) v += __shfl_xor_sync(0xffffffffu, v, o);
    const int warp = tid >> 5, lane = tid & 31;
    if (lane == 0) sbuf[warp] = v;
    __syncthreads();
    float s = (tid < 8) ? sbuf[tid] : 0.f;
    if (warp == 0) {
#pragma unroll
        for (int o = 4; o > 0; o >>= 1) s += __shfl_xor_sync(0xffffffffu, s, o);
        if (lane == 0) sbuf[0] = s;
    }
    __syncthreads();
    float r = sbuf[0];
    __syncthreads();
    return r;
}

// grab a work ticket (whole-CTA). returns -1 when phase exhausted.
__device__ __forceinline__ int grab(unsigned* ctr, unsigned limit, unsigned* s_tile)
{
    __syncthreads();
    if (threadIdx.x == 0) *s_tile = atomicAdd(ctr, 1u);
    __syncthreads();
    unsigned k = *s_tile;
    return (k < limit) ? (int)k : -1;
}

// mark one unit of work complete (whole-CTA; canonical fence pattern)
__device__ __forceinline__ void mark(unsigned* cnt)
{
    __threadfence();
    __syncthreads();
    if (threadIdx.x == 0) atomicAdd(cnt, 1u);
}

// wait until a phase's done counter reaches target. Late CTAs pass instantly.
__device__ __forceinline__ void gate(const unsigned* cnt, unsigned target)
{
    if (threadIdx.x == 0) {
        while (*(volatile const unsigned*)cnt < target) __nanosleep(128);
        __threadfence();
    }
    __syncthreads();
}

// GEMM tile: BM=128(batch), BN=64, BK=16, KIT BK-iterations. A = g_state (ldcg).
template <bool BT, int KIT>
__device__ __forceinline__ void gtile(
    float (*sA)[132], float (*sB)[68],
    const float* A, const float* Bm, int ldb,
    float* C, int ldc)
{
    const int tid = threadIdx.x;
    const int tx = tid & 15;   // 16 cols of 4
    const int ty = tid >> 4;   // 16 rows of 8
    float acc[8][4];
#pragma unroll
    for (int i = 0; i < 8; i++)
#pragma unroll
        for (int j = 0; j < 4; j++) acc[i][j] = 0.f;

#pragma unroll
    for (int it = 0; it < KIT; it++) {
#pragma unroll
        for (int l = 0; l < 2; l++) {
            int idx = tid + l * 256;
            int r = idx >> 2;
            int c4 = (idx & 3) * 4;
            float4 v = __ldcg((const float4*)(A + (size_t)r * RECK + c4));
            sA[c4 + 0][r] = v.x; sA[c4 + 1][r] = v.y;
            sA[c4 + 2][r] = v.z; sA[c4 + 3][r] = v.w;
        }
        if (BT) {
            int r = tid >> 2;            // 0..63 (n)
            int c4 = (tid & 3) * 4;      // k
            float4 v = *(const float4*)(Bm + (size_t)r * ldb + c4);
            sB[c4 + 0][r] = v.x; sB[c4 + 1][r] = v.y;
            sB[c4 + 2][r] = v.z; sB[c4 + 3][r] = v.w;
        } else {
            int r = tid >> 4;            // 0..15 (k)
            int c4 = (tid & 15) * 4;     // n
            float4 v = *(const float4*)(Bm + (size_t)r * ldb + c4);
            *(float4*)&sB[r][c4] = v;
        }
        __syncthreads();
#pragma unroll
        for (int k = 0; k < 16; k++) {
            float a[8], bv[4];
            float4 va0 = *(const float4*)&sA[k][ty * 8];
            float4 va1 = *(const float4*)&sA[k][ty * 8 + 4];
            a[0] = va0.x; a[1] = va0.y; a[2] = va0.z; a[3] = va0.w;
            a[4] = va1.x; a[5] = va1.y; a[6] = va1.z; a[7] = va1.w;
            float4 vb = *(const float4*)&sB[k][tx * 4];
            bv[0] = vb.x; bv[1] = vb.y; bv[2] = vb.z; bv[3] = vb.w;
#pragma unroll
            for (int i = 0; i < 8; i++)
#pragma unroll
                for (int j = 0; j < 4; j++)
                    acc[i][j] = fmaf(a[i], bv[j], acc[i][j]);
        }
        __syncthreads();
        A += 16;
        Bm += BT ? 16 : 16 * ldb;
    }
#pragma unroll
    for (int i = 0; i < 8; i++) {
        float4 o; o.x = acc[i][0]; o.y = acc[i][1]; o.z = acc[i][2]; o.w = acc[i][3];
        *(float4*)(C + (size_t)(ty * 8 + i) * ldc + tx * 4) = o;
    }
}

// ---------------------------------------------------------------------------
// Persistent kernel: whole T=512 recurrence + final FC.
// Work-stealing tickets + completion-counter gates: deadlock-free under ANY
// number of concurrently resident CTAs (no grid barrier, no residency需求).
// ---------------------------------------------------------------------------
__global__ __launch_bounds__(NT_, 2) void hyperlstm_persist(
    const float* __restrict__ Wh, const float* __restrict__ hypWx,
    const float* __restrict__ hypWh,
    const float* __restrict__ hypbx, const float* __restrict__ hypbh,
    const float* __restrict__ hlnag, const float* __restrict__ hlnab,
    const float* __restrict__ hlng, const float* __restrict__ hlnb,
    const float* __restrict__ bias,
    const float* __restrict__ lnag, const float* __restrict__ lnab,
    const float* __restrict__ lng, const float* __restrict__ lnb,
    const float* __restrict__ fcW, const float* __restrict__ fcb,
    float* __restrict__ out)
{
    __shared__ float sA[16][132];
    __shared__ float sB[16][68];
    __shared__ float sred[32];
    __shared__ unsigned s_tile;

    const int tid = threadIdx.x;

    for (int t = 0; t < T_; t++) {
        unsigned* tixP1 = &g_tix[t * NPH + 0];
        unsigned* tixP2 = &g_tix[t * NPH + 1];
        unsigned* tixP3 = &g_tix[t * NPH + 2];
        unsigned* tixP4 = &g_tix[t * NPH + 3];
        unsigned* donP1 = &g_done[t * NPH + 0];
        unsigned* donP2 = &g_done[t * NPH + 1];
        unsigned* donP3 = &g_done[t * NPH + 2];
        unsigned* donP4 = &g_done[t * NPH + 3];

        // ----- P1: rec GEMM from h : N=5120, K=1024 (needs h(t-1) complete) -----
        if (t > 0) gate(&g_done[(t - 1) * NPH + 3], B_);
        for (;;) {
            int k = grab(tixP1, P1_TILES, &s_tile);
            if (k < 0) break;
            int ntile = k >> 4, ks = k & 15;
            int n0 = ntile * 64, kb = ks * 64;
            const float* A = g_state + kb;
            const float* Bp; int ldb;
            if (n0 < H4) { Bp = Wh + (size_t)n0 * H_ + kb; ldb = H_; }
            else { Bp = hypWx + (size_t)(n0 - H4) * (D_ + H_) + D_ + kb; ldb = D_ + H_; }
            float* C = g_recP1 + (size_t)ks * RECSLAB + n0;
            gtile<true, 4>(sA, sB, A, Bp, ldb, C, NREC);
            mark(donP1);
        }
        gate(donP1, P1_TILES);

        // ----- P2: hyper cell (128 batch tickets) -----
        for (;;) {
            int b = grab(tixP2, B_, &s_tile);
            if (b < 0) break;
            const int j = tid;
            const int par = t & 1;
            const float* hx = g_hypX + ((size_t)t * B_ + b) * HH4;
            float v[4];
#pragma unroll
            for (int gk = 0; gk < 4; gk++) {
                int n = gk * HHYP + j;
                float s = hx[n] + hypbx[n] + hypbh[n];
#pragma unroll
                for (int sl = 0; sl < P1S; sl++)
                    s += __ldcg(&g_recP1[(size_t)sl * RECSLAB + (size_t)b * NREC + H4 + n]);
#pragma unroll
                for (int sl = 0; sl < RHHS; sl++)
                    s += __ldcg(&g_recHH[((size_t)par * RHHS + sl) * (B_ * HH4) + (size_t)b * HH4 + n]);
                v[gk] = s;
            }
            float nv[4];
#pragma unroll
            for (int gk = 0; gk < 4; gk++) {
                float m = block_sum256(v[gk], sred) * (1.f / 256.f);
                float xs = v[gk] - m;
                float var = block_sum256(xs * xs, sred) * (1.f / 256.f);
                int n = gk * HHYP + j;
                nv[gk] = hlnag[n] * (xs * rsqrtf(var + EPSLN)) + hlnab[n];
            }
            float ch = __ldcg(&g_ch[b * HHYP + j]);
            float chn = sigf(nv[1]) * ch + sigf(nv[0]) * tanhf(nv[2]);
            float m = block_sum256(chn, sred) * (1.f / 256.f);
            float xs = chn - m;
            float var = block_sum256(xs * xs, sred) * (1.f / 256.f);
            float hn = hlng[j] * (xs * rsqrtf(var + EPSLN)) + hlnb[j];
            float hyp = sigf(nv[3]) * tanhf(hn);
            g_ch[b * HHYP + j] = chn;
            g_state[(size_t)b * RECK + H_ + j] = hyp;
            mark(donP2);
        }
        gate(donP2, B_);

        // ----- P3: mod GEMM (hyp@Mcat) + next-step rec-hh (hyp@hypWh^T) -----
        {
            const int parN = (t + 1) & 1;
            for (;;) {
                int k = grab(tixP3, P3_TILES, &s_tile);
                if (k < 0) break;
                if (k < P3_MODT) {
                    int ntile = k >> 2, ks = k & 3;
                    int n0 = ntile * 64, kb = ks * 64;
                    const float* A = g_state + H_ + kb;
                    const float* Bp = g_Mcat + (size_t)kb * MODN + n0;
                    float* C = g_modS + (size_t)ks * MODSLAB + n0;
                    gtile<false, 4>(sA, sB, A, Bp, MODN, C, MODN);
                } else {
                    int k2 = k - P3_MODT;
                    int ntile = k2 >> 2, ks = k2 & 3;
                    int n0 = ntile * 64, kb = ks * 64;
                    const float* A = g_state + H_ + kb;
                    const float* Bp = hypWh + (size_t)n0 * HHYP + kb;
                    float* C = g_recHH + ((size_t)parN * RHHS + ks) * (B_ * HH4) + n0;
                    gtile<true, 4>(sA, sB, A, Bp, HHYP, C, HH4);
                }
                mark(donP3);
            }
        }
        gate(donP3, P3_TILES);

        // ----- P4: main cell (128 batch tickets) -----
        for (;;) {
            int b = grab(tixP4, B_, &s_tile);
            if (b < 0) break;
            const int j = tid;
            const float* xw = g_XW + ((size_t)t * B_ + b) * H4;
            float pre[4][4];
#pragma unroll
            for (int gk = 0; gk < 4; gk++) {
#pragma unroll
                for (int q = 0; q < 4; q++) {
                    int n = gk * H_ + q * 256 + j;
                    float hg = 0.f;
#pragma unroll
                    for (int sl = 0; sl < P1S; sl++)
                        hg += __ldcg(&g_recP1[(size_t)sl * RECSLAB + (size_t)b * NREC + n]);
                    float sx = 0.f, sh = 0.f, ba = 0.f;
#pragma unroll
                    for (int sl = 0; sl < MODS; sl++) {
                        const float* mp = g_modS + (size_t)sl * MODSLAB + (size_t)b * MODN;
                        sx += __ldcg(&mp[n]);
                        sh += __ldcg(&mp[4 * H_ + n]);
                        ba += __ldcg(&mp[8 * H_ + n]);
                    }
                    sx += g_csc[n];
                    sh += g_csc[4 * H_ + n];
                    pre[gk][q] = fmaf(sx, xw[n], fmaf(sh, hg, bias[n] + ba));
                }
            }
            float nv[4][4];
#pragma unroll
            for (int gk = 0; gk < 4; gk++) {
                float p = pre[gk][0] + pre[gk][1] + pre[gk][2] + pre[gk][3];
                float m = block_sum256(p, sred) * (1.f / 1024.f);
                float vs = 0.f;
#pragma unroll
                for (int q = 0; q < 4; q++) { float d = pre[gk][q] - m; vs += d * d; }
                float var = block_sum256(vs, sred) * (1.f / 1024.f);
                float rs = rsqrtf(var + EPSLN);
#pragma unroll
                for (int q = 0; q < 4; q++) {
                    int n = gk * H_ + q * 256 + j;
                    nv[gk][q] = lnag[n] * ((pre[gk][q] - m) * rs) + lnab[n];
                }
            }
            float cn[4];
            float psum = 0.f;
#pragma unroll
            for (int q = 0; q < 4; q++) {
                int idx = q * 256 + j;
                float c = __ldcg(&g_c[b * H_ + idx]);
                cn[q] = sigf(nv[2][q]) * c + sigf(nv[0][q]) * tanhf(nv[1][q]);
                g_c[b * H_ + idx] = cn[q];
                psum += cn[q];
            }
            float m = block_sum256(psum, sred) * (1.f / 1024.f);
            float vs = 0.f;
#pragma unroll
            for (int q = 0; q < 4; q++) { float d = cn[q] - m; vs += d * d; }
            float var = block_sum256(vs, sred) * (1.f / 1024.f);
            float rs = rsqrtf(var + EPSLN);
#pragma unroll
            for (int q = 0; q < 4; q++) {
                int idx = q * 256 + j;
                float lc = lng[idx] * ((cn[q] - m) * rs) + lnb[idx];
                float h = sigf(nv[3][q]) * tanhf(lc);
                g_state[(size_t)b * RECK + idx] = h;
            }
            mark(donP4);
        }
    }

    // ----- final FC: out = h @ fcW^T + fcb (128 batch tickets) -----
    gate(&g_done[(T_ - 1) * NPH + 3], B_);
    for (;;) {
        int b = grab(&g_tix[T_ * NPH], B_, &s_tile);
        if (b < 0) break;
        float* sh = &sA[0][0];    // 1024 floats of the 2112-float sA buffer
        float* sp = &sB[0][0];    // 256 floats of the 1088-float sB buffer
        for (int i = tid; i < H_; i += NT_) sh[i] = __ldcg(&g_state[(size_t)b * RECK + i]);
        __syncthreads();
        int o = tid & 127, half = tid >> 7;
        const float* w = fcW + (size_t)o * H_ + half * 512;
        const float* hv = sh + half * 512;
        float s = 0.f;
        for (int k = 0; k < 512; k++) s = fmaf(hv[k], w[k], s);
        sp[tid] = s;
        __syncthreads();
        if (tid < NOUT)
            out[(size_t)b * NOUT + tid] = sp[tid] + sp[128 + tid] + fcb[tid];
        __syncthreads();
    }
}

// ---------------------------------------------------------------------------
// Launch
// ---------------------------------------------------------------------------
extern "C" void kernel_launch(void* const* d_in, const int* in_sizes, int n_in,
                              void* d_out, int out_size)
{
    const float* x      = (const float*)d_in[0];
    const float* Wx     = (const float*)d_in[1];
    const float* Wh     = (const float*)d_in[2];
    const float* bias   = (const float*)d_in[3];
    const float* lnag   = (const float*)d_in[4];
    const float* lnab   = (const float*)d_in[5];
    const float* lng    = (const float*)d_in[6];
    const float* lnb    = (const float*)d_in[7];
    const float* zb     = (const float*)d_in[8];
    const float* zbeta  = (const float*)d_in[9];
    const float* zw_w   = (const float*)d_in[10];
    const float* zw_b   = (const float*)d_in[11];
    const float* alpha  = (const float*)d_in[12];
    const float* hypWx  = (const float*)d_in[13];
    const float* hypbx  = (const float*)d_in[14];
    const float* hypWh  = (const float*)d_in[15];
    const float* hypbh  = (const float*)d_in[16];
    const float* hlnag  = (const float*)d_in[17];
    const float* hlnab  = (const float*)d_in[18];
    const float* hlng   = (const float*)d_in[19];
    const float* hlnb   = (const float*)d_in[20];
    const float* fc_W   = (const float*)d_in[21];
    const float* fc_b   = (const float*)d_in[22];
    float* out = (float*)d_out;

    float *pXW, *pHX, *pMcat;
    cudaGetSymbolAddress((void**)&pXW, g_XW);
    cudaGetSymbolAddress((void**)&pHX, g_hypX);
    cudaGetSymbolAddress((void**)&pMcat, g_Mcat);

    // ---- setup ----
    init_k<<<(2 * RHHS * B_ * HH4 + 255) / 256, 256>>>();
    csc_k<<<dim3(8, 4), 256>>>(zw_b, alpha);

    // Mcat: 12 GEMMs (256 x 1024 x 256), NN layout
    for (int s = 0; s < 12; s++) {
        const float* Am = (s < 8) ? zw_w + (size_t)s * HHYP * HHYP
                                  : zb + (size_t)(s - 8) * HHYP * HHYP;
        const float* Bn = (s < 8) ? alpha + (size_t)s * HHYP * H_
                                  : zbeta + (size_t)(s - 8) * HHYP * H_;
        gemm_k<128, 64, 16, 8, 4, false><<<dim3(16, 2), 256>>>(
            HHYP, Am, HHYP, Bn, H_, pMcat + s * H_, MODN);
    }

    // XW = x @ Wx^T : (65536, 4096, K=256)
    gemm_k<128, 64, 16, 8, 4, true><<<dim3(H4 / 64, (T_ * B_) / 128), 256>>>(
        D_, x, D_, Wx, D_, pXW, H4);
    // hypX = x @ hyp_Wx[:, :256]^T : (65536, 1024, K=256)
    gemm_k<128, 64, 16, 8, 4, true><<<dim3(HH4 / 64, (T_ * B_) / 128), 256>>>(
        D_, x, D_, hypWx, D_ + H_, pHX, HH4);

    // ---- whole recurrence + final FC in ONE residency-oblivious kernel ----
    hyperlstm_persist<<<G_, NT_>>>(
        Wh, hypWx, hypWh, hypbx, hypbh, hlnag, hlnab, hlng, hlnb,
        bias, lnag, lnab, lng, lnb, fc_W, fc_b, out);
}

// round 10
// speedup vs baseline: 1.4923x; 1.4923x over previous
#include <cuda_runtime.h>
#include <cuda_bf16.h>
#include <math.h>
#include <stdint.h>

// ---------------------------------------------------------------------------
// Problem constants
// ---------------------------------------------------------------------------
#define T_ 512
#define B_ 128
#define D_ 256
#define H_ 1024      // main hidden
#define HHYP 256     // hyper hidden
#define H4 4096      // 4*H
#define HH4 1024     // 4*HHYP
#define NOUT 128
#define MODN 12288   // 8*H (sc) + 4*H (badj)
#define NREC 5120    // 4096 main rows + 1024 hyper rows
#define RECK 1280    // state length = H + HHYP
#define EPSLN 1e-3f

#define G_ 296       // launched CTAs; design does NOT require co-residency
#define NT_ 256

// phase tiling (BM=128, BN=64, k-extent 64 per ticket, processed as 2x32)
#define P1_TILES 1280          // 80 n-tiles * 16 k-splits  (K=1024)
#define P1S 16                 // slabs
#define P3_MODT 768            // 192 n-tiles * 4 k-splits  (K=256)
#define MODS 4
#define P3_RHHT 64             // 16 n-tiles * 4 k-splits   (K=256)
#define RHHS 4
#define P3_TILES (P3_MODT + P3_RHHT)
#define NPH 4

#define RECSLAB ((size_t)B_ * NREC)
#define MODSLAB ((size_t)B_ * MODN)

#define KP 40   // smem row pitch (bf16 elems) for 32-wide k chunks

// ---------------------------------------------------------------------------
// Device scratch
// ---------------------------------------------------------------------------
__device__ alignas(16) float g_XW[(size_t)T_ * B_ * H4];     // 1 GiB
__device__ alignas(16) float g_hypX[(size_t)T_ * B_ * HH4];  // 256 MiB
__device__ alignas(16) float g_Mcat[(size_t)HHYP * MODN];
__device__ alignas(16) float g_csc[8 * H_];
__device__ alignas(16) float g_state[B_ * RECK];             // fp32 [h | hyp]
__device__ alignas(16) float g_c[B_ * H_];
__device__ alignas(16) float g_ch[B_ * HHYP];
__device__ alignas(16) float g_recP1[(size_t)P1S * RECSLAB]; // 42 MiB
__device__ alignas(16) float g_modS[(size_t)MODS * MODSLAB]; // 25 MiB
__device__ alignas(16) float g_recHH[2 * RHHS * B_ * HH4];   // parity double buffer

// bf16 hi/lo planes
__device__ alignas(16) __nv_bfloat16 g_sthi[B_ * RECK];
__device__ alignas(16) __nv_bfloat16 g_stlo[B_ * RECK];
__device__ alignas(16) __nv_bfloat16 g_W1hi[(size_t)NREC * H_];   // [n][k] packed Wh | hypWx_h
__device__ alignas(16) __nv_bfloat16 g_W1lo[(size_t)NREC * H_];
__device__ alignas(16) __nv_bfloat16 g_WHhi[(size_t)HH4 * HHYP];  // hypWh [n][k]
__device__ alignas(16) __nv_bfloat16 g_WHlo[(size_t)HH4 * HHYP];
__device__ alignas(16) __nv_bfloat16 g_Mthi[(size_t)MODN * HHYP]; // Mcat^T [n][k]
__device__ alignas(16) __nv_bfloat16 g_Mtlo[(size_t)MODN * HHYP];

// dataflow state
__device__ unsigned g_tix[T_ * NPH + 1];
__device__ unsigned g_done[T_ * NPH + 1];

// ---------------------------------------------------------------------------
// fp32 tiled SGEMM for SETUP
// ---------------------------------------------------------------------------
template <int BM, int BN, int BK, int TM, int TN, bool BT>
__global__ __launch_bounds__(256) void gemm_k(
    int K, const float* __restrict__ A, int lda,
    const float* __restrict__ Bm, int ldb,
    float* __restrict__ C, int ldc)
{
    const int n0 = blockIdx.x * BN;
    const int m0 = blockIdx.y * BM;
    A += (size_t)m0 * lda;
    if (BT) Bm += (size_t)n0 * ldb;
    else    Bm += n0;
    C += (size_t)m0 * ldc + n0;

    __shared__ float As[BK][BM + 4];
    __shared__ float Bs[BK][BN + 4];
    const int tid = threadIdx.x;
    const int tx = tid % (BN / TN);
    const int ty = tid / (BN / TN);

    float acc[TM][TN];
#pragma unroll
    for (int i = 0; i < TM; i++)
#pragma unroll
        for (int j = 0; j < TN; j++) acc[i][j] = 0.f;

    for (int kt = 0; kt < K; kt += BK) {
#pragma unroll
        for (int l = 0; l < (BM * BK) / (256 * 4); l++) {
            int idx = tid + l * 256;
            int r = idx / (BK / 4);
            int c4 = idx % (BK / 4);
            float4 v = *(const float4*)(A + (size_t)r * lda + c4 * 4);
            As[c4 * 4 + 0][r] = v.x; As[c4 * 4 + 1][r] = v.y;
            As[c4 * 4 + 2][r] = v.z; As[c4 * 4 + 3][r] = v.w;
        }
        if (BT) {
#pragma unroll
            for (int l = 0; l < (BN * BK) / (256 * 4); l++) {
                int idx = tid + l * 256;
                int r = idx / (BK / 4);
                int c4 = idx % (BK / 4);
                float4 v = *(const float4*)(Bm + (size_t)r * ldb + c4 * 4);
                Bs[c4 * 4 + 0][r] = v.x; Bs[c4 * 4 + 1][r] = v.y;
                Bs[c4 * 4 + 2][r] = v.z; Bs[c4 * 4 + 3][r] = v.w;
            }
        } else {
#pragma unroll
            for (int l = 0; l < (BN * BK) / (256 * 4); l++) {
                int idx = tid + l * 256;
                int r = idx / (BN / 4);
                int c4 = idx % (BN / 4);
                float4 v = *(const float4*)(Bm + (size_t)r * ldb + c4 * 4);
                *(float4*)&Bs[r][c4 * 4] = v;
            }
        }
        __syncthreads();
#pragma unroll
        for (int k = 0; k < BK; k++) {
            float a[TM], bv[TN];
#pragma unroll
            for (int i = 0; i < TM; i += 4) {
                float4 v = *(const float4*)&As[k][ty * TM + i];
                a[i] = v.x; a[i + 1] = v.y; a[i + 2] = v.z; a[i + 3] = v.w;
            }
#pragma unroll
            for (int j = 0; j < TN; j += 4) {
                float4 v = *(const float4*)&Bs[k][tx * TN + j];
                bv[j] = v.x; bv[j + 1] = v.y; bv[j + 2] = v.z; bv[j + 3] = v.w;
            }
#pragma unroll
            for (int i = 0; i < TM; i++)
#pragma unroll
                for (int j = 0; j < TN; j++)
                    acc[i][j] = fmaf(a[i], bv[j], acc[i][j]);
        }
        __syncthreads();
        A += BK;
        if (BT) Bm += BK; else Bm += (size_t)BK * ldb;
    }
#pragma unroll
    for (int i = 0; i < TM; i++) {
        float4 o; o.x = acc[i][0]; o.y = acc[i][1]; o.z = acc[i][2]; o.w = acc[i][3];
        *(float4*)(C + (size_t)(ty * TM + i) * ldc + tx * TN) = o;
    }
}

// ---------------------------------------------------------------------------
// Setup kernels
// ---------------------------------------------------------------------------
__device__ __forceinline__ void split_bf16(float x, __nv_bfloat16& h, __nv_bfloat16& l)
{
    h = __float2bfloat16(x);
    l = __float2bfloat16(x - __bfloat162float(h));
}

__global__ void init_k()
{
    size_t i = (size_t)blockIdx.x * 256 + threadIdx.x;
    if (i < (size_t)B_ * RECK) {
        g_state[i] = 0.f;
        g_sthi[i] = __float2bfloat16(0.f);
        g_stlo[i] = __float2bfloat16(0.f);
    }
    if (i < (size_t)B_ * H_)   g_c[i] = 0.f;
    if (i < (size_t)B_ * HHYP) g_ch[i] = 0.f;
    if (i < (size_t)2 * RHHS * B_ * HH4) g_recHH[i] = 0.f;
    if (i < (size_t)(T_ * NPH + 1)) { g_tix[i] = 0u; g_done[i] = 0u; }
}

__global__ void csc_k(const float* __restrict__ zw_b, const float* __restrict__ alpha)
{
    int k = blockIdx.x;
    int h = blockIdx.y * 256 + threadIdx.x;
    float s = 0.f;
    const float* zb = zw_b + (size_t)k * HHYP;
    const float* al = alpha + (size_t)k * HHYP * H_;
    for (int p = 0; p < HHYP; p++) s = fmaf(zb[p], al[(size_t)p * H_ + h], s);
    g_csc[k * H_ + h] = s;
}

// pack Wh (n<4096) / hypWx h-slice (n>=4096) into [n][k<1024] hi/lo planes
__global__ void convW1_k(const float* __restrict__ Wh, const float* __restrict__ hypWx)
{
    size_t idx = (size_t)blockIdx.x * 256 + threadIdx.x;
    if (idx >= (size_t)NREC * H_) return;
    int n = (int)(idx / H_), k = (int)(idx % H_);
    float v = (n < H4) ? Wh[(size_t)n * H_ + k]
                       : hypWx[(size_t)(n - H4) * (D_ + H_) + D_ + k];
    split_bf16(v, g_W1hi[idx], g_W1lo[idx]);
}

__global__ void convWH_k(const float* __restrict__ hypWh)
{
    size_t idx = (size_t)blockIdx.x * 256 + threadIdx.x;
    if (idx >= (size_t)HH4 * HHYP) return;
    split_bf16(hypWh[idx], g_WHhi[idx], g_WHlo[idx]);
}

// transpose Mcat [k=256][n=12288] -> [n][k] hi/lo planes
__global__ void convMt_k()
{
    size_t idx = (size_t)blockIdx.x * 256 + threadIdx.x;
    if (idx >= (size_t)MODN * HHYP) return;
    int n = (int)(idx / HHYP), k = (int)(idx % HHYP);
    split_bf16(g_Mcat[(size_t)k * MODN + n], g_Mthi[idx], g_Mtlo[idx]);
}

// ---------------------------------------------------------------------------
// Persistent-kernel helpers
// ---------------------------------------------------------------------------
__device__ __forceinline__ float sigf(float x) { return 1.f / (1.f + expf(-x)); }

__device__ __forceinline__ float block_sum256(float v, float* sbuf)
{
    const int tid = threadIdx.x;
#pragma unroll
    for (int o = 16; o > 0; o >>= 1) v += __shfl_xor_sync(0xffffffffu, v, o);
    const int warp = tid >> 5, lane = tid & 31;
    if (lane == 0) sbuf[warp] = v;
    __syncthreads();
    float s = (tid < 8) ? sbuf[tid] : 0.f;
    if (warp == 0) {
#pragma unroll
        for (int o = 4; o > 0; o >>= 1) s += __shfl_xor_sync(0xffffffffu, s, o);
        if (lane == 0) sbuf[0] = s;
    }
    __syncthreads();
    float r = sbuf[0];
    __syncthreads();
    return r;
}

__device__ __forceinline__ int grab(unsigned* ctr, unsigned limit, unsigned* s_tile)
{
    __syncthreads();
    if (threadIdx.x == 0) *s_tile = atomicAdd(ctr, 1u);
    __syncthreads();
    unsigned k = *s_tile;
    return (k < limit) ? (int)k : -1;
}

__device__ __forceinline__ void mark(unsigned* cnt)
{
    __threadfence();
    __syncthreads();
    if (threadIdx.x == 0) atomicAdd(cnt, 1u);
}

__device__ __forceinline__ void gate(const unsigned* cnt, unsigned target)
{
    if (threadIdx.x == 0) {
        while (*(volatile const unsigned*)cnt < target) __nanosleep(128);
        __threadfence();
    }
    __syncthreads();
}

__device__ __forceinline__ void mma16816(float* d, const uint32_t* a, const uint32_t* b)
{
    asm volatile(
        "mma.sync.aligned.m16n8k16.row.col.f32.bf16.bf16.f32 "
        "{%0,%1,%2,%3}, {%4,%5,%6,%7}, {%8,%9}, {%0,%1,%2,%3};\n"
        : "+f"(d[0]), "+f"(d[1]), "+f"(d[2]), "+f"(d[3])
        : "r"(a[0]), "r"(a[1]), "r"(a[2]), "r"(a[3]), "r"(b[0]), "r"(b[1]));
}

// ---------------------------------------------------------------------------
// Tensor GEMM tile: C[128,64] = A[128,64k] * B[64,64k]^T, bf16 hi/lo x3 MMA.
// k-extent 64 processed as two 32-wide chunks through static smem buffers.
// A planes: gmem row pitch RECK (state). B planes: [n][k] row pitch ldbk.
// ---------------------------------------------------------------------------
__device__ void ttile(
    __nv_bfloat16 (*sAh)[KP], __nv_bfloat16 (*sAl)[KP],
    __nv_bfloat16 (*sBh)[KP], __nv_bfloat16 (*sBl)[KP],
    const __nv_bfloat16* gAh, const __nv_bfloat16* gAl,
    const __nv_bfloat16* gBh, const __nv_bfloat16* gBl, int ldbk,
    float* C, int ldc)
{
    const int tid = threadIdx.x;
    const int lane = tid & 31, w = tid >> 5;
    const int wm = w & 3, wn = w >> 2;          // 4 warps M x 2 warps N
    const int g = lane >> 2, tig = lane & 3;

    float acc[2][4][4];
#pragma unroll
    for (int ms = 0; ms < 2; ms++)
#pragma unroll
        for (int ns = 0; ns < 4; ns++)
#pragma unroll
            for (int q = 0; q < 4; q++) acc[ms][ns][q] = 0.f;

#pragma unroll
    for (int ch = 0; ch < 2; ch++) {
        const int kb = ch * 32;
        // ---- load A planes: 128 rows x 32 bf16 = 512 uint4 per plane ----
#pragma unroll
        for (int i = 0; i < 2; i++) {
            int u = tid + i * 256;
            int r = u >> 2, c = (u & 3) * 8;
            *(uint4*)&sAh[r][c] = __ldcg((const uint4*)(gAh + (size_t)r * RECK + kb + c));
            *(uint4*)&sAl[r][c] = __ldcg((const uint4*)(gAl + (size_t)r * RECK + kb + c));
        }
        // ---- load B planes: 64 rows x 32 bf16 = 256 uint4 per plane ----
        {
            int r = tid >> 2, c = (tid & 3) * 8;
            *(uint4*)&sBh[r][c] = *(const uint4*)(gBh + (size_t)r * ldbk + kb + c);
            *(uint4*)&sBl[r][c] = *(const uint4*)(gBl + (size_t)r * ldbk + kb + c);
        }
        __syncthreads();

#pragma unroll
        for (int kk = 0; kk < 2; kk++) {
            const int ko = kk * 16 + tig * 2;
            uint32_t ah[2][4], al[2][4];
#pragma unroll
            for (int ms = 0; ms < 2; ms++) {
                const __nv_bfloat16* ba = &sAh[wm * 32 + ms * 16 + g][0];
                const __nv_bfloat16* bl = &sAl[wm * 32 + ms * 16 + g][0];
                ah[ms][0] = *(const uint32_t*)&ba[ko];
                ah[ms][1] = *(const uint32_t*)&ba[8 * KP + ko];
                ah[ms][2] = *(const uint32_t*)&ba[ko + 8];
                ah[ms][3] = *(const uint32_t*)&ba[8 * KP + ko + 8];
                al[ms][0] = *(const uint32_t*)&bl[ko];
                al[ms][1] = *(const uint32_t*)&bl[8 * KP + ko];
                al[ms][2] = *(const uint32_t*)&bl[ko + 8];
                al[ms][3] = *(const uint32_t*)&bl[8 * KP + ko + 8];
            }
#pragma unroll
            for (int ns = 0; ns < 4; ns++) {
                const __nv_bfloat16* bb = &sBh[wn * 32 + ns * 8 + g][0];
                const __nv_bfloat16* bc = &sBl[wn * 32 + ns * 8 + g][0];
                uint32_t bh[2], blo[2];
                bh[0]  = *(const uint32_t*)&bb[ko];
                bh[1]  = *(const uint32_t*)&bb[ko + 8];
                blo[0] = *(const uint32_t*)&bc[ko];
                blo[1] = *(const uint32_t*)&bc[ko + 8];
#pragma unroll
                for (int ms = 0; ms < 2; ms++) {
                    mma16816(acc[ms][ns], ah[ms], bh);
                    mma16816(acc[ms][ns], ah[ms], blo);
                    mma16816(acc[ms][ns], al[ms], bh);
                }
            }
        }
        __syncthreads();
    }

    // ---- epilogue ----
#pragma unroll
    for (int ms = 0; ms < 2; ms++) {
#pragma unroll
        for (int ns = 0; ns < 4; ns++) {
            int row0 = wm * 32 + ms * 16 + g;
            int col = wn * 32 + ns * 8 + tig * 2;
            float2 v0; v0.x = acc[ms][ns][0]; v0.y = acc[ms][ns][1];
            float2 v1; v1.x = acc[ms][ns][2]; v1.y = acc[ms][ns][3];
            *(float2*)&C[(size_t)row0 * ldc + col] = v0;
            *(float2*)&C[(size_t)(row0 + 8) * ldc + col] = v1;
        }
    }
}

// ---------------------------------------------------------------------------
// Persistent kernel: whole T=512 recurrence + final FC.
// Static shared only (~31 KB): no dynamic smem, no attribute changes.
// ---------------------------------------------------------------------------
__global__ __launch_bounds__(NT_, 2) void hyperlstm_persist(
    const float* __restrict__ hypbx, const float* __restrict__ hypbh,
    const float* __restrict__ hlnag, const float* __restrict__ hlnab,
    const float* __restrict__ hlng, const float* __restrict__ hlnb,
    const float* __restrict__ bias,
    const float* __restrict__ lnag, const float* __restrict__ lnab,
    const float* __restrict__ lng, const float* __restrict__ lnb,
    const float* __restrict__ fcW, const float* __restrict__ fcb,
    float* __restrict__ out)
{
    __shared__ __align__(16) __nv_bfloat16 sAh[128][KP];
    __shared__ __align__(16) __nv_bfloat16 sAl[128][KP];
    __shared__ __align__(16) __nv_bfloat16 sBh[64][KP];
    __shared__ __align__(16) __nv_bfloat16 sBl[64][KP];
    __shared__ float sred[32];
    __shared__ unsigned s_tile;

    const int tid = threadIdx.x;

    for (int t = 0; t < T_; t++) {
        unsigned* tixP1 = &g_tix[t * NPH + 0];
        unsigned* tixP2 = &g_tix[t * NPH + 1];
        unsigned* tixP3 = &g_tix[t * NPH + 2];
        unsigned* tixP4 = &g_tix[t * NPH + 3];
        unsigned* donP1 = &g_done[t * NPH + 0];
        unsigned* donP2 = &g_done[t * NPH + 1];
        unsigned* donP3 = &g_done[t * NPH + 2];
        unsigned* donP4 = &g_done[t * NPH + 3];

        // ----- P1: rec GEMM from h : N=5120, K=1024 (tensor) -----
        if (t > 0) gate(&g_done[(t - 1) * NPH + 3], B_);
        for (;;) {
            int k = grab(tixP1, P1_TILES, &s_tile);
            if (k < 0) break;
            int ntile = k >> 4, ks = k & 15;
            int n0 = ntile * 64, kb = ks * 64;
            ttile(sAh, sAl, sBh, sBl,
                  g_sthi + kb, g_stlo + kb,
                  g_W1hi + (size_t)n0 * H_ + kb, g_W1lo + (size_t)n0 * H_ + kb, H_,
                  g_recP1 + (size_t)ks * RECSLAB + n0, NREC);
            mark(donP1);
        }
        gate(donP1, P1_TILES);

        // ----- P2: hyper cell -----
        for (;;) {
            int b = grab(tixP2, B_, &s_tile);
            if (b < 0) break;
            const int j = tid;
            const int par = t & 1;
            const float* hx = g_hypX + ((size_t)t * B_ + b) * HH4;
            float v[4];
#pragma unroll
            for (int gk = 0; gk < 4; gk++) {
                int n = gk * HHYP + j;
                float s = hx[n] + hypbx[n] + hypbh[n];
#pragma unroll
                for (int sl = 0; sl < P1S; sl++)
                    s += __ldcg(&g_recP1[(size_t)sl * RECSLAB + (size_t)b * NREC + H4 + n]);
#pragma unroll
                for (int sl = 0; sl < RHHS; sl++)
                    s += __ldcg(&g_recHH[((size_t)par * RHHS + sl) * (B_ * HH4) + (size_t)b * HH4 + n]);
                v[gk] = s;
            }
            float nv[4];
#pragma unroll
            for (int gk = 0; gk < 4; gk++) {
                float m = block_sum256(v[gk], sred) * (1.f / 256.f);
                float xs = v[gk] - m;
                float var = block_sum256(xs * xs, sred) * (1.f / 256.f);
                int n = gk * HHYP + j;
                nv[gk] = hlnag[n] * (xs * rsqrtf(var + EPSLN)) + hlnab[n];
            }
            float ch = __ldcg(&g_ch[b * HHYP + j]);
            float chn = sigf(nv[1]) * ch + sigf(nv[0]) * tanhf(nv[2]);
            float m = block_sum256(chn, sred) * (1.f / 256.f);
            float xs = chn - m;
            float var = block_sum256(xs * xs, sred) * (1.f / 256.f);
            float hn = hlng[j] * (xs * rsqrtf(var + EPSLN)) + hlnb[j];
            float hyp = sigf(nv[3]) * tanhf(hn);
            g_ch[b * HHYP + j] = chn;
            size_t sidx = (size_t)b * RECK + H_ + j;
            g_state[sidx] = hyp;
            __nv_bfloat16 hh, hl; split_bf16(hyp, hh, hl);
            g_sthi[sidx] = hh; g_stlo[sidx] = hl;
            mark(donP2);
        }
        gate(donP2, B_);

        // ----- P3: mod GEMM + next-step rec-hh (tensor) -----
        {
            const int parN = (t + 1) & 1;
            for (;;) {
                int k = grab(tixP3, P3_TILES, &s_tile);
                if (k < 0) break;
                if (k < P3_MODT) {
                    int ntile = k >> 2, ks = k & 3;
                    int n0 = ntile * 64, kb = ks * 64;
                    ttile(sAh, sAl, sBh, sBl,
                          g_sthi + H_ + kb, g_stlo + H_ + kb,
                          g_Mthi + (size_t)n0 * HHYP + kb, g_Mtlo + (size_t)n0 * HHYP + kb, HHYP,
                          g_modS + (size_t)ks * MODSLAB + n0, MODN);
                } else {
                    int k2 = k - P3_MODT;
                    int ntile = k2 >> 2, ks = k2 & 3;
                    int n0 = ntile * 64, kb = ks * 64;
                    ttile(sAh, sAl, sBh, sBl,
                          g_sthi + H_ + kb, g_stlo + H_ + kb,
                          g_WHhi + (size_t)n0 * HHYP + kb, g_WHlo + (size_t)n0 * HHYP + kb, HHYP,
                          g_recHH + ((size_t)parN * RHHS + ks) * (B_ * HH4) + n0, HH4);
                }
                mark(donP3);
            }
        }
        gate(donP3, P3_TILES);

        // ----- P4: main cell -----
        for (;;) {
            int b = grab(tixP4, B_, &s_tile);
            if (b < 0) break;
            const int j = tid;
            const float* xw = g_XW + ((size_t)t * B_ + b) * H4;
            float pre[4][4];
#pragma unroll
            for (int gk = 0; gk < 4; gk++) {
#pragma unroll
                for (int q = 0; q < 4; q++) {
                    int n = gk * H_ + q * 256 + j;
                    float hg = 0.f;
#pragma unroll
                    for (int sl = 0; sl < P1S; sl++)
                        hg += __ldcg(&g_recP1[(size_t)sl * RECSLAB + (size_t)b * NREC + n]);
                    float sx = 0.f, sh = 0.f, ba = 0.f;
#pragma unroll
                    for (int sl = 0; sl < MODS; sl++) {
                        const float* mp = g_modS + (size_t)sl * MODSLAB + (size_t)b * MODN;
                        sx += __ldcg(&mp[n]);
                        sh += __ldcg(&mp[4 * H_ + n]);
                        ba += __ldcg(&mp[8 * H_ + n]);
                    }
                    sx += g_csc[n];
                    sh += g_csc[4 * H_ + n];
                    pre[gk][q] = fmaf(sx, xw[n], fmaf(sh, hg, bias[n] + ba));
                }
            }
            float nv[4][4];
#pragma unroll
            for (int gk = 0; gk < 4; gk++) {
                float p = pre[gk][0] + pre[gk][1] + pre[gk][2] + pre[gk][3];
                float m = block_sum256(p, sred) * (1.f / 1024.f);
                float vs = 0.f;
#pragma unroll
                for (int q = 0; q < 4; q++) { float d = pre[gk][q] - m; vs += d * d; }
                float var = block_sum256(vs, sred) * (1.f / 1024.f);
                float rs = rsqrtf(var + EPSLN);
#pragma unroll
                for (int q = 0; q < 4; q++) {
                    int n = gk * H_ + q * 256 + j;
                    nv[gk][q] = lnag[n] * ((pre[gk][q] - m) * rs) + lnab[n];
                }
            }
            float cn[4];
            float psum = 0.f;
#pragma unroll
            for (int q = 0; q < 4; q++) {
                int idx = q * 256 + j;
                float c = __ldcg(&g_c[b * H_ + idx]);
                cn[q] = sigf(nv[2][q]) * c + sigf(nv[0][q]) * tanhf(nv[1][q]);
                g_c[b * H_ + idx] = cn[q];
                psum += cn[q];
            }
            float m = block_sum256(psum, sred) * (1.f / 1024.f);
            float vs = 0.f;
#pragma unroll
            for (int q = 0; q < 4; q++) { float d = cn[q] - m; vs += d * d; }
            float var = block_sum256(vs, sred) * (1.f / 1024.f);
            float rs = rsqrtf(var + EPSLN);
#pragma unroll
            for (int q = 0; q < 4; q++) {
                int idx = q * 256 + j;
                float lc = lng[idx] * ((cn[q] - m) * rs) + lnb[idx];
                float h = sigf(nv[3][q]) * tanhf(lc);
                size_t sidx = (size_t)b * RECK + idx;
                g_state[sidx] = h;
                __nv_bfloat16 hh, hl; split_bf16(h, hh, hl);
                g_sthi[sidx] = hh; g_stlo[sidx] = hl;
            }
            mark(donP4);
        }
    }

    // ----- final FC: out = h @ fcW^T + fcb -----
    gate(&g_done[(T_ - 1) * NPH + 3], B_);
    for (;;) {
        int b = grab(&g_tix[T_ * NPH], B_, &s_tile);
        if (b < 0) break;
        float* sh = (float*)&sAh[0][0];   // 1024 floats fit in 10240-byte buffer
        float* sp = (float*)&sBh[0][0];   // 256 floats fit in 5120-byte buffer
        for (int i = tid; i < H_; i += NT_) sh[i] = __ldcg(&g_state[(size_t)b * RECK + i]);
        __syncthreads();
        int o = tid & 127, half = tid >> 7;
        const float* w = fcW + (size_t)o * H_ + half * 512;
        const float* hv = sh + half * 512;
        float s = 0.f;
        for (int k = 0; k < 512; k++) s = fmaf(hv[k], w[k], s);
        sp[tid] = s;
        __syncthreads();
        if (tid < NOUT)
            out[(size_t)b * NOUT + tid] = sp[tid] + sp[128 + tid] + fcb[tid];
        __syncthreads();
    }
}

// ---------------------------------------------------------------------------
// Launch
// ---------------------------------------------------------------------------
extern "C" void kernel_launch(void* const* d_in, const int* in_sizes, int n_in,
                              void* d_out, int out_size)
{
    const float* x      = (const float*)d_in[0];
    const float* Wx     = (const float*)d_in[1];
    const float* Wh     = (const float*)d_in[2];
    const float* bias   = (const float*)d_in[3];
    const float* lnag   = (const float*)d_in[4];
    const float* lnab   = (const float*)d_in[5];
    const float* lng    = (const float*)d_in[6];
    const float* lnb    = (const float*)d_in[7];
    const float* zb     = (const float*)d_in[8];
    const float* zbeta  = (const float*)d_in[9];
    const float* zw_w   = (const float*)d_in[10];
    const float* zw_b   = (const float*)d_in[11];
    const float* alpha  = (const float*)d_in[12];
    const float* hypWx  = (const float*)d_in[13];
    const float* hypbx  = (const float*)d_in[14];
    const float* hypWh  = (const float*)d_in[15];
    const float* hypbh  = (const float*)d_in[16];
    const float* hlnag  = (const float*)d_in[17];
    const float* hlnab  = (const float*)d_in[18];
    const float* hlng   = (const float*)d_in[19];
    const float* hlnb   = (const float*)d_in[20];
    const float* fc_W   = (const float*)d_in[21];
    const float* fc_b   = (const float*)d_in[22];
    float* out = (float*)d_out;

    float *pXW, *pHX, *pMcat;
    cudaGetSymbolAddress((void**)&pXW, g_XW);
    cudaGetSymbolAddress((void**)&pHX, g_hypX);
    cudaGetSymbolAddress((void**)&pMcat, g_Mcat);

    // ---- setup ----
    init_k<<<(2 * RHHS * B_ * HH4 + 255) / 256, 256>>>();
    csc_k<<<dim3(8, 4), 256>>>(zw_b, alpha);
    convW1_k<<<(int)(((size_t)NREC * H_ + 255) / 256), 256>>>(Wh, hypWx);
    convWH_k<<<(int)(((size_t)HH4 * HHYP + 255) / 256), 256>>>(hypWh);

    // Mcat: 12 GEMMs (256 x 1024 x 256), NN layout
    for (int s = 0; s < 12; s++) {
        const float* Am = (s < 8) ? zw_w + (size_t)s * HHYP * HHYP
                                  : zb + (size_t)(s - 8) * HHYP * HHYP;
        const float* Bn = (s < 8) ? alpha + (size_t)s * HHYP * H_
                                  : zbeta + (size_t)(s - 8) * HHYP * H_;
        gemm_k<128, 64, 16, 8, 4, false><<<dim3(16, 2), 256>>>(
            HHYP, Am, HHYP, Bn, H_, pMcat + s * H_, MODN);
    }
    convMt_k<<<(int)(((size_t)MODN * HHYP + 255) / 256), 256>>>();

    // XW = x @ Wx^T : (65536, 4096, K=256)
    gemm_k<128, 64, 16, 8, 4, true><<<dim3(H4 / 64, (T_ * B_) / 128), 256>>>(
        D_, x, D_, Wx, D_, pXW, H4);
    // hypX = x @ hyp_Wx[:, :256]^T : (65536, 1024, K=256)
    gemm_k<128, 64, 16, 8, 4, true><<<dim3(HH4 / 64, (T_ * B_) / 128), 256>>>(
        D_, x, D_, hypWx, D_ + H_, pHX, HH4);

    // ---- whole recurrence + final FC in ONE residency-oblivious kernel ----
    hyperlstm_persist<<<G_, NT_>>>(
        hypbx, hypbh, hlnag, hlnab, hlng, hlnb,
        bias, lnag, lnab, lng, lnb, fc_W, fc_b, out);
}

// round 11
// speedup vs baseline: 1.9197x; 1.2865x over previous
#include <cuda_runtime.h>
#include <cuda_bf16.h>
#include <math.h>
#include <stdint.h>

// ---------------------------------------------------------------------------
// Problem constants
// ---------------------------------------------------------------------------
#define T_ 512
#define B_ 128
#define D_ 256
#define H_ 1024      // main hidden
#define HHYP 256     // hyper hidden
#define H4 4096      // 4*H
#define HH4 1024     // 4*HHYP
#define NOUT 128
#define MODN 12288   // 8*H (sc) + 4*H (badj)
#define NREC 5120    // 4096 main rows + 1024 hyper rows
#define RECK 1280    // state length = H + HHYP
#define EPSLN 1e-3f

#define G_ 296       // launched CTAs; design does NOT require co-residency
#define NT_ 256

// phase tiling (BM=128, BN=64; K processed in 32-wide chunks)
#define P1_TILES 320           // 80 n-tiles * 4 k-splits  (K=1024, 256/ticket)
#define P1S 4                  // slabs
#define P3_MODT 192            // 192 n-tiles, K=256 whole  (1 slab)
#define P3_RHHT 16             // 16 n-tiles, K=256 whole
#define P3_TILES (P3_MODT + P3_RHHT)
#define NPH 4

#define RECSLAB ((size_t)B_ * NREC)

#define KP 40   // smem row pitch (bf16 elems) for 32-wide k chunks

// ---------------------------------------------------------------------------
// Device scratch
// ---------------------------------------------------------------------------
__device__ alignas(16) float g_XW[(size_t)T_ * B_ * H4];     // 1 GiB
__device__ alignas(16) float g_hypX[(size_t)T_ * B_ * HH4];  // 256 MiB
__device__ alignas(16) float g_Mcat[(size_t)HHYP * MODN];
__device__ alignas(16) float g_csc[8 * H_];
__device__ alignas(16) float g_state[B_ * RECK];             // fp32 [h | hyp]
__device__ alignas(16) float g_c[B_ * H_];
__device__ alignas(16) float g_ch[B_ * HHYP];
__device__ alignas(16) float g_recP1[(size_t)P1S * RECSLAB]; // 10.5 MiB
__device__ alignas(16) float g_modS[(size_t)B_ * MODN];      // 6.3 MiB (single slab)
__device__ alignas(16) float g_recHH[2 * B_ * HH4];          // parity double buffer

// bf16 hi/lo planes
__device__ alignas(16) __nv_bfloat16 g_sthi[B_ * RECK];
__device__ alignas(16) __nv_bfloat16 g_stlo[B_ * RECK];
__device__ alignas(16) __nv_bfloat16 g_W1hi[(size_t)NREC * H_];   // [n][k] packed Wh | hypWx_h
__device__ alignas(16) __nv_bfloat16 g_W1lo[(size_t)NREC * H_];
__device__ alignas(16) __nv_bfloat16 g_WHhi[(size_t)HH4 * HHYP];  // hypWh [n][k]
__device__ alignas(16) __nv_bfloat16 g_WHlo[(size_t)HH4 * HHYP];
__device__ alignas(16) __nv_bfloat16 g_Mthi[(size_t)MODN * HHYP]; // Mcat^T [n][k]
__device__ alignas(16) __nv_bfloat16 g_Mtlo[(size_t)MODN * HHYP];
__device__ alignas(16) __nv_bfloat16 g_xhi[(size_t)T_ * B_ * D_]; // x planes
__device__ alignas(16) __nv_bfloat16 g_xlo[(size_t)T_ * B_ * D_];
__device__ alignas(16) __nv_bfloat16 g_W0hi[(size_t)NREC * D_];   // [n][k] packed Wx | hypWx_x
__device__ alignas(16) __nv_bfloat16 g_W0lo[(size_t)NREC * D_];

// dataflow state
__device__ unsigned g_tix[T_ * NPH + 1];
__device__ unsigned g_done[T_ * NPH + 1];

// ---------------------------------------------------------------------------
// fp32 tiled SGEMM (setup: Mcat only)
// ---------------------------------------------------------------------------
template <int BM, int BN, int BK, int TM, int TN, bool BT>
__global__ __launch_bounds__(256) void gemm_k(
    int K, const float* __restrict__ A, int lda,
    const float* __restrict__ Bm, int ldb,
    float* __restrict__ C, int ldc)
{
    const int n0 = blockIdx.x * BN;
    const int m0 = blockIdx.y * BM;
    A += (size_t)m0 * lda;
    if (BT) Bm += (size_t)n0 * ldb;
    else    Bm += n0;
    C += (size_t)m0 * ldc + n0;

    __shared__ float As[BK][BM + 4];
    __shared__ float Bs[BK][BN + 4];
    const int tid = threadIdx.x;
    const int tx = tid % (BN / TN);
    const int ty = tid / (BN / TN);

    float acc[TM][TN];
#pragma unroll
    for (int i = 0; i < TM; i++)
#pragma unroll
        for (int j = 0; j < TN; j++) acc[i][j] = 0.f;

    for (int kt = 0; kt < K; kt += BK) {
#pragma unroll
        for (int l = 0; l < (BM * BK) / (256 * 4); l++) {
            int idx = tid + l * 256;
            int r = idx / (BK / 4);
            int c4 = idx % (BK / 4);
            float4 v = *(const float4*)(A + (size_t)r * lda + c4 * 4);
            As[c4 * 4 + 0][r] = v.x; As[c4 * 4 + 1][r] = v.y;
            As[c4 * 4 + 2][r] = v.z; As[c4 * 4 + 3][r] = v.w;
        }
        if (BT) {
#pragma unroll
            for (int l = 0; l < (BN * BK) / (256 * 4); l++) {
                int idx = tid + l * 256;
                int r = idx / (BK / 4);
                int c4 = idx % (BK / 4);
                float4 v = *(const float4*)(Bm + (size_t)r * ldb + c4 * 4);
                Bs[c4 * 4 + 0][r] = v.x; Bs[c4 * 4 + 1][r] = v.y;
                Bs[c4 * 4 + 2][r] = v.z; Bs[c4 * 4 + 3][r] = v.w;
            }
        } else {
#pragma unroll
            for (int l = 0; l < (BN * BK) / (256 * 4); l++) {
                int idx = tid + l * 256;
                int r = idx / (BN / 4);
                int c4 = idx % (BN / 4);
                float4 v = *(const float4*)(Bm + (size_t)r * ldb + c4 * 4);
                *(float4*)&Bs[r][c4 * 4] = v;
            }
        }
        __syncthreads();
#pragma unroll
        for (int k = 0; k < BK; k++) {
            float a[TM], bv[TN];
#pragma unroll
            for (int i = 0; i < TM; i += 4) {
                float4 v = *(const float4*)&As[k][ty * TM + i];
                a[i] = v.x; a[i + 1] = v.y; a[i + 2] = v.z; a[i + 3] = v.w;
            }
#pragma unroll
            for (int j = 0; j < TN; j += 4) {
                float4 v = *(const float4*)&Bs[k][tx * TN + j];
                bv[j] = v.x; bv[j + 1] = v.y; bv[j + 2] = v.z; bv[j + 3] = v.w;
            }
#pragma unroll
            for (int i = 0; i < TM; i++)
#pragma unroll
                for (int j = 0; j < TN; j++)
                    acc[i][j] = fmaf(a[i], bv[j], acc[i][j]);
        }
        __syncthreads();
        A += BK;
        if (BT) Bm += BK; else Bm += (size_t)BK * ldb;
    }
#pragma unroll
    for (int i = 0; i < TM; i++) {
        float4 o; o.x = acc[i][0]; o.y = acc[i][1]; o.z = acc[i][2]; o.w = acc[i][3];
        *(float4*)(C + (size_t)(ty * TM + i) * ldc + tx * TN) = o;
    }
}

// ---------------------------------------------------------------------------
// Setup conversion kernels
// ---------------------------------------------------------------------------
__device__ __forceinline__ void split_bf16(float x, __nv_bfloat16& h, __nv_bfloat16& l)
{
    h = __float2bfloat16(x);
    l = __float2bfloat16(x - __bfloat162float(h));
}

__global__ void init_k()
{
    size_t i = (size_t)blockIdx.x * 256 + threadIdx.x;
    if (i < (size_t)B_ * RECK) {
        g_state[i] = 0.f;
        g_sthi[i] = __float2bfloat16(0.f);
        g_stlo[i] = __float2bfloat16(0.f);
    }
    if (i < (size_t)B_ * H_)   g_c[i] = 0.f;
    if (i < (size_t)B_ * HHYP) g_ch[i] = 0.f;
    if (i < (size_t)2 * B_ * HH4) g_recHH[i] = 0.f;
    if (i < (size_t)(T_ * NPH + 1)) { g_tix[i] = 0u; g_done[i] = 0u; }
}

__global__ void csc_k(const float* __restrict__ zw_b, const float* __restrict__ alpha)
{
    int k = blockIdx.x;
    int h = blockIdx.y * 256 + threadIdx.x;
    float s = 0.f;
    const float* zb = zw_b + (size_t)k * HHYP;
    const float* al = alpha + (size_t)k * HHYP * H_;
    for (int p = 0; p < HHYP; p++) s = fmaf(zb[p], al[(size_t)p * H_ + h], s);
    g_csc[k * H_ + h] = s;
}

// pack Wh (n<4096) / hypWx h-slice (n>=4096) into [n][k<1024] hi/lo planes
__global__ void convW1_k(const float* __restrict__ Wh, const float* __restrict__ hypWx)
{
    size_t idx = (size_t)blockIdx.x * 256 + threadIdx.x;
    if (idx >= (size_t)NREC * H_) return;
    int n = (int)(idx / H_), k = (int)(idx % H_);
    float v = (n < H4) ? Wh[(size_t)n * H_ + k]
                       : hypWx[(size_t)(n - H4) * (D_ + H_) + D_ + k];
    split_bf16(v, g_W1hi[idx], g_W1lo[idx]);
}

// pack Wx (n<4096) / hypWx x-slice (n>=4096) into [n][k<256] hi/lo planes
__global__ void convW0_k(const float* __restrict__ Wx, const float* __restrict__ hypWx)
{
    size_t idx = (size_t)blockIdx.x * 256 + threadIdx.x;
    if (idx >= (size_t)NREC * D_) return;
    int n = (int)(idx / D_), k = (int)(idx % D_);
    float v = (n < H4) ? Wx[(size_t)n * D_ + k]
                       : hypWx[(size_t)(n - H4) * (D_ + H_) + k];
    split_bf16(v, g_W0hi[idx], g_W0lo[idx]);
}

__global__ void convWH_k(const float* __restrict__ hypWh)
{
    size_t idx = (size_t)blockIdx.x * 256 + threadIdx.x;
    if (idx >= (size_t)HH4 * HHYP) return;
    split_bf16(hypWh[idx], g_WHhi[idx], g_WHlo[idx]);
}

// transpose Mcat [k=256][n=12288] -> [n][k] hi/lo planes
__global__ void convMt_k()
{
    size_t idx = (size_t)blockIdx.x * 256 + threadIdx.x;
    if (idx >= (size_t)MODN * HHYP) return;
    int n = (int)(idx / HHYP), k = (int)(idx % HHYP);
    split_bf16(g_Mcat[(size_t)k * MODN + n], g_Mthi[idx], g_Mtlo[idx]);
}

// split x into bf16 hi/lo planes
__global__ void convX_k(const float* __restrict__ x)
{
    size_t idx = (size_t)blockIdx.x * 256 + threadIdx.x;
    if (idx >= (size_t)T_ * B_ * D_) return;
    split_bf16(x[idx], g_xhi[idx], g_xlo[idx]);
}

// ---------------------------------------------------------------------------
// Shared helpers
// ---------------------------------------------------------------------------
__device__ __forceinline__ float sigf(float x) { return 1.f / (1.f + expf(-x)); }

__device__ __forceinline__ float block_sum256(float v, float* sbuf)
{
    const int tid = threadIdx.x;
#pragma unroll
    for (int o = 16; o > 0; o >>= 1) v += __shfl_xor_sync(0xffffffffu, v, o);
    const int warp = tid >> 5, lane = tid & 31;
    if (lane == 0) sbuf[warp] = v;
    __syncthreads();
    float s = (tid < 8) ? sbuf[tid] : 0.f;
    if (warp == 0) {
#pragma unroll
        for (int o = 4; o > 0; o >>= 1) s += __shfl_xor_sync(0xffffffffu, s, o);
        if (lane == 0) sbuf[0] = s;
    }
    __syncthreads();
    float r = sbuf[0];
    __syncthreads();
    return r;
}

__device__ __forceinline__ int grab(unsigned* ctr, unsigned limit, unsigned* s_tile)
{
    __syncthreads();
    if (threadIdx.x == 0) *s_tile = atomicAdd(ctr, 1u);
    __syncthreads();
    unsigned k = *s_tile;
    return (k < limit) ? (int)k : -1;
}

__device__ __forceinline__ void mark(unsigned* cnt)
{
    __threadfence();
    __syncthreads();
    if (threadIdx.x == 0) atomicAdd(cnt, 1u);
}

__device__ __forceinline__ void gate(const unsigned* cnt, unsigned target)
{
    if (threadIdx.x == 0) {
        while (*(volatile const unsigned*)cnt < target) __nanosleep(128);
        __threadfence();
    }
    __syncthreads();
}

__device__ __forceinline__ void mma16816(float* d, const uint32_t* a, const uint32_t* b)
{
    asm volatile(
        "mma.sync.aligned.m16n8k16.row.col.f32.bf16.bf16.f32 "
        "{%0,%1,%2,%3}, {%4,%5,%6,%7}, {%8,%9}, {%0,%1,%2,%3};\n"
        : "+f"(d[0]), "+f"(d[1]), "+f"(d[2]), "+f"(d[3])
        : "r"(a[0]), "r"(a[1]), "r"(a[2]), "r"(a[3]), "r"(b[0]), "r"(b[1]));
}

// ---------------------------------------------------------------------------
// Tensor GEMM tile: C[128,64] = A[128,K] * B[64,K]^T, bf16 hi/lo x3 MMA.
// K = nchunk*32 processed through static smem buffers.
// A planes: row pitch lda. B planes: [n][k] row pitch ldbk.
// ---------------------------------------------------------------------------
__device__ void ttile(
    __nv_bfloat16 (*sAh)[KP], __nv_bfloat16 (*sAl)[KP],
    __nv_bfloat16 (*sBh)[KP], __nv_bfloat16 (*sBl)[KP],
    const __nv_bfloat16* gAh, const __nv_bfloat16* gAl, int lda,
    const __nv_bfloat16* gBh, const __nv_bfloat16* gBl, int ldbk,
    float* C, int ldc, int nchunk)
{
    const int tid = threadIdx.x;
    const int lane = tid & 31, w = tid >> 5;
    const int wm = w & 3, wn = w >> 2;          // 4 warps M x 2 warps N
    const int g = lane >> 2, tig = lane & 3;

    float acc[2][4][4];
#pragma unroll
    for (int ms = 0; ms < 2; ms++)
#pragma unroll
        for (int ns = 0; ns < 4; ns++)
#pragma unroll
            for (int q = 0; q < 4; q++) acc[ms][ns][q] = 0.f;

    for (int ch = 0; ch < nchunk; ch++) {
        const int kb = ch * 32;
        // ---- load A planes: 128 rows x 32 bf16 ----
#pragma unroll
        for (int i = 0; i < 2; i++) {
            int u = tid + i * 256;
            int r = u >> 2, c = (u & 3) * 8;
            *(uint4*)&sAh[r][c] = __ldcg((const uint4*)(gAh + (size_t)r * lda + kb + c));
            *(uint4*)&sAl[r][c] = __ldcg((const uint4*)(gAl + (size_t)r * lda + kb + c));
        }
        // ---- load B planes: 64 rows x 32 bf16 ----
        {
            int r = tid >> 2, c = (tid & 3) * 8;
            *(uint4*)&sBh[r][c] = *(const uint4*)(gBh + (size_t)r * ldbk + kb + c);
            *(uint4*)&sBl[r][c] = *(const uint4*)(gBl + (size_t)r * ldbk + kb + c);
        }
        __syncthreads();

#pragma unroll
        for (int kk = 0; kk < 2; kk++) {
            const int ko = kk * 16 + tig * 2;
            uint32_t ah[2][4], al[2][4];
#pragma unroll
            for (int ms = 0; ms < 2; ms++) {
                const __nv_bfloat16* ba = &sAh[wm * 32 + ms * 16 + g][0];
                const __nv_bfloat16* bl = &sAl[wm * 32 + ms * 16 + g][0];
                ah[ms][0] = *(const uint32_t*)&ba[ko];
                ah[ms][1] = *(const uint32_t*)&ba[8 * KP + ko];
                ah[ms][2] = *(const uint32_t*)&ba[ko + 8];
                ah[ms][3] = *(const uint32_t*)&ba[8 * KP + ko + 8];
                al[ms][0] = *(const uint32_t*)&bl[ko];
                al[ms][1] = *(const uint32_t*)&bl[8 * KP + ko];
                al[ms][2] = *(const uint32_t*)&bl[ko + 8];
                al[ms][3] = *(const uint32_t*)&bl[8 * KP + ko + 8];
            }
#pragma unroll
            for (int ns = 0; ns < 4; ns++) {
                const __nv_bfloat16* bb = &sBh[wn * 32 + ns * 8 + g][0];
                const __nv_bfloat16* bc = &sBl[wn * 32 + ns * 8 + g][0];
                uint32_t bh[2], blo[2];
                bh[0]  = *(const uint32_t*)&bb[ko];
                bh[1]  = *(const uint32_t*)&bb[ko + 8];
                blo[0] = *(const uint32_t*)&bc[ko];
                blo[1] = *(const uint32_t*)&bc[ko + 8];
#pragma unroll
                for (int ms = 0; ms < 2; ms++) {
                    mma16816(acc[ms][ns], ah[ms], bh);
                    mma16816(acc[ms][ns], ah[ms], blo);
                    mma16816(acc[ms][ns], al[ms], bh);
                }
            }
        }
        __syncthreads();
    }

    // ---- epilogue ----
#pragma unroll
    for (int ms = 0; ms < 2; ms++) {
#pragma unroll
        for (int ns = 0; ns < 4; ns++) {
            int row0 = wm * 32 + ms * 16 + g;
            int col = wn * 32 + ns * 8 + tig * 2;
            float2 v0; v0.x = acc[ms][ns][0]; v0.y = acc[ms][ns][1];
            float2 v1; v1.x = acc[ms][ns][2]; v1.y = acc[ms][ns][3];
            *(float2*)&C[(size_t)row0 * ldc + col] = v0;
            *(float2*)&C[(size_t)(row0 + 8) * ldc + col] = v1;
        }
    }
}

// ---------------------------------------------------------------------------
// Setup tensor GEMM: [XW | hypX] = x @ W0^T  (M=65536, N=5120, K=256)
// grid = (80 n-tiles, 512 m-tiles)
// ---------------------------------------------------------------------------
__global__ __launch_bounds__(NT_) void xw_tensor_k()
{
    __shared__ __align__(16) __nv_bfloat16 sAh[128][KP];
    __shared__ __align__(16) __nv_bfloat16 sAl[128][KP];
    __shared__ __align__(16) __nv_bfloat16 sBh[64][KP];
    __shared__ __align__(16) __nv_bfloat16 sBl[64][KP];

    const int n0 = blockIdx.x * 64;
    const size_t m0 = (size_t)blockIdx.y * 128;
    float* C;
    int ldc;
    if (n0 < H4) { C = g_XW + m0 * H4 + n0; ldc = H4; }
    else         { C = g_hypX + m0 * HH4 + (n0 - H4); ldc = HH4; }
    ttile(sAh, sAl, sBh, sBl,
          g_xhi + m0 * D_, g_xlo + m0 * D_, D_,
          g_W0hi + (size_t)n0 * D_, g_W0lo + (size_t)n0 * D_, D_,
          C, ldc, 8);
}

// ---------------------------------------------------------------------------
// Persistent kernel: whole T=512 recurrence + final FC
// ---------------------------------------------------------------------------
__global__ __launch_bounds__(NT_, 2) void hyperlstm_persist(
    const float* __restrict__ hypbx, const float* __restrict__ hypbh,
    const float* __restrict__ hlnag, const float* __restrict__ hlnab,
    const float* __restrict__ hlng, const float* __restrict__ hlnb,
    const float* __restrict__ bias,
    const float* __restrict__ lnag, const float* __restrict__ lnab,
    const float* __restrict__ lng, const float* __restrict__ lnb,
    const float* __restrict__ fcW, const float* __restrict__ fcb,
    float* __restrict__ out)
{
    __shared__ __align__(16) __nv_bfloat16 sAh[128][KP];
    __shared__ __align__(16) __nv_bfloat16 sAl[128][KP];
    __shared__ __align__(16) __nv_bfloat16 sBh[64][KP];
    __shared__ __align__(16) __nv_bfloat16 sBl[64][KP];
    __shared__ float sred[32];
    __shared__ unsigned s_tile;

    const int tid = threadIdx.x;

    for (int t = 0; t < T_; t++) {
        unsigned* tixP1 = &g_tix[t * NPH + 0];
        unsigned* tixP2 = &g_tix[t * NPH + 1];
        unsigned* tixP3 = &g_tix[t * NPH + 2];
        unsigned* tixP4 = &g_tix[t * NPH + 3];
        unsigned* donP1 = &g_done[t * NPH + 0];
        unsigned* donP2 = &g_done[t * NPH + 1];
        unsigned* donP3 = &g_done[t * NPH + 2];
        unsigned* donP4 = &g_done[t * NPH + 3];

        // ----- P1: rec GEMM from h : N=5120, K=1024 (tensor, ksplit 4) -----
        if (t > 0) gate(&g_done[(t - 1) * NPH + 3], B_);
        for (;;) {
            int k = grab(tixP1, P1_TILES, &s_tile);
            if (k < 0) break;
            int ntile = k >> 2, ks = k & 3;
            int n0 = ntile * 64, kb = ks * 256;
            ttile(sAh, sAl, sBh, sBl,
                  g_sthi + kb, g_stlo + kb, RECK,
                  g_W1hi + (size_t)n0 * H_ + kb, g_W1lo + (size_t)n0 * H_ + kb, H_,
                  g_recP1 + (size_t)ks * RECSLAB + n0, NREC, 8);
            mark(donP1);
        }
        gate(donP1, P1_TILES);

        // ----- P2: hyper cell -----
        for (;;) {
            int b = grab(tixP2, B_, &s_tile);
            if (b < 0) break;
            const int j = tid;
            const int par = t & 1;
            const float* hx = g_hypX + ((size_t)t * B_ + b) * HH4;
            float v[4];
#pragma unroll
            for (int gk = 0; gk < 4; gk++) {
                int n = gk * HHYP + j;
                float s = hx[n] + hypbx[n] + hypbh[n];
#pragma unroll
                for (int sl = 0; sl < P1S; sl++)
                    s += __ldcg(&g_recP1[(size_t)sl * RECSLAB + (size_t)b * NREC + H4 + n]);
                s += __ldcg(&g_recHH[(size_t)par * (B_ * HH4) + (size_t)b * HH4 + n]);
                v[gk] = s;
            }
            float nv[4];
#pragma unroll
            for (int gk = 0; gk < 4; gk++) {
                float m = block_sum256(v[gk], sred) * (1.f / 256.f);
                float xs = v[gk] - m;
                float var = block_sum256(xs * xs, sred) * (1.f / 256.f);
                int n = gk * HHYP + j;
                nv[gk] = hlnag[n] * (xs * rsqrtf(var + EPSLN)) + hlnab[n];
            }
            float ch = __ldcg(&g_ch[b * HHYP + j]);
            float chn = sigf(nv[1]) * ch + sigf(nv[0]) * tanhf(nv[2]);
            float m = block_sum256(chn, sred) * (1.f / 256.f);
            float xs = chn - m;
            float var = block_sum256(xs * xs, sred) * (1.f / 256.f);
            float hn = hlng[j] * (xs * rsqrtf(var + EPSLN)) + hlnb[j];
            float hyp = sigf(nv[3]) * tanhf(hn);
            g_ch[b * HHYP + j] = chn;
            size_t sidx = (size_t)b * RECK + H_ + j;
            g_state[sidx] = hyp;
            __nv_bfloat16 hh, hl; split_bf16(hyp, hh, hl);
            g_sthi[sidx] = hh; g_stlo[sidx] = hl;
            mark(donP2);
        }
        gate(donP2, B_);

        // ----- P3: mod GEMM (K=256 whole) + next-step rec-hh -----
        {
            const int parN = (t + 1) & 1;
            for (;;) {
                int k = grab(tixP3, P3_TILES, &s_tile);
                if (k < 0) break;
                if (k < P3_MODT) {
                    int n0 = k * 64;
                    ttile(sAh, sAl, sBh, sBl,
                          g_sthi + H_, g_stlo + H_, RECK,
                          g_Mthi + (size_t)n0 * HHYP, g_Mtlo + (size_t)n0 * HHYP, HHYP,
                          g_modS + n0, MODN, 8);
                } else {
                    int n0 = (k - P3_MODT) * 64;
                    ttile(sAh, sAl, sBh, sBl,
                          g_sthi + H_, g_stlo + H_, RECK,
                          g_WHhi + (size_t)n0 * HHYP, g_WHlo + (size_t)n0 * HHYP, HHYP,
                          g_recHH + (size_t)parN * (B_ * HH4) + n0, HH4, 8);
                }
                mark(donP3);
            }
        }
        gate(donP3, P3_TILES);

        // ----- P4: main cell -----
        for (;;) {
            int b = grab(tixP4, B_, &s_tile);
            if (b < 0) break;
            const int j = tid;
            const float* xw = g_XW + ((size_t)t * B_ + b) * H4;
            const float* mp = g_modS + (size_t)b * MODN;
            float pre[4][4];
#pragma unroll
            for (int gk = 0; gk < 4; gk++) {
#pragma unroll
                for (int q = 0; q < 4; q++) {
                    int n = gk * H_ + q * 256 + j;
                    float hg = 0.f;
#pragma unroll
                    for (int sl = 0; sl < P1S; sl++)
                        hg += __ldcg(&g_recP1[(size_t)sl * RECSLAB + (size_t)b * NREC + n]);
                    float sx = __ldcg(&mp[n]) + g_csc[n];
                    float sh = __ldcg(&mp[4 * H_ + n]) + g_csc[4 * H_ + n];
                    float ba = __ldcg(&mp[8 * H_ + n]);
                    pre[gk][q] = fmaf(sx, xw[n], fmaf(sh, hg, bias[n] + ba));
                }
            }
            float nv[4][4];
#pragma unroll
            for (int gk = 0; gk < 4; gk++) {
                float p = pre[gk][0] + pre[gk][1] + pre[gk][2] + pre[gk][3];
                float m = block_sum256(p, sred) * (1.f / 1024.f);
                float vs = 0.f;
#pragma unroll
                for (int q = 0; q < 4; q++) { float d = pre[gk][q] - m; vs += d * d; }
                float var = block_sum256(vs, sred) * (1.f / 1024.f);
                float rs = rsqrtf(var + EPSLN);
#pragma unroll
                for (int q = 0; q < 4; q++) {
                    int n = gk * H_ + q * 256 + j;
                    nv[gk][q] = lnag[n] * ((pre[gk][q] - m) * rs) + lnab[n];
                }
            }
            float cn[4];
            float psum = 0.f;
#pragma unroll
            for (int q = 0; q < 4; q++) {
                int idx = q * 256 + j;
                float c = __ldcg(&g_c[b * H_ + idx]);
                cn[q] = sigf(nv[2][q]) * c + sigf(nv[0][q]) * tanhf(nv[1][q]);
                g_c[b * H_ + idx] = cn[q];
                psum += cn[q];
            }
            float m = block_sum256(psum, sred) * (1.f / 1024.f);
            float vs = 0.f;
#pragma unroll
            for (int q = 0; q < 4; q++) { float d = cn[q] - m; vs += d * d; }
            float var = block_sum256(vs, sred) * (1.f / 1024.f);
            float rs = rsqrtf(var + EPSLN);
#pragma unroll
            for (int q = 0; q < 4; q++) {
                int idx = q * 256 + j;
                float lc = lng[idx] * ((cn[q] - m) * rs) + lnb[idx];
                float h = sigf(nv[3][q]) * tanhf(lc);
                size_t sidx = (size_t)b * RECK + idx;
                g_state[sidx] = h;
                __nv_bfloat16 hh, hl; split_bf16(h, hh, hl);
                g_sthi[sidx] = hh; g_stlo[sidx] = hl;
            }
            mark(donP4);
        }
    }

    // ----- final FC: out = h @ fcW^T + fcb -----
    gate(&g_done[(T_ - 1) * NPH + 3], B_);
    for (;;) {
        int b = grab(&g_tix[T_ * NPH], B_, &s_tile);
        if (b < 0) break;
        float* sh = (float*)&sAh[0][0];   // 1024 floats fit in 10240-byte buffer
        float* sp = (float*)&sBh[0][0];   // 256 floats fit in 5120-byte buffer
        for (int i = tid; i < H_; i += NT_) sh[i] = __ldcg(&g_state[(size_t)b * RECK + i]);
        __syncthreads();
        int o = tid & 127, half = tid >> 7;
        const float* w = fcW + (size_t)o * H_ + half * 512;
        const float* hv = sh + half * 512;
        float s = 0.f;
        for (int k = 0; k < 512; k++) s = fmaf(hv[k], w[k], s);
        sp[tid] = s;
        __syncthreads();
        if (tid < NOUT)
            out[(size_t)b * NOUT + tid] = sp[tid] + sp[128 + tid] + fcb[tid];
        __syncthreads();
    }
}

// ---------------------------------------------------------------------------
// Launch
// ---------------------------------------------------------------------------
extern "C" void kernel_launch(void* const* d_in, const int* in_sizes, int n_in,
                              void* d_out, int out_size)
{
    const float* x      = (const float*)d_in[0];
    const float* Wx     = (const float*)d_in[1];
    const float* Wh     = (const float*)d_in[2];
    const float* bias   = (const float*)d_in[3];
    const float* lnag   = (const float*)d_in[4];
    const float* lnab   = (const float*)d_in[5];
    const float* lng    = (const float*)d_in[6];
    const float* lnb    = (const float*)d_in[7];
    const float* zb     = (const float*)d_in[8];
    const float* zbeta  = (const float*)d_in[9];
    const float* zw_w   = (const float*)d_in[10];
    const float* zw_b   = (const float*)d_in[11];
    const float* alpha  = (const float*)d_in[12];
    const float* hypWx  = (const float*)d_in[13];
    const float* hypbx  = (const float*)d_in[14];
    const float* hypWh  = (const float*)d_in[15];
    const float* hypbh  = (const float*)d_in[16];
    const float* hlnag  = (const float*)d_in[17];
    const float* hlnab  = (const float*)d_in[18];
    const float* hlng   = (const float*)d_in[19];
    const float* hlnb   = (const float*)d_in[20];
    const float* fc_W   = (const float*)d_in[21];
    const float* fc_b   = (const float*)d_in[22];
    float* out = (float*)d_out;

    float* pMcat;
    cudaGetSymbolAddress((void**)&pMcat, g_Mcat);

    // ---- setup ----
    init_k<<<(2 * B_ * HH4 + 255) / 256, 256>>>();
    csc_k<<<dim3(8, 4), 256>>>(zw_b, alpha);
    convW1_k<<<(int)(((size_t)NREC * H_ + 255) / 256), 256>>>(Wh, hypWx);
    convW0_k<<<(int)(((size_t)NREC * D_ + 255) / 256), 256>>>(Wx, hypWx);
    convWH_k<<<(int)(((size_t)HH4 * HHYP + 255) / 256), 256>>>(hypWh);
    convX_k<<<(int)(((size_t)T_ * B_ * D_ + 255) / 256), 256>>>(x);

    // Mcat: 12 GEMMs (256 x 1024 x 256), NN layout (fp32 — exact)
    for (int s = 0; s < 12; s++) {
        const float* Am = (s < 8) ? zw_w + (size_t)s * HHYP * HHYP
                                  : zb + (size_t)(s - 8) * HHYP * HHYP;
        const float* Bn = (s < 8) ? alpha + (size_t)s * HHYP * H_
                                  : zbeta + (size_t)(s - 8) * HHYP * H_;
        gemm_k<128, 64, 16, 8, 4, false><<<dim3(16, 2), 256>>>(
            HHYP, Am, HHYP, Bn, H_, pMcat + s * H_, MODN);
    }
    convMt_k<<<(int)(((size_t)MODN * HHYP + 255) / 256), 256>>>();

    // [XW | hypX] = x @ W0^T on tensor cores
    xw_tensor_k<<<dim3(NREC / 64, (T_ * B_) / 128), NT_>>>();

    // ---- whole recurrence + final FC in ONE residency-oblivious kernel ----
    hyperlstm_persist<<<G_, NT_>>>(
        hypbx, hypbh, hlnag, hlnab, hlng, hlnb,
        bias, lnag, lnab, lng, lnb, fc_W, fc_b, out);
}

// round 14
// speedup vs baseline: 2.2656x; 1.1802x over previous
#include <cuda_runtime.h>
#include <cuda_bf16.h>
#include <math.h>
#include <stdint.h>

// ---------------------------------------------------------------------------
// Problem constants
// ---------------------------------------------------------------------------
#define T_ 512
#define B_ 128
#define D_ 256
#define H_ 1024      // main hidden
#define HHYP 256     // hyper hidden
#define H4 4096      // 4*H
#define HH4 1024     // 4*HHYP
#define NOUT 128
#define MODN 12288   // 8*H (sc) + 4*H (badj)
#define NREC 5120    // 4096 main rows + 1024 hyper rows
#define RECK 1280    // state length = H + HHYP
#define EPSLN 1e-3f

#define G_ 296       // launched CTAs; design does NOT require co-residency
#define NT_ 256

// phase tiling (BM=128, BN=64; K processed in 32-wide chunks)
#define P1_TILES 320           // 80 n-tiles * 4 k-splits  (K=1024, 256/ticket)
#define P1_HYP 64              // hyper tiles (issued first)
#define P1S 4                  // slabs
#define P3_MODT 192            // 192 n-tiles, K=256 whole  (1 slab)
#define P3_RHHT 16             // 16 n-tiles, K=256 whole
#define P3_TILES (P3_MODT + P3_RHHT)
#define NPH 4

#define RECSLAB ((size_t)B_ * NREC)

#define KP 40   // smem row pitch (bf16 elems) for 32-wide k chunks

// ---------------------------------------------------------------------------
// Device scratch
// ---------------------------------------------------------------------------
__device__ alignas(16) float g_XW[(size_t)T_ * B_ * H4];     // 1 GiB
__device__ alignas(16) float g_hypX[(size_t)T_ * B_ * HH4];  // 256 MiB
__device__ alignas(16) float g_Mcat[(size_t)HHYP * MODN];
__device__ alignas(16) float g_csc[8 * H_];
__device__ alignas(16) float g_state[B_ * RECK];             // fp32 [h | hyp]
__device__ alignas(16) float g_c[B_ * H_];
__device__ alignas(16) float g_ch[B_ * HHYP];
__device__ alignas(16) float g_recP1[(size_t)P1S * RECSLAB]; // 10.5 MiB
__device__ alignas(16) float g_modS[(size_t)B_ * MODN];      // 6.3 MiB (single slab)
__device__ alignas(16) float g_recHH[2 * B_ * HH4];          // parity double buffer

// bf16 hi/lo planes
__device__ alignas(16) __nv_bfloat16 g_sthi[B_ * RECK];
__device__ alignas(16) __nv_bfloat16 g_stlo[B_ * RECK];
__device__ alignas(16) __nv_bfloat16 g_W1hi[(size_t)NREC * H_];   // [n][k] packed Wh | hypWx_h
__device__ alignas(16) __nv_bfloat16 g_W1lo[(size_t)NREC * H_];
__device__ alignas(16) __nv_bfloat16 g_WHhi[(size_t)HH4 * HHYP];  // hypWh [n][k]
__device__ alignas(16) __nv_bfloat16 g_WHlo[(size_t)HH4 * HHYP];
__device__ alignas(16) __nv_bfloat16 g_Mthi[(size_t)MODN * HHYP]; // Mcat^T [n][k]
__device__ alignas(16) __nv_bfloat16 g_Mtlo[(size_t)MODN * HHYP];
__device__ alignas(16) __nv_bfloat16 g_xhi[(size_t)T_ * B_ * D_]; // x planes
__device__ alignas(16) __nv_bfloat16 g_xlo[(size_t)T_ * B_ * D_];
__device__ alignas(16) __nv_bfloat16 g_W0hi[(size_t)NREC * D_];   // [n][k] packed Wx | hypWx_x
__device__ alignas(16) __nv_bfloat16 g_W0lo[(size_t)NREC * D_];

// dataflow state
__device__ unsigned g_tix[T_ * NPH + 1];
__device__ unsigned g_done[T_ * NPH + 1];
__device__ unsigned g_doneH[T_];      // P1 hyper-tile completion (gates P2 early)

// ---------------------------------------------------------------------------
// fp32 tiled SGEMM (setup: Mcat only)
// ---------------------------------------------------------------------------
template <int BM, int BN, int BK, int TM, int TN, bool BT>
__global__ __launch_bounds__(256) void gemm_k(
    int K, const float* __restrict__ A, int lda,
    const float* __restrict__ Bm, int ldb,
    float* __restrict__ C, int ldc)
{
    const int n0 = blockIdx.x * BN;
    const int m0 = blockIdx.y * BM;
    A += (size_t)m0 * lda;
    if (BT) Bm += (size_t)n0 * ldb;
    else    Bm += n0;
    C += (size_t)m0 * ldc + n0;

    __shared__ float As[BK][BM + 4];
    __shared__ float Bs[BK][BN + 4];
    const int tid = threadIdx.x;
    const int tx = tid % (BN / TN);
    const int ty = tid / (BN / TN);

    float acc[TM][TN];
#pragma unroll
    for (int i = 0; i < TM; i++)
#pragma unroll
        for (int j = 0; j < TN; j++) acc[i][j] = 0.f;

    for (int kt = 0; kt < K; kt += BK) {
#pragma unroll
        for (int l = 0; l < (BM * BK) / (256 * 4); l++) {
            int idx = tid + l * 256;
            int r = idx / (BK / 4);
            int c4 = idx % (BK / 4);
            float4 v = *(const float4*)(A + (size_t)r * lda + c4 * 4);
            As[c4 * 4 + 0][r] = v.x; As[c4 * 4 + 1][r] = v.y;
            As[c4 * 4 + 2][r] = v.z; As[c4 * 4 + 3][r] = v.w;
        }
        if (BT) {
#pragma unroll
            for (int l = 0; l < (BN * BK) / (256 * 4); l++) {
                int idx = tid + l * 256;
                int r = idx / (BK / 4);
                int c4 = idx % (BK / 4);
                float4 v = *(const float4*)(Bm + (size_t)r * ldb + c4 * 4);
                Bs[c4 * 4 + 0][r] = v.x; Bs[c4 * 4 + 1][r] = v.y;
                Bs[c4 * 4 + 2][r] = v.z; Bs[c4 * 4 + 3][r] = v.w;
            }
        } else {
#pragma unroll
            for (int l = 0; l < (BN * BK) / (256 * 4); l++) {
                int idx = tid + l * 256;
                int r = idx / (BN / 4);
                int c4 = idx % (BN / 4);
                float4 v = *(const float4*)(Bm + (size_t)r * ldb + c4 * 4);
                *(float4*)&Bs[r][c4 * 4] = v;
            }
        }
        __syncthreads();
#pragma unroll
        for (int k = 0; k < BK; k++) {
            float a[TM], bv[TN];
#pragma unroll
            for (int i = 0; i < TM; i += 4) {
                float4 v = *(const float4*)&As[k][ty * TM + i];
                a[i] = v.x; a[i + 1] = v.y; a[i + 2] = v.z; a[i + 3] = v.w;
            }
#pragma unroll
            for (int j = 0; j < TN; j += 4) {
                float4 v = *(const float4*)&Bs[k][tx * TN + j];
                bv[j] = v.x; bv[j + 1] = v.y; bv[j + 2] = v.z; bv[j + 3] = v.w;
            }
#pragma unroll
            for (int i = 0; i < TM; i++)
#pragma unroll
                for (int j = 0; j < TN; j++)
                    acc[i][j] = fmaf(a[i], bv[j], acc[i][j]);
        }
        __syncthreads();
        A += BK;
        if (BT) Bm += BK; else Bm += (size_t)BK * ldb;
    }
#pragma unroll
    for (int i = 0; i < TM; i++) {
        float4 o; o.x = acc[i][0]; o.y = acc[i][1]; o.z = acc[i][2]; o.w = acc[i][3];
        *(float4*)(C + (size_t)(ty * TM + i) * ldc + tx * TN) = o;
    }
}

// ---------------------------------------------------------------------------
// Setup conversion kernels
// ---------------------------------------------------------------------------
__device__ __forceinline__ void split_bf16(float x, __nv_bfloat16& h, __nv_bfloat16& l)
{
    h = __float2bfloat16(x);
    l = __float2bfloat16(x - __bfloat162float(h));
}

__global__ void init_k()
{
    size_t i = (size_t)blockIdx.x * 256 + threadIdx.x;
    if (i < (size_t)B_ * RECK) {
        g_state[i] = 0.f;
        g_sthi[i] = __float2bfloat16(0.f);
        g_stlo[i] = __float2bfloat16(0.f);
    }
    if (i < (size_t)B_ * H_)   g_c[i] = 0.f;
    if (i < (size_t)B_ * HHYP) g_ch[i] = 0.f;
    if (i < (size_t)2 * B_ * HH4) g_recHH[i] = 0.f;
    if (i < (size_t)(T_ * NPH + 1)) { g_tix[i] = 0u; g_done[i] = 0u; }
    if (i < (size_t)T_) g_doneH[i] = 0u;
}

__global__ void csc_k(const float* __restrict__ zw_b, const float* __restrict__ alpha)
{
    int k = blockIdx.x;
    int h = blockIdx.y * 256 + threadIdx.x;
    float s = 0.f;
    const float* zb = zw_b + (size_t)k * HHYP;
    const float* al = alpha + (size_t)k * HHYP * H_;
    for (int p = 0; p < HHYP; p++) s = fmaf(zb[p], al[(size_t)p * H_ + h], s);
    g_csc[k * H_ + h] = s;
}

// pack Wh (n<4096) / hypWx h-slice (n>=4096) into [n][k<1024] hi/lo planes
__global__ void convW1_k(const float* __restrict__ Wh, const float* __restrict__ hypWx)
{
    size_t idx = (size_t)blockIdx.x * 256 + threadIdx.x;
    if (idx >= (size_t)NREC * H_) return;
    int n = (int)(idx / H_), k = (int)(idx % H_);
    float v = (n < H4) ? Wh[(size_t)n * H_ + k]
                       : hypWx[(size_t)(n - H4) * (D_ + H_) + D_ + k];
    split_bf16(v, g_W1hi[idx], g_W1lo[idx]);
}

// pack Wx (n<4096) / hypWx x-slice (n>=4096) into [n][k<256] hi/lo planes
__global__ void convW0_k(const float* __restrict__ Wx, const float* __restrict__ hypWx)
{
    size_t idx = (size_t)blockIdx.x * 256 + threadIdx.x;
    if (idx >= (size_t)NREC * D_) return;
    int n = (int)(idx / D_), k = (int)(idx % D_);
    float v = (n < H4) ? Wx[(size_t)n * D_ + k]
                       : hypWx[(size_t)(n - H4) * (D_ + H_) + k];
    split_bf16(v, g_W0hi[idx], g_W0lo[idx]);
}

__global__ void convWH_k(const float* __restrict__ hypWh)
{
    size_t idx = (size_t)blockIdx.x * 256 + threadIdx.x;
    if (idx >= (size_t)HH4 * HHYP) return;
    split_bf16(hypWh[idx], g_WHhi[idx], g_WHlo[idx]);
}

// transpose Mcat [k=256][n=12288] -> [n][k] hi/lo planes
__global__ void convMt_k()
{
    size_t idx = (size_t)blockIdx.x * 256 + threadIdx.x;
    if (idx >= (size_t)MODN * HHYP) return;
    int n = (int)(idx / HHYP), k = (int)(idx % HHYP);
    split_bf16(g_Mcat[(size_t)k * MODN + n], g_Mthi[idx], g_Mtlo[idx]);
}

// split x into bf16 hi/lo planes
__global__ void convX_k(const float* __restrict__ x)
{
    size_t idx = (size_t)blockIdx.x * 256 + threadIdx.x;
    if (idx >= (size_t)T_ * B_ * D_) return;
    split_bf16(x[idx], g_xhi[idx], g_xlo[idx]);
}

// ---------------------------------------------------------------------------
// Shared helpers
// ---------------------------------------------------------------------------
__device__ __forceinline__ float sigf(float x) { return 1.f / (1.f + expf(-x)); }

__device__ __forceinline__ float block_sum256(float v, float* sbuf)
{
    const int tid = threadIdx.x;
#pragma unroll
    for (int o = 16; o > 0; o >>= 1) v += __shfl_xor_sync(0xffffffffu, v, o);
    const int warp = tid >> 5, lane = tid & 31;
    if (lane == 0) sbuf[warp] = v;
    __syncthreads();
    float s = (tid < 8) ? sbuf[tid] : 0.f;
    if (warp == 0) {
#pragma unroll
        for (int o = 4; o > 0; o >>= 1) s += __shfl_xor_sync(0xffffffffu, s, o);
        if (lane == 0) sbuf[0] = s;
    }
    __syncthreads();
    float r = sbuf[0];
    __syncthreads();
    return r;
}

__device__ __forceinline__ int grab(unsigned* ctr, unsigned limit, unsigned* s_tile)
{
    __syncthreads();
    if (threadIdx.x == 0) *s_tile = atomicAdd(ctr, 1u);
    __syncthreads();
    unsigned k = *s_tile;
    return (k < limit) ? (int)k : -1;
}

__device__ __forceinline__ void mark(unsigned* cnt)
{
    __threadfence();
    __syncthreads();
    if (threadIdx.x == 0) atomicAdd(cnt, 1u);
}

__device__ __forceinline__ void gate(const unsigned* cnt, unsigned target)
{
    if (threadIdx.x == 0) {
        while (*(volatile const unsigned*)cnt < target) __nanosleep(128);
        __threadfence();
    }
    __syncthreads();
}

__device__ __forceinline__ void mma16816(float* d, const uint32_t* a, const uint32_t* b)
{
    asm volatile(
        "mma.sync.aligned.m16n8k16.row.col.f32.bf16.bf16.f32 "
        "{%0,%1,%2,%3}, {%4,%5,%6,%7}, {%8,%9}, {%0,%1,%2,%3};\n"
        : "+f"(d[0]), "+f"(d[1]), "+f"(d[2]), "+f"(d[3])
        : "r"(a[0]), "r"(a[1]), "r"(a[2]), "r"(a[3]), "r"(b[0]), "r"(b[1]));
}

// ---------------------------------------------------------------------------
// Tensor GEMM tile: C[128,64] = A[128,K] * B[64,K]^T, bf16 hi/lo x3 MMA.
// K = nchunk*32; register-prefetch pipelined: next chunk's gmem loads are
// issued before the MMA block so L2 latency overlaps tensor compute.
// A planes: row pitch lda. B planes: [n][k] row pitch ldbk.
// ---------------------------------------------------------------------------
__device__ void ttile(
    __nv_bfloat16 (*sAh)[KP], __nv_bfloat16 (*sAl)[KP],
    __nv_bfloat16 (*sBh)[KP], __nv_bfloat16 (*sBl)[KP],
    const __nv_bfloat16* gAh, const __nv_bfloat16* gAl, int lda,
    const __nv_bfloat16* gBh, const __nv_bfloat16* gBl, int ldbk,
    float* C, int ldc, int nchunk)
{
    const int tid = threadIdx.x;
    const int lane = tid & 31, w = tid >> 5;
    const int wm = w & 3, wn = w >> 2;          // 4 warps M x 2 warps N
    const int g = lane >> 2, tig = lane & 3;

    // per-thread load coordinates
    const int ar = tid >> 2;            // A rows ar and ar+64
    const int ac = (tid & 3) * 8;       // col within 32-wide chunk
    const __nv_bfloat16* pAh0 = gAh + (size_t)ar * lda + ac;
    const __nv_bfloat16* pAh1 = gAh + (size_t)(ar + 64) * lda + ac;
    const __nv_bfloat16* pAl0 = gAl + (size_t)ar * lda + ac;
    const __nv_bfloat16* pAl1 = gAl + (size_t)(ar + 64) * lda + ac;
    const __nv_bfloat16* pBh  = gBh + (size_t)ar * ldbk + ac;   // B rows 0..63
    const __nv_bfloat16* pBl  = gBl + (size_t)ar * ldbk + ac;

    float acc[2][4][4];
#pragma unroll
    for (int ms = 0; ms < 2; ms++)
#pragma unroll
        for (int ns = 0; ns < 4; ns++)
#pragma unroll
            for (int q = 0; q < 4; q++) acc[ms][ns][q] = 0.f;

    // prefetch chunk 0
    uint4 ra_h0 = __ldcg((const uint4*)pAh0);
    uint4 ra_h1 = __ldcg((const uint4*)pAh1);
    uint4 ra_l0 = __ldcg((const uint4*)pAl0);
    uint4 ra_l1 = __ldcg((const uint4*)pAl1);
    uint4 rb_h  = *(const uint4*)pBh;
    uint4 rb_l  = *(const uint4*)pBl;

    for (int ch = 0; ch < nchunk; ch++) {
        // store prefetched regs to smem
        *(uint4*)&sAh[ar][ac]      = ra_h0;
        *(uint4*)&sAh[ar + 64][ac] = ra_h1;
        *(uint4*)&sAl[ar][ac]      = ra_l0;
        *(uint4*)&sAl[ar + 64][ac] = ra_l1;
        *(uint4*)&sBh[ar][ac]      = rb_h;
        *(uint4*)&sBl[ar][ac]      = rb_l;
        __syncthreads();

        // issue next chunk's loads (latency hidden under MMA below)
        if (ch + 1 < nchunk) {
            int kb = (ch + 1) * 32;
            ra_h0 = __ldcg((const uint4*)(pAh0 + kb));
            ra_h1 = __ldcg((const uint4*)(pAh1 + kb));
            ra_l0 = __ldcg((const uint4*)(pAl0 + kb));
            ra_l1 = __ldcg((const uint4*)(pAl1 + kb));
            rb_h  = *(const uint4*)(pBh + kb);
            rb_l  = *(const uint4*)(pBl + kb);
        }

#pragma unroll
        for (int kk = 0; kk < 2; kk++) {
            const int ko = kk * 16 + tig * 2;
            uint32_t ah[2][4], al[2][4];
#pragma unroll
            for (int ms = 0; ms < 2; ms++) {
                const __nv_bfloat16* ba = &sAh[wm * 32 + ms * 16 + g][0];
                const __nv_bfloat16* bl = &sAl[wm * 32 + ms * 16 + g][0];
                ah[ms][0] = *(const uint32_t*)&ba[ko];
                ah[ms][1] = *(const uint32_t*)&ba[8 * KP + ko];
                ah[ms][2] = *(const uint32_t*)&ba[ko + 8];
                ah[ms][3] = *(const uint32_t*)&ba[8 * KP + ko + 8];
                al[ms][0] = *(const uint32_t*)&bl[ko];
                al[ms][1] = *(const uint32_t*)&bl[8 * KP + ko];
                al[ms][2] = *(const uint32_t*)&bl[ko + 8];
                al[ms][3] = *(const uint32_t*)&bl[8 * KP + ko + 8];
            }
#pragma unroll
            for (int ns = 0; ns < 4; ns++) {
                const __nv_bfloat16* bb = &sBh[wn * 32 + ns * 8 + g][0];
                const __nv_bfloat16* bc = &sBl[wn * 32 + ns * 8 + g][0];
                uint32_t bh[2], blo[2];
                bh[0]  = *(const uint32_t*)&bb[ko];
                bh[1]  = *(const uint32_t*)&bb[ko + 8];
                blo[0] = *(const uint32_t*)&bc[ko];
                blo[1] = *(const uint32_t*)&bc[ko + 8];
#pragma unroll
                for (int ms = 0; ms < 2; ms++) {
                    mma16816(acc[ms][ns], ah[ms], bh);
                    mma16816(acc[ms][ns], ah[ms], blo);
                    mma16816(acc[ms][ns], al[ms], bh);
                }
            }
        }
        __syncthreads();
    }

    // ---- epilogue ----
#pragma unroll
    for (int ms = 0; ms < 2; ms++) {
#pragma unroll
        for (int ns = 0; ns < 4; ns++) {
            int row0 = wm * 32 + ms * 16 + g;
            int col = wn * 32 + ns * 8 + tig * 2;
            float2 v0; v0.x = acc[ms][ns][0]; v0.y = acc[ms][ns][1];
            float2 v1; v1.x = acc[ms][ns][2]; v1.y = acc[ms][ns][3];
            *(float2*)&C[(size_t)row0 * ldc + col] = v0;
            *(float2*)&C[(size_t)(row0 + 8) * ldc + col] = v1;
        }
    }
}

// ---------------------------------------------------------------------------
// Setup tensor GEMM: [XW | hypX] = x @ W0^T  (M=65536, N=5120, K=256)
// ---------------------------------------------------------------------------
__global__ __launch_bounds__(NT_) void xw_tensor_k()
{
    __shared__ __align__(16) __nv_bfloat16 sAh[128][KP];
    __shared__ __align__(16) __nv_bfloat16 sAl[128][KP];
    __shared__ __align__(16) __nv_bfloat16 sBh[64][KP];
    __shared__ __align__(16) __nv_bfloat16 sBl[64][KP];

    const int n0 = blockIdx.x * 64;
    const size_t m0 = (size_t)blockIdx.y * 128;
    float* C;
    int ldc;
    if (n0 < H4) { C = g_XW + m0 * H4 + n0; ldc = H4; }
    else         { C = g_hypX + m0 * HH4 + (n0 - H4); ldc = HH4; }
    ttile(sAh, sAl, sBh, sBl,
          g_xhi + m0 * D_, g_xlo + m0 * D_, D_,
          g_W0hi + (size_t)n0 * D_, g_W0lo + (size_t)n0 * D_, D_,
          C, ldc, 8);
}

// ---------------------------------------------------------------------------
// Persistent kernel: whole T=512 recurrence + final FC.
// Dependence-precise gating: P1 reads state cols [0,1024) only; P2 writes
// cols [1024,1280) and reads only P1's hyper-row slabs -> P2 gates on the 64
// hyper tiles (issued first), letting the 256 main tiles overlap P2+P3.
// ---------------------------------------------------------------------------
__global__ __launch_bounds__(NT_, 2) void hyperlstm_persist(
    const float* __restrict__ hypbx, const float* __restrict__ hypbh,
    const float* __restrict__ hlnag, const float* __restrict__ hlnab,
    const float* __restrict__ hlng, const float* __restrict__ hlnb,
    const float* __restrict__ bias,
    const float* __restrict__ lnag, const float* __restrict__ lnab,
    const float* __restrict__ lng, const float* __restrict__ lnb,
    const float* __restrict__ fcW, const float* __restrict__ fcb,
    float* __restrict__ out)
{
    __shared__ __align__(16) __nv_bfloat16 sAh[128][KP];
    __shared__ __align__(16) __nv_bfloat16 sAl[128][KP];
    __shared__ __align__(16) __nv_bfloat16 sBh[64][KP];
    __shared__ __align__(16) __nv_bfloat16 sBl[64][KP];
    __shared__ float sred[32];
    __shared__ unsigned s_tile;

    const int tid = threadIdx.x;

    for (int t = 0; t < T_; t++) {
        unsigned* tixP1 = &g_tix[t * NPH + 0];
        unsigned* tixP2 = &g_tix[t * NPH + 1];
        unsigned* tixP3 = &g_tix[t * NPH + 2];
        unsigned* tixP4 = &g_tix[t * NPH + 3];
        unsigned* donP1 = &g_done[t * NPH + 0];
        unsigned* donP2 = &g_done[t * NPH + 1];
        unsigned* donP3 = &g_done[t * NPH + 2];
        unsigned* donP4 = &g_done[t * NPH + 3];

        // ----- P1: rec GEMM from h : N=5120, K=1024 (hyper tiles first) -----
        if (t > 0) gate(&g_done[(t - 1) * NPH + 3], B_);
        for (;;) {
            int k = grab(tixP1, P1_TILES, &s_tile);
            if (k < 0) break;
            int n0, ks;
            bool hyp_tile = (k < P1_HYP);
            if (hyp_tile) { n0 = H4 + (k >> 2) * 64; ks = k & 3; }
            else { int k2 = k - P1_HYP; n0 = (k2 >> 2) * 64; ks = k2 & 3; }
            int kb = ks * 256;
            ttile(sAh, sAl, sBh, sBl,
                  g_sthi + kb, g_stlo + kb, RECK,
                  g_W1hi + (size_t)n0 * H_ + kb, g_W1lo + (size_t)n0 * H_ + kb, H_,
                  g_recP1 + (size_t)ks * RECSLAB + n0, NREC, 8);
            __threadfence();
            __syncthreads();
            if (tid == 0) {
                atomicAdd(donP1, 1u);
                if (hyp_tile) atomicAdd(&g_doneH[t], 1u);
            }
        }

        // ----- P2: hyper cell (gates only on the 64 hyper tiles) -----
        gate(&g_doneH[t], P1_HYP);
        for (;;) {
            int b = grab(tixP2, B_, &s_tile);
            if (b < 0) break;
            const int j = tid;
            const int par = t & 1;
            const float* hx = g_hypX + ((size_t)t * B_ + b) * HH4;
            float v[4];
#pragma unroll
            for (int gk = 0; gk < 4; gk++) {
                int n = gk * HHYP + j;
                float s = hx[n] + hypbx[n] + hypbh[n];
#pragma unroll
                for (int sl = 0; sl < P1S; sl++)
                    s += __ldcg(&g_recP1[(size_t)sl * RECSLAB + (size_t)b * NREC + H4 + n]);
                s += __ldcg(&g_recHH[(size_t)par * (B_ * HH4) + (size_t)b * HH4 + n]);
                v[gk] = s;
            }
            float nv[4];
#pragma unroll
            for (int gk = 0; gk < 4; gk++) {
                float m = block_sum256(v[gk], sred) * (1.f / 256.f);
                float xs = v[gk] - m;
                float var = block_sum256(xs * xs, sred) * (1.f / 256.f);
                int n = gk * HHYP + j;
                nv[gk] = hlnag[n] * (xs * rsqrtf(var + EPSLN)) + hlnab[n];
            }
            float ch = __ldcg(&g_ch[b * HHYP + j]);
            float chn = sigf(nv[1]) * ch + sigf(nv[0]) * tanhf(nv[2]);
            float m = block_sum256(chn, sred) * (1.f / 256.f);
            float xs = chn - m;
            float var = block_sum256(xs * xs, sred) * (1.f / 256.f);
            float hn = hlng[j] * (xs * rsqrtf(var + EPSLN)) + hlnb[j];
            float hyp = sigf(nv[3]) * tanhf(hn);
            g_ch[b * HHYP + j] = chn;
            size_t sidx = (size_t)b * RECK + H_ + j;
            g_state[sidx] = hyp;
            __nv_bfloat16 hh, hl; split_bf16(hyp, hh, hl);
            g_sthi[sidx] = hh; g_stlo[sidx] = hl;
            mark(donP2);
        }
        gate(donP2, B_);

        // ----- P3: mod GEMM (K=256 whole) + next-step rec-hh -----
        {
            const int parN = (t + 1) & 1;
            for (;;) {
                int k = grab(tixP3, P3_TILES, &s_tile);
                if (k < 0) break;
                if (k < P3_MODT) {
                    int n0 = k * 64;
                    ttile(sAh, sAl, sBh, sBl,
                          g_sthi + H_, g_stlo + H_, RECK,
                          g_Mthi + (size_t)n0 * HHYP, g_Mtlo + (size_t)n0 * HHYP, HHYP,
                          g_modS + n0, MODN, 8);
                } else {
                    int n0 = (k - P3_MODT) * 64;
                    ttile(sAh, sAl, sBh, sBl,
                          g_sthi + H_, g_stlo + H_, RECK,
                          g_WHhi + (size_t)n0 * HHYP, g_WHlo + (size_t)n0 * HHYP, HHYP,
                          g_recHH + (size_t)parN * (B_ * HH4) + n0, HH4, 8);
                }
                mark(donP3);
            }
        }
        gate(donP3, P3_TILES);
        gate(donP1, P1_TILES);   // P4 needs the main-row slabs too

        // ----- P4: main cell -----
        for (;;) {
            int b = grab(tixP4, B_, &s_tile);
            if (b < 0) break;
            const int j = tid;
            const float* xw = g_XW + ((size_t)t * B_ + b) * H4;
            const float* mp = g_modS + (size_t)b * MODN;
            float pre[4][4];
#pragma unroll
            for (int gk = 0; gk < 4; gk++) {
#pragma unroll
                for (int q = 0; q < 4; q++) {
                    int n = gk * H_ + q * 256 + j;
                    float hg = 0.f;
#pragma unroll
                    for (int sl = 0; sl < P1S; sl++)
                        hg += __ldcg(&g_recP1[(size_t)sl * RECSLAB + (size_t)b * NREC + n]);
                    float sx = __ldcg(&mp[n]) + g_csc[n];
                    float sh = __ldcg(&mp[4 * H_ + n]) + g_csc[4 * H_ + n];
                    float ba = __ldcg(&mp[8 * H_ + n]);
                    pre[gk][q] = fmaf(sx, xw[n], fmaf(sh, hg, bias[n] + ba));
                }
            }
            float nv[4][4];
#pragma unroll
            for (int gk = 0; gk < 4; gk++) {
                float p = pre[gk][0] + pre[gk][1] + pre[gk][2] + pre[gk][3];
                float m = block_sum256(p, sred) * (1.f / 1024.f);
                float vs = 0.f;
#pragma unroll
                for (int q = 0; q < 4; q++) { float d = pre[gk][q] - m; vs += d * d; }
                float var = block_sum256(vs, sred) * (1.f / 1024.f);
                float rs = rsqrtf(var + EPSLN);
#pragma unroll
                for (int q = 0; q < 4; q++) {
                    int n = gk * H_ + q * 256 + j;
                    nv[gk][q] = lnag[n] * ((pre[gk][q] - m) * rs) + lnab[n];
                }
            }
            float cn[4];
            float psum = 0.f;
#pragma unroll
            for (int q = 0; q < 4; q++) {
                int idx = q * 256 + j;
                float c = __ldcg(&g_c[b * H_ + idx]);
                cn[q] = sigf(nv[2][q]) * c + sigf(nv[0][q]) * tanhf(nv[1][q]);
                g_c[b * H_ + idx] = cn[q];
                psum += cn[q];
            }
            float m = block_sum256(psum, sred) * (1.f / 1024.f);
            float vs = 0.f;
#pragma unroll
            for (int q = 0; q < 4; q++) { float d = cn[q] - m; vs += d * d; }
            float var = block_sum256(vs, sred) * (1.f / 1024.f);
            float rs = rsqrtf(var + EPSLN);
#pragma unroll
            for (int q = 0; q < 4; q++) {
                int idx = q * 256 + j;
                float lc = lng[idx] * ((cn[q] - m) * rs) + lnb[idx];
                float h = sigf(nv[3][q]) * tanhf(lc);
                size_t sidx = (size_t)b * RECK + idx;
                g_state[sidx] = h;
                __nv_bfloat16 hh, hl; split_bf16(h, hh, hl);
                g_sthi[sidx] = hh; g_stlo[sidx] = hl;
            }
            mark(donP4);
        }
    }

    // ----- final FC: out = h @ fcW^T + fcb -----
    gate(&g_done[(T_ - 1) * NPH + 3], B_);
    for (;;) {
        int b = grab(&g_tix[T_ * NPH], B_, &s_tile);
        if (b < 0) break;
        float* sh = (float*)&sAh[0][0];   // 1024 floats fit in 10240-byte buffer
        float* sp = (float*)&sBh[0][0];   // 256 floats fit in 5120-byte buffer
        for (int i = tid; i < H_; i += NT_) sh[i] = __ldcg(&g_state[(size_t)b * RECK + i]);
        __syncthreads();
        int o = tid & 127, half = tid >> 7;
        const float* w = fcW + (size_t)o * H_ + half * 512;
        const float* hv = sh + half * 512;
        float s = 0.f;
        for (int k = 0; k < 512; k++) s = fmaf(hv[k], w[k], s);
        sp[tid] = s;
        __syncthreads();
        if (tid < NOUT)
            out[(size_t)b * NOUT + tid] = sp[tid] + sp[128 + tid] + fcb[tid];
        __syncthreads();
    }
}

// ---------------------------------------------------------------------------
// Launch
// ---------------------------------------------------------------------------
extern "C" void kernel_launch(void* const* d_in, const int* in_sizes, int n_in,
                              void* d_out, int out_size)
{
    const float* x      = (const float*)d_in[0];
    const float* Wx     = (const float*)d_in[1];
    const float* Wh     = (const float*)d_in[2];
    const float* bias   = (const float*)d_in[3];
    const float* lnag   = (const float*)d_in[4];
    const float* lnab   = (const float*)d_in[5];
    const float* lng    = (const float*)d_in[6];
    const float* lnb    = (const float*)d_in[7];
    const float* zb     = (const float*)d_in[8];
    const float* zbeta  = (const float*)d_in[9];
    const float* zw_w   = (const float*)d_in[10];
    const float* zw_b   = (const float*)d_in[11];
    const float* alpha  = (const float*)d_in[12];
    const float* hypWx  = (const float*)d_in[13];
    const float* hypbx  = (const float*)d_in[14];
    const float* hypWh  = (const float*)d_in[15];
    const float* hypbh  = (const float*)d_in[16];
    const float* hlnag  = (const float*)d_in[17];
    const float* hlnab  = (const float*)d_in[18];
    const float* hlng   = (const float*)d_in[19];
    const float* hlnb   = (const float*)d_in[20];
    const float* fc_W   = (const float*)d_in[21];
    const float* fc_b   = (const float*)d_in[22];
    float* out = (float*)d_out;

    float* pMcat;
    cudaGetSymbolAddress((void**)&pMcat, g_Mcat);

    // ---- setup ----
    init_k<<<(2 * B_ * HH4 + 255) / 256, 256>>>();
    csc_k<<<dim3(8, 4), 256>>>(zw_b, alpha);
    convW1_k<<<(int)(((size_t)NREC * H_ + 255) / 256), 256>>>(Wh, hypWx);
    convW0_k<<<(int)(((size_t)NREC * D_ + 255) / 256), 256>>>(Wx, hypWx);
    convWH_k<<<(int)(((size_t)HH4 * HHYP + 255) / 256), 256>>>(hypWh);
    convX_k<<<(int)(((size_t)T_ * B_ * D_ + 255) / 256), 256>>>(x);

    // Mcat: 12 GEMMs (256 x 1024 x 256), NN layout (fp32 — exact)
    for (int s = 0; s < 12; s++) {
        const float* Am = (s < 8) ? zw_w + (size_t)s * HHYP * HHYP
                                  : zb + (size_t)(s - 8) * HHYP * HHYP;
        const float* Bn = (s < 8) ? alpha + (size_t)s * HHYP * H_
                                  : zbeta + (size_t)(s - 8) * HHYP * H_;
        gemm_k<128, 64, 16, 8, 4, false><<<dim3(16, 2), 256>>>(
            HHYP, Am, HHYP, Bn, H_, pMcat + s * H_, MODN);
    }
    convMt_k<<<(int)(((size_t)MODN * HHYP + 255) / 256), 256>>>();

    // [XW | hypX] = x @ W0^T on tensor cores
    xw_tensor_k<<<dim3(NREC / 64, (T_ * B_) / 128), NT_>>>();

    // ---- whole recurrence + final FC in ONE residency-oblivious kernel ----
    hyperlstm_persist<<<G_, NT_>>>(
        hypbx, hypbh, hlnag, hlnab, hlng, hlnb,
        bias, lnag, lnab, lng, lnb, fc_W, fc_b, out);
}

// round 15
// speedup vs baseline: 2.4331x; 1.0739x over previous
#include <cuda_runtime.h>
#include <cuda_bf16.h>
#include <math.h>
#include <stdint.h>

// ---------------------------------------------------------------------------
// Problem constants
// ---------------------------------------------------------------------------
#define T_ 512
#define B_ 128
#define D_ 256
#define H_ 1024      // main hidden
#define HHYP 256     // hyper hidden
#define H4 4096      // 4*H
#define HH4 1024     // 4*HHYP
#define NOUT 128
#define MODN 12288   // 8*H (sc) + 4*H (badj)
#define NREC 5120    // 4096 main rows + 1024 hyper rows
#define RECK 1280    // state length = H + HHYP
#define EPSLN 1e-3f

#define G_ 296       // launched CTAs; design does NOT require co-residency
#define NT_ 256

// phase tiling (BM=128, BN=64; K processed in 32-wide chunks)
#define P1_HYPT 128            // 16 n-tiles * 8 k-splits (K=1024, 128/ticket)
#define P1_MAINT 128           // 64 n-tiles * 2 k-splits (K=1024, 512/ticket)
#define P1_TILES (P1_HYPT + P1_MAINT)
#define HYPS 8                 // hyper slabs
#define MAINS 2                // main slabs
#define P3_MODT 192            // 192 n-tiles, K=256 whole  (1 slab)
#define P3_RHHT 16             // 16 n-tiles, K=256 whole
#define P3_TILES (P3_MODT + P3_RHHT)
#define NPH 4

#define KP 40   // smem row pitch (bf16 elems) for 32-wide k chunks

// ---------------------------------------------------------------------------
// Device scratch
// ---------------------------------------------------------------------------
__device__ alignas(16) float g_XW[(size_t)T_ * B_ * H4];     // 1 GiB
__device__ alignas(16) float g_hypX[(size_t)T_ * B_ * HH4];  // 256 MiB
__device__ alignas(16) float g_Mcat[(size_t)HHYP * MODN];
__device__ alignas(16) float g_csc[8 * H_];
__device__ alignas(16) float g_state[B_ * RECK];             // fp32 [h | hyp]
__device__ alignas(16) float g_c[B_ * H_];
__device__ alignas(16) float g_ch[B_ * HHYP];
__device__ alignas(16) float g_recP1[(size_t)MAINS * B_ * H4];  // main slabs (4 MB)
__device__ alignas(16) float g_recHyp[(size_t)HYPS * B_ * HH4]; // hyper slabs (4 MB)
__device__ alignas(16) float g_modS[(size_t)B_ * MODN];      // 6.3 MiB (single slab)
__device__ alignas(16) float g_recHH[2 * B_ * HH4];          // parity double buffer

// bf16 hi/lo planes
__device__ alignas(16) __nv_bfloat16 g_sthi[B_ * RECK];
__device__ alignas(16) __nv_bfloat16 g_stlo[B_ * RECK];
__device__ alignas(16) __nv_bfloat16 g_W1hi[(size_t)NREC * H_];   // [n][k] packed Wh | hypWx_h
__device__ alignas(16) __nv_bfloat16 g_W1lo[(size_t)NREC * H_];
__device__ alignas(16) __nv_bfloat16 g_WHhi[(size_t)HH4 * HHYP];  // hypWh [n][k]
__device__ alignas(16) __nv_bfloat16 g_WHlo[(size_t)HH4 * HHYP];
__device__ alignas(16) __nv_bfloat16 g_Mthi[(size_t)MODN * HHYP]; // Mcat^T [n][k]
__device__ alignas(16) __nv_bfloat16 g_Mtlo[(size_t)MODN * HHYP];
__device__ alignas(16) __nv_bfloat16 g_xhi[(size_t)T_ * B_ * D_]; // x planes
__device__ alignas(16) __nv_bfloat16 g_xlo[(size_t)T_ * B_ * D_];
__device__ alignas(16) __nv_bfloat16 g_W0hi[(size_t)NREC * D_];   // [n][k] packed Wx | hypWx_x
__device__ alignas(16) __nv_bfloat16 g_W0lo[(size_t)NREC * D_];

// dataflow state
__device__ unsigned g_tix[T_ * NPH + 1];
__device__ unsigned g_done[T_ * NPH + 1];
__device__ unsigned g_doneH[T_];      // P1 hyper-tile completion (gates P2 early)

// ---------------------------------------------------------------------------
// Setup: split helper
// ---------------------------------------------------------------------------
__device__ __forceinline__ void split_bf16(float x, __nv_bfloat16& h, __nv_bfloat16& l)
{
    h = __float2bfloat16(x);
    l = __float2bfloat16(x - __bfloat162float(h));
}

// launch #1: zero state + counters
__global__ void init_k()
{
    size_t i = (size_t)blockIdx.x * 256 + threadIdx.x;
    if (i < (size_t)B_ * RECK) {
        g_state[i] = 0.f;
        g_sthi[i] = __float2bfloat16(0.f);
        g_stlo[i] = __float2bfloat16(0.f);
    }
    if (i < (size_t)B_ * H_)   g_c[i] = 0.f;
    if (i < (size_t)B_ * HHYP) g_ch[i] = 0.f;
    if (i < (size_t)2 * B_ * HH4) g_recHH[i] = 0.f;
    if (i < (size_t)(T_ * NPH + 1)) { g_tix[i] = 0u; g_done[i] = 0u; }
    if (i < (size_t)T_) g_doneH[i] = 0u;
}

// launch #2: all input conversions + csc, fused (all independent)
__global__ void setupAll_k(const float* __restrict__ x,
                           const float* __restrict__ Wx,
                           const float* __restrict__ Wh,
                           const float* __restrict__ hypWx,
                           const float* __restrict__ hypWh,
                           const float* __restrict__ zw_b,
                           const float* __restrict__ alpha)
{
    size_t i = (size_t)blockIdx.x * 256 + threadIdx.x;
    // convX: T*B*D = 16,777,216 (largest range)
    if (i < (size_t)T_ * B_ * D_)
        split_bf16(x[i], g_xhi[i], g_xlo[i]);
    // convW1: NREC*H = 5,242,880
    if (i < (size_t)NREC * H_) {
        int n = (int)(i / H_), k = (int)(i % H_);
        float v = (n < H4) ? Wh[(size_t)n * H_ + k]
                           : hypWx[(size_t)(n - H4) * (D_ + H_) + D_ + k];
        split_bf16(v, g_W1hi[i], g_W1lo[i]);
    }
    // convW0: NREC*D = 1,310,720
    if (i < (size_t)NREC * D_) {
        int n = (int)(i / D_), k = (int)(i % D_);
        float v = (n < H4) ? Wx[(size_t)n * D_ + k]
                           : hypWx[(size_t)(n - H4) * (D_ + H_) + k];
        split_bf16(v, g_W0hi[i], g_W0lo[i]);
    }
    // convWH: HH4*HHYP = 262,144
    if (i < (size_t)HH4 * HHYP)
        split_bf16(hypWh[i], g_WHhi[i], g_WHlo[i]);
    // csc: 8*H = 8192 entries, each a 256-long dot
    if (i < (size_t)(8 * H_)) {
        int k = (int)(i / H_), h = (int)(i % H_);
        float s = 0.f;
        const float* zb = zw_b + (size_t)k * HHYP;
        const float* al = alpha + (size_t)k * HHYP * H_;
        for (int p = 0; p < HHYP; p++) s = fmaf(zb[p], al[(size_t)p * H_ + h], s);
        g_csc[i] = s;
    }
}

// launch #3: Mcat = 12 fused GEMMs (256 x 1024 x 256) NN, z = which GEMM
__global__ __launch_bounds__(256) void gemmAll_k(
    const float* __restrict__ zw_w, const float* __restrict__ zb,
    const float* __restrict__ alpha, const float* __restrict__ zbeta)
{
    const int s = blockIdx.z;
    const float* A = (s < 8) ? zw_w + (size_t)s * HHYP * HHYP
                             : zb + (size_t)(s - 8) * HHYP * HHYP;
    const float* Bm = (s < 8) ? alpha + (size_t)s * HHYP * H_
                              : zbeta + (size_t)(s - 8) * HHYP * H_;
    float* C = g_Mcat + s * H_;
    const int lda = HHYP, ldb = H_, ldc = MODN;

    const int n0 = blockIdx.x * 64;
    const int m0 = blockIdx.y * 128;
    A += (size_t)m0 * lda;
    Bm += n0;
    C += (size_t)m0 * ldc + n0;

    __shared__ float As[16][132];
    __shared__ float Bs[16][68];
    const int tid = threadIdx.x;
    const int tx = tid % 16;
    const int ty = tid / 16;

    float acc[8][4];
#pragma unroll
    for (int i = 0; i < 8; i++)
#pragma unroll
        for (int j = 0; j < 4; j++) acc[i][j] = 0.f;

    for (int kt = 0; kt < HHYP; kt += 16) {
#pragma unroll
        for (int l = 0; l < 2; l++) {
            int idx = tid + l * 256;
            int r = idx / 4;
            int c4 = idx % 4;
            float4 v = *(const float4*)(A + (size_t)r * lda + c4 * 4);
            As[c4 * 4 + 0][r] = v.x; As[c4 * 4 + 1][r] = v.y;
            As[c4 * 4 + 2][r] = v.z; As[c4 * 4 + 3][r] = v.w;
        }
        {
            int r = tid / 16;
            int c4 = tid % 16;
            float4 v = *(const float4*)(Bm + (size_t)r * ldb + c4 * 4);
            *(float4*)&Bs[r][c4 * 4] = v;
        }
        __syncthreads();
#pragma unroll
        for (int k = 0; k < 16; k++) {
            float a[8], bv[4];
#pragma unroll
            for (int i = 0; i < 8; i += 4) {
                float4 v = *(const float4*)&As[k][ty * 8 + i];
                a[i] = v.x; a[i + 1] = v.y; a[i + 2] = v.z; a[i + 3] = v.w;
            }
            float4 vb = *(const float4*)&Bs[k][tx * 4];
            bv[0] = vb.x; bv[1] = vb.y; bv[2] = vb.z; bv[3] = vb.w;
#pragma unroll
            for (int i = 0; i < 8; i++)
#pragma unroll
                for (int j = 0; j < 4; j++)
                    acc[i][j] = fmaf(a[i], bv[j], acc[i][j]);
        }
        __syncthreads();
        A += 16;
        Bm += (size_t)16 * ldb;
    }
#pragma unroll
    for (int i = 0; i < 8; i++) {
        float4 o; o.x = acc[i][0]; o.y = acc[i][1]; o.z = acc[i][2]; o.w = acc[i][3];
        *(float4*)(C + (size_t)(ty * 8 + i) * ldc + tx * 4) = o;
    }
}

// launch #5: transpose Mcat -> [n][k] hi/lo planes
__global__ void convMt_k()
{
    size_t idx = (size_t)blockIdx.x * 256 + threadIdx.x;
    if (idx >= (size_t)MODN * HHYP) return;
    int n = (int)(idx / HHYP), k = (int)(idx % HHYP);
    split_bf16(g_Mcat[(size_t)k * MODN + n], g_Mthi[idx], g_Mtlo[idx]);
}

// ---------------------------------------------------------------------------
// Shared helpers
// ---------------------------------------------------------------------------
__device__ __forceinline__ float sigf(float x) { return 1.f / (1.f + expf(-x)); }

__device__ __forceinline__ float block_sum256(float v, float* sbuf)
{
    const int tid = threadIdx.x;
#pragma unroll
    for (int o = 16; o > 0; o >>= 1) v += __shfl_xor_sync(0xffffffffu, v, o);
    const int warp = tid >> 5, lane = tid & 31;
    if (lane == 0) sbuf[warp] = v;
    __syncthreads();
    float s = (tid < 8) ? sbuf[tid] : 0.f;
    if (warp == 0) {
#pragma unroll
        for (int o = 4; o > 0; o >>= 1) s += __shfl_xor_sync(0xffffffffu, s, o);
        if (lane == 0) sbuf[0] = s;
    }
    __syncthreads();
    float r = sbuf[0];
    __syncthreads();
    return r;
}

__device__ __forceinline__ int grab(unsigned* ctr, unsigned limit, unsigned* s_tile)
{
    __syncthreads();
    if (threadIdx.x == 0) *s_tile = atomicAdd(ctr, 1u);
    __syncthreads();
    unsigned k = *s_tile;
    return (k < limit) ? (int)k : -1;
}

__device__ __forceinline__ void mark(unsigned* cnt)
{
    __threadfence();
    __syncthreads();
    if (threadIdx.x == 0) atomicAdd(cnt, 1u);
}

__device__ __forceinline__ void gate(const unsigned* cnt, unsigned target)
{
    if (threadIdx.x == 0) {
        while (*(volatile const unsigned*)cnt < target) __nanosleep(64);
        __threadfence();
    }
    __syncthreads();
}

__device__ __forceinline__ void mma16816(float* d, const uint32_t* a, const uint32_t* b)
{
    asm volatile(
        "mma.sync.aligned.m16n8k16.row.col.f32.bf16.bf16.f32 "
        "{%0,%1,%2,%3}, {%4,%5,%6,%7}, {%8,%9}, {%0,%1,%2,%3};\n"
        : "+f"(d[0]), "+f"(d[1]), "+f"(d[2]), "+f"(d[3])
        : "r"(a[0]), "r"(a[1]), "r"(a[2]), "r"(a[3]), "r"(b[0]), "r"(b[1]));
}

// ---------------------------------------------------------------------------
// Tensor GEMM tile: C[128,64] = A[128,K] * B[64,K]^T, bf16 hi/lo x3 MMA.
// K = nchunk*32; register-prefetch pipelined.
// ---------------------------------------------------------------------------
__device__ void ttile(
    __nv_bfloat16 (*sAh)[KP], __nv_bfloat16 (*sAl)[KP],
    __nv_bfloat16 (*sBh)[KP], __nv_bfloat16 (*sBl)[KP],
    const __nv_bfloat16* gAh, const __nv_bfloat16* gAl, int lda,
    const __nv_bfloat16* gBh, const __nv_bfloat16* gBl, int ldbk,
    float* C, int ldc, int nchunk)
{
    const int tid = threadIdx.x;
    const int lane = tid & 31, w = tid >> 5;
    const int wm = w & 3, wn = w >> 2;          // 4 warps M x 2 warps N
    const int g = lane >> 2, tig = lane & 3;

    const int ar = tid >> 2;            // A rows ar and ar+64
    const int ac = (tid & 3) * 8;       // col within 32-wide chunk
    const __nv_bfloat16* pAh0 = gAh + (size_t)ar * lda + ac;
    const __nv_bfloat16* pAh1 = gAh + (size_t)(ar + 64) * lda + ac;
    const __nv_bfloat16* pAl0 = gAl + (size_t)ar * lda + ac;
    const __nv_bfloat16* pAl1 = gAl + (size_t)(ar + 64) * lda + ac;
    const __nv_bfloat16* pBh  = gBh + (size_t)ar * ldbk + ac;   // B rows 0..63
    const __nv_bfloat16* pBl  = gBl + (size_t)ar * ldbk + ac;

    float acc[2][4][4];
#pragma unroll
    for (int ms = 0; ms < 2; ms++)
#pragma unroll
        for (int ns = 0; ns < 4; ns++)
#pragma unroll
            for (int q = 0; q < 4; q++) acc[ms][ns][q] = 0.f;

    uint4 ra_h0 = __ldcg((const uint4*)pAh0);
    uint4 ra_h1 = __ldcg((const uint4*)pAh1);
    uint4 ra_l0 = __ldcg((const uint4*)pAl0);
    uint4 ra_l1 = __ldcg((const uint4*)pAl1);
    uint4 rb_h  = *(const uint4*)pBh;
    uint4 rb_l  = *(const uint4*)pBl;

    for (int ch = 0; ch < nchunk; ch++) {
        *(uint4*)&sAh[ar][ac]      = ra_h0;
        *(uint4*)&sAh[ar + 64][ac] = ra_h1;
        *(uint4*)&sAl[ar][ac]      = ra_l0;
        *(uint4*)&sAl[ar + 64][ac] = ra_l1;
        *(uint4*)&sBh[ar][ac]      = rb_h;
        *(uint4*)&sBl[ar][ac]      = rb_l;
        __syncthreads();

        if (ch + 1 < nchunk) {
            int kb = (ch + 1) * 32;
            ra_h0 = __ldcg((const uint4*)(pAh0 + kb));
            ra_h1 = __ldcg((const uint4*)(pAh1 + kb));
            ra_l0 = __ldcg((const uint4*)(pAl0 + kb));
            ra_l1 = __ldcg((const uint4*)(pAl1 + kb));
            rb_h  = *(const uint4*)(pBh + kb);
            rb_l  = *(const uint4*)(pBl + kb);
        }

#pragma unroll
        for (int kk = 0; kk < 2; kk++) {
            const int ko = kk * 16 + tig * 2;
            uint32_t ah[2][4], al[2][4];
#pragma unroll
            for (int ms = 0; ms < 2; ms++) {
                const __nv_bfloat16* ba = &sAh[wm * 32 + ms * 16 + g][0];
                const __nv_bfloat16* bl = &sAl[wm * 32 + ms * 16 + g][0];
                ah[ms][0] = *(const uint32_t*)&ba[ko];
                ah[ms][1] = *(const uint32_t*)&ba[8 * KP + ko];
                ah[ms][2] = *(const uint32_t*)&ba[ko + 8];
                ah[ms][3] = *(const uint32_t*)&ba[8 * KP + ko + 8];
                al[ms][0] = *(const uint32_t*)&bl[ko];
                al[ms][1] = *(const uint32_t*)&bl[8 * KP + ko];
                al[ms][2] = *(const uint32_t*)&bl[ko + 8];
                al[ms][3] = *(const uint32_t*)&bl[8 * KP + ko + 8];
            }
#pragma unroll
            for (int ns = 0; ns < 4; ns++) {
                const __nv_bfloat16* bb = &sBh[wn * 32 + ns * 8 + g][0];
                const __nv_bfloat16* bc = &sBl[wn * 32 + ns * 8 + g][0];
                uint32_t bh[2], blo[2];
                bh[0]  = *(const uint32_t*)&bb[ko];
                bh[1]  = *(const uint32_t*)&bb[ko + 8];
                blo[0] = *(const uint32_t*)&bc[ko];
                blo[1] = *(const uint32_t*)&bc[ko + 8];
#pragma unroll
                for (int ms = 0; ms < 2; ms++) {
                    mma16816(acc[ms][ns], ah[ms], bh);
                    mma16816(acc[ms][ns], ah[ms], blo);
                    mma16816(acc[ms][ns], al[ms], bh);
                }
            }
        }
        __syncthreads();
    }

#pragma unroll
    for (int ms = 0; ms < 2; ms++) {
#pragma unroll
        for (int ns = 0; ns < 4; ns++) {
            int row0 = wm * 32 + ms * 16 + g;
            int col = wn * 32 + ns * 8 + tig * 2;
            float2 v0; v0.x = acc[ms][ns][0]; v0.y = acc[ms][ns][1];
            float2 v1; v1.x = acc[ms][ns][2]; v1.y = acc[ms][ns][3];
            *(float2*)&C[(size_t)row0 * ldc + col] = v0;
            *(float2*)&C[(size_t)(row0 + 8) * ldc + col] = v1;
        }
    }
}

// launch #4: [XW | hypX] = x @ W0^T  (M=65536, N=5120, K=256)
__global__ __launch_bounds__(NT_) void xw_tensor_k()
{
    __shared__ __align__(16) __nv_bfloat16 sAh[128][KP];
    __shared__ __align__(16) __nv_bfloat16 sAl[128][KP];
    __shared__ __align__(16) __nv_bfloat16 sBh[64][KP];
    __shared__ __align__(16) __nv_bfloat16 sBl[64][KP];

    const int n0 = blockIdx.x * 64;
    const size_t m0 = (size_t)blockIdx.y * 128;
    float* C;
    int ldc;
    if (n0 < H4) { C = g_XW + m0 * H4 + n0; ldc = H4; }
    else         { C = g_hypX + m0 * HH4 + (n0 - H4); ldc = HH4; }
    ttile(sAh, sAl, sBh, sBl,
          g_xhi + m0 * D_, g_xlo + m0 * D_, D_,
          g_W0hi + (size_t)n0 * D_, g_W0lo + (size_t)n0 * D_, D_,
          C, ldc, 8);
}

// ---------------------------------------------------------------------------
// launch #6: persistent kernel — whole T=512 recurrence + final FC.
// P1-hyper: 128 tiles of K=128 (8 slabs) gate P2 early; P1-main: 128 tiles of
// K=512 (2 slabs) overlap P2+P3 and gate P4.
// ---------------------------------------------------------------------------
__global__ __launch_bounds__(NT_, 2) void hyperlstm_persist(
    const float* __restrict__ hypbx, const float* __restrict__ hypbh,
    const float* __restrict__ hlnag, const float* __restrict__ hlnab,
    const float* __restrict__ hlng, const float* __restrict__ hlnb,
    const float* __restrict__ bias,
    const float* __restrict__ lnag, const float* __restrict__ lnab,
    const float* __restrict__ lng, const float* __restrict__ lnb,
    const float* __restrict__ fcW, const float* __restrict__ fcb,
    float* __restrict__ out)
{
    __shared__ __align__(16) __nv_bfloat16 sAh[128][KP];
    __shared__ __align__(16) __nv_bfloat16 sAl[128][KP];
    __shared__ __align__(16) __nv_bfloat16 sBh[64][KP];
    __shared__ __align__(16) __nv_bfloat16 sBl[64][KP];
    __shared__ float sred[32];
    __shared__ unsigned s_tile;

    const int tid = threadIdx.x;

    for (int t = 0; t < T_; t++) {
        unsigned* tixP1 = &g_tix[t * NPH + 0];
        unsigned* tixP2 = &g_tix[t * NPH + 1];
        unsigned* tixP3 = &g_tix[t * NPH + 2];
        unsigned* tixP4 = &g_tix[t * NPH + 3];
        unsigned* donP1 = &g_done[t * NPH + 0];
        unsigned* donP2 = &g_done[t * NPH + 1];
        unsigned* donP3 = &g_done[t * NPH + 2];
        unsigned* donP4 = &g_done[t * NPH + 3];

        // ----- P1: rec GEMM from h (hyper tiles first, K=128 each) -----
        if (t > 0) gate(&g_done[(t - 1) * NPH + 3], B_);
        for (;;) {
            int k = grab(tixP1, P1_TILES, &s_tile);
            if (k < 0) break;
            bool hyp_tile = (k < P1_HYPT);
            if (hyp_tile) {
                int nt = k >> 3, ks = k & 7;
                int n0 = nt * 64, kb = ks * 128;
                ttile(sAh, sAl, sBh, sBl,
                      g_sthi + kb, g_stlo + kb, RECK,
                      g_W1hi + (size_t)(H4 + n0) * H_ + kb,
                      g_W1lo + (size_t)(H4 + n0) * H_ + kb, H_,
                      g_recHyp + (size_t)ks * (B_ * HH4) + n0, HH4, 4);
            } else {
                int k2 = k - P1_HYPT;
                int nt = k2 >> 1, ks = k2 & 1;
                int n0 = nt * 64, kb = ks * 512;
                ttile(sAh, sAl, sBh, sBl,
                      g_sthi + kb, g_stlo + kb, RECK,
                      g_W1hi + (size_t)n0 * H_ + kb,
                      g_W1lo + (size_t)n0 * H_ + kb, H_,
                      g_recP1 + (size_t)ks * (B_ * H4) + n0, H4, 16);
            }
            __threadfence();
            __syncthreads();
            if (tid == 0) {
                atomicAdd(donP1, 1u);
                if (hyp_tile) atomicAdd(&g_doneH[t], 1u);
            }
        }

        // ----- P2: hyper cell (gates only on the 128 hyper tiles) -----
        gate(&g_doneH[t], P1_HYPT);
        for (;;) {
            int b = grab(tixP2, B_, &s_tile);
            if (b < 0) break;
            const int j = tid;
            const int par = t & 1;
            const float* hx = g_hypX + ((size_t)t * B_ + b) * HH4;
            float v[4];
#pragma unroll
            for (int gk = 0; gk < 4; gk++) {
                int n = gk * HHYP + j;
                float s = hx[n] + hypbx[n] + hypbh[n];
#pragma unroll
                for (int sl = 0; sl < HYPS; sl++)
                    s += __ldcg(&g_recHyp[(size_t)sl * (B_ * HH4) + (size_t)b * HH4 + n]);
                s += __ldcg(&g_recHH[(size_t)par * (B_ * HH4) + (size_t)b * HH4 + n]);
                v[gk] = s;
            }
            float nv[4];
#pragma unroll
            for (int gk = 0; gk < 4; gk++) {
                float m = block_sum256(v[gk], sred) * (1.f / 256.f);
                float xs = v[gk] - m;
                float var = block_sum256(xs * xs, sred) * (1.f / 256.f);
                int n = gk * HHYP + j;
                nv[gk] = hlnag[n] * (xs * rsqrtf(var + EPSLN)) + hlnab[n];
            }
            float ch = __ldcg(&g_ch[b * HHYP + j]);
            float chn = sigf(nv[1]) * ch + sigf(nv[0]) * tanhf(nv[2]);
            float m = block_sum256(chn, sred) * (1.f / 256.f);
            float xs = chn - m;
            float var = block_sum256(xs * xs, sred) * (1.f / 256.f);
            float hn = hlng[j] * (xs * rsqrtf(var + EPSLN)) + hlnb[j];
            float hyp = sigf(nv[3]) * tanhf(hn);
            g_ch[b * HHYP + j] = chn;
            size_t sidx = (size_t)b * RECK + H_ + j;
            g_state[sidx] = hyp;
            __nv_bfloat16 hh, hl; split_bf16(hyp, hh, hl);
            g_sthi[sidx] = hh; g_stlo[sidx] = hl;
            mark(donP2);
        }
        gate(donP2, B_);

        // ----- P3: mod GEMM (K=256 whole) + next-step rec-hh -----
        {
            const int parN = (t + 1) & 1;
            for (;;) {
                int k = grab(tixP3, P3_TILES, &s_tile);
                if (k < 0) break;
                if (k < P3_MODT) {
                    int n0 = k * 64;
                    ttile(sAh, sAl, sBh, sBl,
                          g_sthi + H_, g_stlo + H_, RECK,
                          g_Mthi + (size_t)n0 * HHYP, g_Mtlo + (size_t)n0 * HHYP, HHYP,
                          g_modS + n0, MODN, 8);
                } else {
                    int n0 = (k - P3_MODT) * 64;
                    ttile(sAh, sAl, sBh, sBl,
                          g_sthi + H_, g_stlo + H_, RECK,
                          g_WHhi + (size_t)n0 * HHYP, g_WHlo + (size_t)n0 * HHYP, HHYP,
                          g_recHH + (size_t)parN * (B_ * HH4) + n0, HH4, 8);
                }
                mark(donP3);
            }
        }
        gate(donP3, P3_TILES);
        gate(donP1, P1_TILES);   // P4 needs the main-row slabs too

        // ----- P4: main cell -----
        for (;;) {
            int b = grab(tixP4, B_, &s_tile);
            if (b < 0) break;
            const int j = tid;
            const float* xw = g_XW + ((size_t)t * B_ + b) * H4;
            const float* mp = g_modS + (size_t)b * MODN;
            float pre[4][4];
#pragma unroll
            for (int gk = 0; gk < 4; gk++) {
#pragma unroll
                for (int q = 0; q < 4; q++) {
                    int n = gk * H_ + q * 256 + j;
                    float hg = __ldcg(&g_recP1[(size_t)b * H4 + n])
                             + __ldcg(&g_recP1[(size_t)(B_ * H4) + (size_t)b * H4 + n]);
                    float sx = __ldcg(&mp[n]) + g_csc[n];
                    float sh = __ldcg(&mp[4 * H_ + n]) + g_csc[4 * H_ + n];
                    float ba = __ldcg(&mp[8 * H_ + n]);
                    pre[gk][q] = fmaf(sx, xw[n], fmaf(sh, hg, bias[n] + ba));
                }
            }
            float nv[4][4];
#pragma unroll
            for (int gk = 0; gk < 4; gk++) {
                float p = pre[gk][0] + pre[gk][1] + pre[gk][2] + pre[gk][3];
                float m = block_sum256(p, sred) * (1.f / 1024.f);
                float vs = 0.f;
#pragma unroll
                for (int q = 0; q < 4; q++) { float d = pre[gk][q] - m; vs += d * d; }
                float var = block_sum256(vs, sred) * (1.f / 1024.f);
                float rs = rsqrtf(var + EPSLN);
#pragma unroll
                for (int q = 0; q < 4; q++) {
                    int n = gk * H_ + q * 256 + j;
                    nv[gk][q] = lnag[n] * ((pre[gk][q] - m) * rs) + lnab[n];
                }
            }
            float cn[4];
            float psum = 0.f;
#pragma unroll
            for (int q = 0; q < 4; q++) {
                int idx = q * 256 + j;
                float c = __ldcg(&g_c[b * H_ + idx]);
                cn[q] = sigf(nv[2][q]) * c + sigf(nv[0][q]) * tanhf(nv[1][q]);
                g_c[b * H_ + idx] = cn[q];
                psum += cn[q];
            }
            float m = block_sum256(psum, sred) * (1.f / 1024.f);
            float vs = 0.f;
#pragma unroll
            for (int q = 0; q < 4; q++) { float d = cn[q] - m; vs += d * d; }
            float var = block_sum256(vs, sred) * (1.f / 1024.f);
            float rs = rsqrtf(var + EPSLN);
#pragma unroll
            for (int q = 0; q < 4; q++) {
                int idx = q * 256 + j;
                float lc = lng[idx] * ((cn[q] - m) * rs) + lnb[idx];
                float h = sigf(nv[3][q]) * tanhf(lc);
                size_t sidx = (size_t)b * RECK + idx;
                g_state[sidx] = h;
                __nv_bfloat16 hh, hl; split_bf16(h, hh, hl);
                g_sthi[sidx] = hh; g_stlo[sidx] = hl;
            }
            mark(donP4);
        }
    }

    // ----- final FC: out = h @ fcW^T + fcb -----
    gate(&g_done[(T_ - 1) * NPH + 3], B_);
    for (;;) {
        int b = grab(&g_tix[T_ * NPH], B_, &s_tile);
        if (b < 0) break;
        float* sh = (float*)&sAh[0][0];   // 1024 floats fit in 10240-byte buffer
        float* sp = (float*)&sBh[0][0];   // 256 floats fit in 5120-byte buffer
        for (int i = tid; i < H_; i += NT_) sh[i] = __ldcg(&g_state[(size_t)b * RECK + i]);
        __syncthreads();
        int o = tid & 127, half = tid >> 7;
        const float* w = fcW + (size_t)o * H_ + half * 512;
        const float* hv = sh + half * 512;
        float s = 0.f;
        for (int k = 0; k < 512; k++) s = fmaf(hv[k], w[k], s);
        sp[tid] = s;
        __syncthreads();
        if (tid < NOUT)
            out[(size_t)b * NOUT + tid] = sp[tid] + sp[128 + tid] + fcb[tid];
        __syncthreads();
    }
}

// ---------------------------------------------------------------------------
// Launch: exactly 6 launches so ncu (-s 5 -c 1) profiles the persistent kernel
// ---------------------------------------------------------------------------
extern "C" void kernel_launch(void* const* d_in, const int* in_sizes, int n_in,
                              void* d_out, int out_size)
{
    const float* x      = (const float*)d_in[0];
    const float* Wx     = (const float*)d_in[1];
    const float* Wh     = (const float*)d_in[2];
    const float* bias   = (const float*)d_in[3];
    const float* lnag   = (const float*)d_in[4];
    const float* lnab   = (const float*)d_in[5];
    const float* lng    = (const float*)d_in[6];
    const float* lnb    = (const float*)d_in[7];
    const float* zb     = (const float*)d_in[8];
    const float* zbeta  = (const float*)d_in[9];
    const float* zw_w   = (const float*)d_in[10];
    const float* zw_b   = (const float*)d_in[11];
    const float* alpha  = (const float*)d_in[12];
    const float* hypWx  = (const float*)d_in[13];
    const float* hypbx  = (const float*)d_in[14];
    const float* hypWh  = (const float*)d_in[15];
    const float* hypbh  = (const float*)d_in[16];
    const float* hlnag  = (const float*)d_in[17];
    const float* hlnab  = (const float*)d_in[18];
    const float* hlng   = (const float*)d_in[19];
    const float* hlnb   = (const float*)d_in[20];
    const float* fc_W   = (const float*)d_in[21];
    const float* fc_b   = (const float*)d_in[22];
    float* out = (float*)d_out;

    // #1 init
    init_k<<<(2 * B_ * HH4 + 255) / 256, 256>>>();
    // #2 all conversions + csc (largest range: T*B*D)
    setupAll_k<<<(int)(((size_t)T_ * B_ * D_ + 255) / 256), 256>>>(
        x, Wx, Wh, hypWx, hypWh, zw_b, alpha);
    // #3 Mcat (12 GEMMs fused via blockIdx.z)
    gemmAll_k<<<dim3(16, 2, 12), 256>>>(zw_w, zb, alpha, zbeta);
    // #4 [XW | hypX] = x @ W0^T on tensor cores
    xw_tensor_k<<<dim3(NREC / 64, (T_ * B_) / 128), NT_>>>();
    // #5 Mcat transpose to bf16 planes
    convMt_k<<<(int)(((size_t)MODN * HHYP + 255) / 256), 256>>>();
    // #6 persistent recurrence + final FC
    hyperlstm_persist<<<G_, NT_>>>(
        hypbx, hypbh, hlnag, hlnab, hlng, hlnb,
        bias, lnag, lnab, lng, lnb, fc_W, fc_b, out);
}

// round 16
// speedup vs baseline: 2.5188x; 1.0352x over previous
#include <cuda_runtime.h>
#include <cuda_bf16.h>
#include <math.h>
#include <stdint.h>

// ---------------------------------------------------------------------------
// Problem constants
// ---------------------------------------------------------------------------
#define T_ 512
#define B_ 128
#define D_ 256
#define H_ 1024      // main hidden
#define HHYP 256     // hyper hidden
#define H4 4096      // 4*H
#define HH4 1024     // 4*HHYP
#define NOUT 128
#define MODN 12288   // 8*H (sc) + 4*H (badj)
#define NREC 5120    // 4096 main rows + 1024 hyper rows
#define RECK 1280    // state length = H + HHYP
#define EPSLN 1e-3f

#define G_ 296       // launched CTAs; design does NOT require co-residency
#define NT_ 256

// phase tiling (BM=128, BN=64; K processed in 32-wide chunks)
#define P1_HYPT 128            // 16 n-tiles * 8 k-splits (K=1024, 128/ticket)
#define P1_MAINT 128           // 64 n-tiles * 2 k-splits (K=1024, 512/ticket)
#define P1_TILES (P1_HYPT + P1_MAINT)
#define HYPS 8                 // hyper slabs
#define MAINS 2                // main slabs
#define P3_MODT 192            // 192 n-tiles, K=256 whole  (1 slab)
#define P3_RHHT 16             // 16 n-tiles, K=256 whole
#define P3_TILES (P3_MODT + P3_RHHT)
#define NPH 4

#define KP 40   // smem row pitch (bf16 elems); rows stride 20 banks -> LDSM conflict-free

// ---------------------------------------------------------------------------
// Device scratch
// ---------------------------------------------------------------------------
__device__ alignas(16) float g_XW[(size_t)T_ * B_ * H4];     // 1 GiB
__device__ alignas(16) float g_hypX[(size_t)T_ * B_ * HH4];  // 256 MiB
__device__ alignas(16) float g_Mcat[(size_t)HHYP * MODN];
__device__ alignas(16) float g_csc[8 * H_];
__device__ alignas(16) float g_state[B_ * RECK];             // fp32 [h | hyp]
__device__ alignas(16) float g_c[B_ * H_];
__device__ alignas(16) float g_ch[B_ * HHYP];
__device__ alignas(16) float g_recP1[(size_t)MAINS * B_ * H4];  // main slabs
__device__ alignas(16) float g_recHyp[(size_t)HYPS * B_ * HH4]; // hyper slabs
__device__ alignas(16) float g_modS[(size_t)B_ * MODN];      // single slab
__device__ alignas(16) float g_recHH[2 * B_ * HH4];          // parity double buffer

// bf16 hi/lo planes
__device__ alignas(16) __nv_bfloat16 g_sthi[B_ * RECK];
__device__ alignas(16) __nv_bfloat16 g_stlo[B_ * RECK];
__device__ alignas(16) __nv_bfloat16 g_W1hi[(size_t)NREC * H_];   // [n][k] packed Wh | hypWx_h
__device__ alignas(16) __nv_bfloat16 g_W1lo[(size_t)NREC * H_];
__device__ alignas(16) __nv_bfloat16 g_WHhi[(size_t)HH4 * HHYP];  // hypWh [n][k]
__device__ alignas(16) __nv_bfloat16 g_WHlo[(size_t)HH4 * HHYP];
__device__ alignas(16) __nv_bfloat16 g_Mthi[(size_t)MODN * HHYP]; // Mcat^T [n][k]
__device__ alignas(16) __nv_bfloat16 g_Mtlo[(size_t)MODN * HHYP];
__device__ alignas(16) __nv_bfloat16 g_xhi[(size_t)T_ * B_ * D_]; // x planes
__device__ alignas(16) __nv_bfloat16 g_xlo[(size_t)T_ * B_ * D_];
__device__ alignas(16) __nv_bfloat16 g_W0hi[(size_t)NREC * D_];   // [n][k] packed Wx | hypWx_x
__device__ alignas(16) __nv_bfloat16 g_W0lo[(size_t)NREC * D_];

// dataflow state
__device__ unsigned g_tix[T_ * NPH + 1];
__device__ unsigned g_done[T_ * NPH + 1];
__device__ unsigned g_doneH[T_];      // P1 hyper-tile completion (gates P2 early)

// ---------------------------------------------------------------------------
// Setup: split helper
// ---------------------------------------------------------------------------
__device__ __forceinline__ void split_bf16(float x, __nv_bfloat16& h, __nv_bfloat16& l)
{
    h = __float2bfloat16(x);
    l = __float2bfloat16(x - __bfloat162float(h));
}

// launch #1: zero state + counters
__global__ void init_k()
{
    size_t i = (size_t)blockIdx.x * 256 + threadIdx.x;
    if (i < (size_t)B_ * RECK) {
        g_state[i] = 0.f;
        g_sthi[i] = __float2bfloat16(0.f);
        g_stlo[i] = __float2bfloat16(0.f);
    }
    if (i < (size_t)B_ * H_)   g_c[i] = 0.f;
    if (i < (size_t)B_ * HHYP) g_ch[i] = 0.f;
    if (i < (size_t)2 * B_ * HH4) g_recHH[i] = 0.f;
    if (i < (size_t)(T_ * NPH + 1)) { g_tix[i] = 0u; g_done[i] = 0u; }
    if (i < (size_t)T_) g_doneH[i] = 0u;
}

// launch #2: all input conversions + csc, fused (all independent)
__global__ void setupAll_k(const float* __restrict__ x,
                           const float* __restrict__ Wx,
                           const float* __restrict__ Wh,
                           const float* __restrict__ hypWx,
                           const float* __restrict__ hypWh,
                           const float* __restrict__ zw_b,
                           const float* __restrict__ alpha)
{
    size_t i = (size_t)blockIdx.x * 256 + threadIdx.x;
    if (i < (size_t)T_ * B_ * D_)
        split_bf16(x[i], g_xhi[i], g_xlo[i]);
    if (i < (size_t)NREC * H_) {
        int n = (int)(i / H_), k = (int)(i % H_);
        float v = (n < H4) ? Wh[(size_t)n * H_ + k]
                           : hypWx[(size_t)(n - H4) * (D_ + H_) + D_ + k];
        split_bf16(v, g_W1hi[i], g_W1lo[i]);
    }
    if (i < (size_t)NREC * D_) {
        int n = (int)(i / D_), k = (int)(i % D_);
        float v = (n < H4) ? Wx[(size_t)n * D_ + k]
                           : hypWx[(size_t)(n - H4) * (D_ + H_) + k];
        split_bf16(v, g_W0hi[i], g_W0lo[i]);
    }
    if (i < (size_t)HH4 * HHYP)
        split_bf16(hypWh[i], g_WHhi[i], g_WHlo[i]);
    if (i < (size_t)(8 * H_)) {
        int k = (int)(i / H_), h = (int)(i % H_);
        float s = 0.f;
        const float* zb = zw_b + (size_t)k * HHYP;
        const float* al = alpha + (size_t)k * HHYP * H_;
        for (int p = 0; p < HHYP; p++) s = fmaf(zb[p], al[(size_t)p * H_ + h], s);
        g_csc[i] = s;
    }
}

// launch #3: Mcat = 12 fused GEMMs (256 x 1024 x 256) NN, z = which GEMM
__global__ __launch_bounds__(256) void gemmAll_k(
    const float* __restrict__ zw_w, const float* __restrict__ zb,
    const float* __restrict__ alpha, const float* __restrict__ zbeta)
{
    const int s = blockIdx.z;
    const float* A = (s < 8) ? zw_w + (size_t)s * HHYP * HHYP
                             : zb + (size_t)(s - 8) * HHYP * HHYP;
    const float* Bm = (s < 8) ? alpha + (size_t)s * HHYP * H_
                              : zbeta + (size_t)(s - 8) * HHYP * H_;
    float* C = g_Mcat + s * H_;
    const int lda = HHYP, ldb = H_, ldc = MODN;

    const int n0 = blockIdx.x * 64;
    const int m0 = blockIdx.y * 128;
    A += (size_t)m0 * lda;
    Bm += n0;
    C += (size_t)m0 * ldc + n0;

    __shared__ float As[16][132];
    __shared__ float Bs[16][68];
    const int tid = threadIdx.x;
    const int tx = tid % 16;
    const int ty = tid / 16;

    float acc[8][4];
#pragma unroll
    for (int i = 0; i < 8; i++)
#pragma unroll
        for (int j = 0; j < 4; j++) acc[i][j] = 0.f;

    for (int kt = 0; kt < HHYP; kt += 16) {
#pragma unroll
        for (int l = 0; l < 2; l++) {
            int idx = tid + l * 256;
            int r = idx / 4;
            int c4 = idx % 4;
            float4 v = *(const float4*)(A + (size_t)r * lda + c4 * 4);
            As[c4 * 4 + 0][r] = v.x; As[c4 * 4 + 1][r] = v.y;
            As[c4 * 4 + 2][r] = v.z; As[c4 * 4 + 3][r] = v.w;
        }
        {
            int r = tid / 16;
            int c4 = tid % 16;
            float4 v = *(const float4*)(Bm + (size_t)r * ldb + c4 * 4);
            *(float4*)&Bs[r][c4 * 4] = v;
        }
        __syncthreads();
#pragma unroll
        for (int k = 0; k < 16; k++) {
            float a[8], bv[4];
#pragma unroll
            for (int i = 0; i < 8; i += 4) {
                float4 v = *(const float4*)&As[k][ty * 8 + i];
                a[i] = v.x; a[i + 1] = v.y; a[i + 2] = v.z; a[i + 3] = v.w;
            }
            float4 vb = *(const float4*)&Bs[k][tx * 4];
            bv[0] = vb.x; bv[1] = vb.y; bv[2] = vb.z; bv[3] = vb.w;
#pragma unroll
            for (int i = 0; i < 8; i++)
#pragma unroll
                for (int j = 0; j < 4; j++)
                    acc[i][j] = fmaf(a[i], bv[j], acc[i][j]);
        }
        __syncthreads();
        A += 16;
        Bm += (size_t)16 * ldb;
    }
#pragma unroll
    for (int i = 0; i < 8; i++) {
        float4 o; o.x = acc[i][0]; o.y = acc[i][1]; o.z = acc[i][2]; o.w = acc[i][3];
        *(float4*)(C + (size_t)(ty * 8 + i) * ldc + tx * 4) = o;
    }
}

// launch #5: transpose Mcat -> [n][k] hi/lo planes
__global__ void convMt_k()
{
    size_t idx = (size_t)blockIdx.x * 256 + threadIdx.x;
    if (idx >= (size_t)MODN * HHYP) return;
    int n = (int)(idx / HHYP), k = (int)(idx % HHYP);
    split_bf16(g_Mcat[(size_t)k * MODN + n], g_Mthi[idx], g_Mtlo[idx]);
}

// ---------------------------------------------------------------------------
// Shared helpers
// ---------------------------------------------------------------------------
__device__ __forceinline__ float sigf(float x) { return 1.f / (1.f + expf(-x)); }

__device__ __forceinline__ float block_sum256(float v, float* sbuf)
{
    const int tid = threadIdx.x;
#pragma unroll
    for (int o = 16; o > 0; o >>= 1) v += __shfl_xor_sync(0xffffffffu, v, o);
    const int warp = tid >> 5, lane = tid & 31;
    if (lane == 0) sbuf[warp] = v;
    __syncthreads();
    float s = (tid < 8) ? sbuf[tid] : 0.f;
    if (warp == 0) {
#pragma unroll
        for (int o = 4; o > 0; o >>= 1) s += __shfl_xor_sync(0xffffffffu, s, o);
        if (lane == 0) sbuf[0] = s;
    }
    __syncthreads();
    float r = sbuf[0];
    __syncthreads();
    return r;
}

__device__ __forceinline__ int grab(unsigned* ctr, unsigned limit, unsigned* s_tile)
{
    __syncthreads();
    if (threadIdx.x == 0) *s_tile = atomicAdd(ctr, 1u);
    __syncthreads();
    unsigned k = *s_tile;
    return (k < limit) ? (int)k : -1;
}

__device__ __forceinline__ void mark(unsigned* cnt)
{
    __threadfence();
    __syncthreads();
    if (threadIdx.x == 0) atomicAdd(cnt, 1u);
}

__device__ __forceinline__ void gate(const unsigned* cnt, unsigned target)
{
    if (threadIdx.x == 0) {
        while (*(volatile const unsigned*)cnt < target) __nanosleep(64);
        __threadfence();
    }
    __syncthreads();
}

__device__ __forceinline__ void mma16816(float* d, const uint32_t* a, const uint32_t* b)
{
    asm volatile(
        "mma.sync.aligned.m16n8k16.row.col.f32.bf16.bf16.f32 "
        "{%0,%1,%2,%3}, {%4,%5,%6,%7}, {%8,%9}, {%0,%1,%2,%3};\n"
        : "+f"(d[0]), "+f"(d[1]), "+f"(d[2]), "+f"(d[3])
        : "r"(a[0]), "r"(a[1]), "r"(a[2]), "r"(a[3]), "r"(b[0]), "r"(b[1]));
}

__device__ __forceinline__ void ldsm_x4(uint32_t* r, uint32_t addr)
{
    asm volatile("ldmatrix.sync.aligned.m8n8.x4.shared.b16 {%0,%1,%2,%3}, [%4];"
                 : "=r"(r[0]), "=r"(r[1]), "=r"(r[2]), "=r"(r[3]) : "r"(addr));
}

__device__ __forceinline__ void ldsm_x2(uint32_t* r, uint32_t addr)
{
    asm volatile("ldmatrix.sync.aligned.m8n8.x2.shared.b16 {%0,%1}, [%2];"
                 : "=r"(r[0]), "=r"(r[1]) : "r"(addr));
}

// ---------------------------------------------------------------------------
// Tensor GEMM tile: C[128,64] = A[128,K] * B[64,K]^T, bf16 hi/lo x3 MMA.
// Fragments loaded via ldmatrix (LDSM) — 5x fewer shared-mem instructions
// than scalar gathers. K = nchunk*32; register-prefetch pipelined gmem->smem.
// ---------------------------------------------------------------------------
__device__ void ttile(
    __nv_bfloat16 (*sAh)[KP], __nv_bfloat16 (*sAl)[KP],
    __nv_bfloat16 (*sBh)[KP], __nv_bfloat16 (*sBl)[KP],
    const __nv_bfloat16* gAh, const __nv_bfloat16* gAl, int lda,
    const __nv_bfloat16* gBh, const __nv_bfloat16* gBl, int ldbk,
    float* C, int ldc, int nchunk)
{
    const int tid = threadIdx.x;
    const int lane = tid & 31, w = tid >> 5;
    const int wm = w & 3, wn = w >> 2;          // 4 warps M x 2 warps N
    const int g = lane >> 2, tig = lane & 3;

    const int ar = tid >> 2;            // A rows ar and ar+64 (gmem staging)
    const int ac = (tid & 3) * 8;       // col within 32-wide chunk
    const __nv_bfloat16* pAh0 = gAh + (size_t)ar * lda + ac;
    const __nv_bfloat16* pAh1 = gAh + (size_t)(ar + 64) * lda + ac;
    const __nv_bfloat16* pAl0 = gAl + (size_t)ar * lda + ac;
    const __nv_bfloat16* pAl1 = gAl + (size_t)(ar + 64) * lda + ac;
    const __nv_bfloat16* pBh  = gBh + (size_t)ar * ldbk + ac;   // B rows 0..63
    const __nv_bfloat16* pBl  = gBl + (size_t)ar * ldbk + ac;

    // ldmatrix per-thread address components (byte offsets into smem)
    // A x4: row = wm*32 + ms*16 + (lane&15), col = kk*16 + (lane>>4)*8
    // B x2: row = wn*32 + ns*8 + (lane&7),  col = kk*16 + ((lane>>3)&1)*8
    const uint32_t aAddrH = (uint32_t)__cvta_generic_to_shared(&sAh[0][0])
                          + ((wm * 32 + (lane & 15)) * KP + (lane >> 4) * 8) * 2;
    const uint32_t aAddrL = (uint32_t)__cvta_generic_to_shared(&sAl[0][0])
                          + ((wm * 32 + (lane & 15)) * KP + (lane >> 4) * 8) * 2;
    const uint32_t bAddrH = (uint32_t)__cvta_generic_to_shared(&sBh[0][0])
                          + ((wn * 32 + (lane & 7)) * KP + ((lane >> 3) & 1) * 8) * 2;
    const uint32_t bAddrL = (uint32_t)__cvta_generic_to_shared(&sBl[0][0])
                          + ((wn * 32 + (lane & 7)) * KP + ((lane >> 3) & 1) * 8) * 2;

    float acc[2][4][4];
#pragma unroll
    for (int ms = 0; ms < 2; ms++)
#pragma unroll
        for (int ns = 0; ns < 4; ns++)
#pragma unroll
            for (int q = 0; q < 4; q++) acc[ms][ns][q] = 0.f;

    uint4 ra_h0 = __ldcg((const uint4*)pAh0);
    uint4 ra_h1 = __ldcg((const uint4*)pAh1);
    uint4 ra_l0 = __ldcg((const uint4*)pAl0);
    uint4 ra_l1 = __ldcg((const uint4*)pAl1);
    uint4 rb_h  = *(const uint4*)pBh;
    uint4 rb_l  = *(const uint4*)pBl;

    for (int ch = 0; ch < nchunk; ch++) {
        *(uint4*)&sAh[ar][ac]      = ra_h0;
        *(uint4*)&sAh[ar + 64][ac] = ra_h1;
        *(uint4*)&sAl[ar][ac]      = ra_l0;
        *(uint4*)&sAl[ar + 64][ac] = ra_l1;
        *(uint4*)&sBh[ar][ac]      = rb_h;
        *(uint4*)&sBl[ar][ac]      = rb_l;
        __syncthreads();

        if (ch + 1 < nchunk) {
            int kb = (ch + 1) * 32;
            ra_h0 = __ldcg((const uint4*)(pAh0 + kb));
            ra_h1 = __ldcg((const uint4*)(pAh1 + kb));
            ra_l0 = __ldcg((const uint4*)(pAl0 + kb));
            ra_l1 = __ldcg((const uint4*)(pAl1 + kb));
            rb_h  = *(const uint4*)(pBh + kb);
            rb_l  = *(const uint4*)(pBl + kb);
        }

#pragma unroll
        for (int kk = 0; kk < 2; kk++) {
            const uint32_t kOff = kk * 16 * 2;   // 16 bf16 = 32 bytes
            uint32_t ah[2][4], al[2][4];
#pragma unroll
            for (int ms = 0; ms < 2; ms++) {
                const uint32_t rOff = ms * 16 * KP * 2;
                ldsm_x4(ah[ms], aAddrH + rOff + kOff);
                ldsm_x4(al[ms], aAddrL + rOff + kOff);
            }
#pragma unroll
            for (int ns = 0; ns < 4; ns++) {
                const uint32_t rOff = ns * 8 * KP * 2;
                uint32_t bh[2], blo[2];
                ldsm_x2(bh, bAddrH + rOff + kOff);
                ldsm_x2(blo, bAddrL + rOff + kOff);
#pragma unroll
                for (int ms = 0; ms < 2; ms++) {
                    mma16816(acc[ms][ns], ah[ms], bh);
                    mma16816(acc[ms][ns], ah[ms], blo);
                    mma16816(acc[ms][ns], al[ms], bh);
                }
            }
        }
        __syncthreads();
    }

#pragma unroll
    for (int ms = 0; ms < 2; ms++) {
#pragma unroll
        for (int ns = 0; ns < 4; ns++) {
            int row0 = wm * 32 + ms * 16 + g;
            int col = wn * 32 + ns * 8 + tig * 2;
            float2 v0; v0.x = acc[ms][ns][0]; v0.y = acc[ms][ns][1];
            float2 v1; v1.x = acc[ms][ns][2]; v1.y = acc[ms][ns][3];
            *(float2*)&C[(size_t)row0 * ldc + col] = v0;
            *(float2*)&C[(size_t)(row0 + 8) * ldc + col] = v1;
        }
    }
}

// launch #4: [XW | hypX] = x @ W0^T  (M=65536, N=5120, K=256)
__global__ __launch_bounds__(NT_) void xw_tensor_k()
{
    __shared__ __align__(16) __nv_bfloat16 sAh[128][KP];
    __shared__ __align__(16) __nv_bfloat16 sAl[128][KP];
    __shared__ __align__(16) __nv_bfloat16 sBh[64][KP];
    __shared__ __align__(16) __nv_bfloat16 sBl[64][KP];

    const int n0 = blockIdx.x * 64;
    const size_t m0 = (size_t)blockIdx.y * 128;
    float* C;
    int ldc;
    if (n0 < H4) { C = g_XW + m0 * H4 + n0; ldc = H4; }
    else         { C = g_hypX + m0 * HH4 + (n0 - H4); ldc = HH4; }
    ttile(sAh, sAl, sBh, sBl,
          g_xhi + m0 * D_, g_xlo + m0 * D_, D_,
          g_W0hi + (size_t)n0 * D_, g_W0lo + (size_t)n0 * D_, D_,
          C, ldc, 8);
}

// ---------------------------------------------------------------------------
// launch #6: persistent kernel — whole T=512 recurrence + final FC.
// ---------------------------------------------------------------------------
__global__ __launch_bounds__(NT_, 2) void hyperlstm_persist(
    const float* __restrict__ hypbx, const float* __restrict__ hypbh,
    const float* __restrict__ hlnag, const float* __restrict__ hlnab,
    const float* __restrict__ hlng, const float* __restrict__ hlnb,
    const float* __restrict__ bias,
    const float* __restrict__ lnag, const float* __restrict__ lnab,
    const float* __restrict__ lng, const float* __restrict__ lnb,
    const float* __restrict__ fcW, const float* __restrict__ fcb,
    float* __restrict__ out)
{
    __shared__ __align__(16) __nv_bfloat16 sAh[128][KP];
    __shared__ __align__(16) __nv_bfloat16 sAl[128][KP];
    __shared__ __align__(16) __nv_bfloat16 sBh[64][KP];
    __shared__ __align__(16) __nv_bfloat16 sBl[64][KP];
    __shared__ float sred[32];
    __shared__ unsigned s_tile;

    const int tid = threadIdx.x;

    for (int t = 0; t < T_; t++) {
        unsigned* tixP1 = &g_tix[t * NPH + 0];
        unsigned* tixP2 = &g_tix[t * NPH + 1];
        unsigned* tixP3 = &g_tix[t * NPH + 2];
        unsigned* tixP4 = &g_tix[t * NPH + 3];
        unsigned* donP1 = &g_done[t * NPH + 0];
        unsigned* donP2 = &g_done[t * NPH + 1];
        unsigned* donP3 = &g_done[t * NPH + 2];
        unsigned* donP4 = &g_done[t * NPH + 3];

        // ----- P1: rec GEMM from h (hyper tiles first, K=128 each) -----
        if (t > 0) gate(&g_done[(t - 1) * NPH + 3], B_);
        for (;;) {
            int k = grab(tixP1, P1_TILES, &s_tile);
            if (k < 0) break;
            bool hyp_tile = (k < P1_HYPT);
            if (hyp_tile) {
                int nt = k >> 3, ks = k & 7;
                int n0 = nt * 64, kb = ks * 128;
                ttile(sAh, sAl, sBh, sBl,
                      g_sthi + kb, g_stlo + kb, RECK,
                      g_W1hi + (size_t)(H4 + n0) * H_ + kb,
                      g_W1lo + (size_t)(H4 + n0) * H_ + kb, H_,
                      g_recHyp + (size_t)ks * (B_ * HH4) + n0, HH4, 4);
            } else {
                int k2 = k - P1_HYPT;
                int nt = k2 >> 1, ks = k2 & 1;
                int n0 = nt * 64, kb = ks * 512;
                ttile(sAh, sAl, sBh, sBl,
                      g_sthi + kb, g_stlo + kb, RECK,
                      g_W1hi + (size_t)n0 * H_ + kb,
                      g_W1lo + (size_t)n0 * H_ + kb, H_,
                      g_recP1 + (size_t)ks * (B_ * H4) + n0, H4, 16);
            }
            __threadfence();
            __syncthreads();
            if (tid == 0) {
                atomicAdd(donP1, 1u);
                if (hyp_tile) atomicAdd(&g_doneH[t], 1u);
            }
        }

        // ----- P2: hyper cell (gates only on the 128 hyper tiles) -----
        gate(&g_doneH[t], P1_HYPT);
        for (;;) {
            int b = grab(tixP2, B_, &s_tile);
            if (b < 0) break;
            const int j = tid;
            const int par = t & 1;
            const float* hx = g_hypX + ((size_t)t * B_ + b) * HH4;
            float v[4];
#pragma unroll
            for (int gk = 0; gk < 4; gk++) {
                int n = gk * HHYP + j;
                float s = hx[n] + hypbx[n] + hypbh[n];
#pragma unroll
                for (int sl = 0; sl < HYPS; sl++)
                    s += __ldcg(&g_recHyp[(size_t)sl * (B_ * HH4) + (size_t)b * HH4 + n]);
                s += __ldcg(&g_recHH[(size_t)par * (B_ * HH4) + (size_t)b * HH4 + n]);
                v[gk] = s;
            }
            float nv[4];
#pragma unroll
            for (int gk = 0; gk < 4; gk++) {
                float m = block_sum256(v[gk], sred) * (1.f / 256.f);
                float xs = v[gk] - m;
                float var = block_sum256(xs * xs, sred) * (1.f / 256.f);
                int n = gk * HHYP + j;
                nv[gk] = hlnag[n] * (xs * rsqrtf(var + EPSLN)) + hlnab[n];
            }
            float ch = __ldcg(&g_ch[b * HHYP + j]);
            float chn = sigf(nv[1]) * ch + sigf(nv[0]) * tanhf(nv[2]);
            float m = block_sum256(chn, sred) * (1.f / 256.f);
            float xs = chn - m;
            float var = block_sum256(xs * xs, sred) * (1.f / 256.f);
            float hn = hlng[j] * (xs * rsqrtf(var + EPSLN)) + hlnb[j];
            float hyp = sigf(nv[3]) * tanhf(hn);
            g_ch[b * HHYP + j] = chn;
            size_t sidx = (size_t)b * RECK + H_ + j;
            g_state[sidx] = hyp;
            __nv_bfloat16 hh, hl; split_bf16(hyp, hh, hl);
            g_sthi[sidx] = hh; g_stlo[sidx] = hl;
            mark(donP2);
        }
        gate(donP2, B_);

        // ----- P3: mod GEMM (K=256 whole) + next-step rec-hh -----
        {
            const int parN = (t + 1) & 1;
            for (;;) {
                int k = grab(tixP3, P3_TILES, &s_tile);
                if (k < 0) break;
                if (k < P3_MODT) {
                    int n0 = k * 64;
                    ttile(sAh, sAl, sBh, sBl,
                          g_sthi + H_, g_stlo + H_, RECK,
                          g_Mthi + (size_t)n0 * HHYP, g_Mtlo + (size_t)n0 * HHYP, HHYP,
                          g_modS + n0, MODN, 8);
                } else {
                    int n0 = (k - P3_MODT) * 64;
                    ttile(sAh, sAl, sBh, sBl,
                          g_sthi + H_, g_stlo + H_, RECK,
                          g_WHhi + (size_t)n0 * HHYP, g_WHlo + (size_t)n0 * HHYP, HHYP,
                          g_recHH + (size_t)parN * (B_ * HH4) + n0, HH4, 8);
                }
                mark(donP3);
            }
        }
        gate(donP3, P3_TILES);
        gate(donP1, P1_TILES);   // P4 needs the main-row slabs too

        // ----- P4: main cell -----
        for (;;) {
            int b = grab(tixP4, B_, &s_tile);
            if (b < 0) break;
            const int j = tid;
            const float* xw = g_XW + ((size_t)t * B_ + b) * H4;
            const float* mp = g_modS + (size_t)b * MODN;
            float pre[4][4];
#pragma unroll
            for (int gk = 0; gk < 4; gk++) {
#pragma unroll
                for (int q = 0; q < 4; q++) {
                    int n = gk * H_ + q * 256 + j;
                    float hg = __ldcg(&g_recP1[(size_t)b * H4 + n])
                             + __ldcg(&g_recP1[(size_t)(B_ * H4) + (size_t)b * H4 + n]);
                    float sx = __ldcg(&mp[n]) + g_csc[n];
                    float sh = __ldcg(&mp[4 * H_ + n]) + g_csc[4 * H_ + n];
                    float ba = __ldcg(&mp[8 * H_ + n]);
                    pre[gk][q] = fmaf(sx, xw[n], fmaf(sh, hg, bias[n] + ba));
                }
            }
            float nv[4][4];
#pragma unroll
            for (int gk = 0; gk < 4; gk++) {
                float p = pre[gk][0] + pre[gk][1] + pre[gk][2] + pre[gk][3];
                float m = block_sum256(p, sred) * (1.f / 1024.f);
                float vs = 0.f;
#pragma unroll
                for (int q = 0; q < 4; q++) { float d = pre[gk][q] - m; vs += d * d; }
                float var = block_sum256(vs, sred) * (1.f / 1024.f);
                float rs = rsqrtf(var + EPSLN);
#pragma unroll
                for (int q = 0; q < 4; q++) {
                    int n = gk * H_ + q * 256 + j;
                    nv[gk][q] = lnag[n] * ((pre[gk][q] - m) * rs) + lnab[n];
                }
            }
            float cn[4];
            float psum = 0.f;
#pragma unroll
            for (int q = 0; q < 4; q++) {
                int idx = q * 256 + j;
                float c = __ldcg(&g_c[b * H_ + idx]);
                cn[q] = sigf(nv[2][q]) * c + sigf(nv[0][q]) * tanhf(nv[1][q]);
                g_c[b * H_ + idx] = cn[q];
                psum += cn[q];
            }
            float m = block_sum256(psum, sred) * (1.f / 1024.f);
            float vs = 0.f;
#pragma unroll
            for (int q = 0; q < 4; q++) { float d = cn[q] - m; vs += d * d; }
            float var = block_sum256(vs, sred) * (1.f / 1024.f);
            float rs = rsqrtf(var + EPSLN);
#pragma unroll
            for (int q = 0; q < 4; q++) {
                int idx = q * 256 + j;
                float lc = lng[idx] * ((cn[q] - m) * rs) + lnb[idx];
                float h = sigf(nv[3][q]) * tanhf(lc);
                size_t sidx = (size_t)b * RECK + idx;
                g_state[sidx] = h;
                __nv_bfloat16 hh, hl; split_bf16(h, hh, hl);
                g_sthi[sidx] = hh; g_stlo[sidx] = hl;
            }
            mark(donP4);
        }
    }

    // ----- final FC: out = h @ fcW^T + fcb -----
    gate(&g_done[(T_ - 1) * NPH + 3], B_);
    for (;;) {
        int b = grab(&g_tix[T_ * NPH], B_, &s_tile);
        if (b < 0) break;
        float* sh = (float*)&sAh[0][0];   // 1024 floats fit in 10240-byte buffer
        float* sp = (float*)&sBh[0][0];   // 256 floats fit in 5120-byte buffer
        for (int i = tid; i < H_; i += NT_) sh[i] = __ldcg(&g_state[(size_t)b * RECK + i]);
        __syncthreads();
        int o = tid & 127, half = tid >> 7;
        const float* w = fcW + (size_t)o * H_ + half * 512;
        const float* hv = sh + half * 512;
        float s = 0.f;
        for (int k = 0; k < 512; k++) s = fmaf(hv[k], w[k], s);
        sp[tid] = s;
        __syncthreads();
        if (tid < NOUT)
            out[(size_t)b * NOUT + tid] = sp[tid] + sp[128 + tid] + fcb[tid];
        __syncthreads();
    }
}

// ---------------------------------------------------------------------------
// Launch: exactly 6 launches so ncu (-s 5 -c 1) profiles the persistent kernel
// ---------------------------------------------------------------------------
extern "C" void kernel_launch(void* const* d_in, const int* in_sizes, int n_in,
                              void* d_out, int out_size)
{
    const float* x      = (const float*)d_in[0];
    const float* Wx     = (const float*)d_in[1];
    const float* Wh     = (const float*)d_in[2];
    const float* bias   = (const float*)d_in[3];
    const float* lnag   = (const float*)d_in[4];
    const float* lnab   = (const float*)d_in[5];
    const float* lng    = (const float*)d_in[6];
    const float* lnb    = (const float*)d_in[7];
    const float* zb     = (const float*)d_in[8];
    const float* zbeta  = (const float*)d_in[9];
    const float* zw_w   = (const float*)d_in[10];
    const float* zw_b   = (const float*)d_in[11];
    const float* alpha  = (const float*)d_in[12];
    const float* hypWx  = (const float*)d_in[13];
    const float* hypbx  = (const float*)d_in[14];
    const float* hypWh  = (const float*)d_in[15];
    const float* hypbh  = (const float*)d_in[16];
    const float* hlnag  = (const float*)d_in[17];
    const float* hlnab  = (const float*)d_in[18];
    const float* hlng   = (const float*)d_in[19];
    const float* hlnb   = (const float*)d_in[20];
    const float* fc_W   = (const float*)d_in[21];
    const float* fc_b   = (const float*)d_in[22];
    float* out = (float*)d_out;

    // #1 init
    init_k<<<(2 * B_ * HH4 + 255) / 256, 256>>>();
    // #2 all conversions + csc (largest range: T*B*D)
    setupAll_k<<<(int)(((size_t)T_ * B_ * D_ + 255) / 256), 256>>>(
        x, Wx, Wh, hypWx, hypWh, zw_b, alpha);
    // #3 Mcat (12 GEMMs fused via blockIdx.z)
    gemmAll_k<<<dim3(16, 2, 12), 256>>>(zw_w, zb, alpha, zbeta);
    // #4 [XW | hypX] = x @ W0^T on tensor cores
    xw_tensor_k<<<dim3(NREC / 64, (T_ * B_) / 128), NT_>>>();
    // #5 Mcat transpose to bf16 planes
    convMt_k<<<(int)(((size_t)MODN * HHYP + 255) / 256), 256>>>();
    // #6 persistent recurrence + final FC
    hyperlstm_persist<<<G_, NT_>>>(
        hypbx, hypbh, hlnag, hlnab, hlng, hlnb,
        bias, lnag, lnab, lng, lnb, fc_W, fc_b, out);
}

// round 17
// speedup vs baseline: 2.6115x; 1.0368x over previous
#include <cuda_runtime.h>
#include <cuda_bf16.h>
#include <math.h>
#include <stdint.h>

// ---------------------------------------------------------------------------
// Problem constants
// ---------------------------------------------------------------------------
#define T_ 512
#define B_ 128
#define D_ 256
#define H_ 1024      // main hidden
#define HHYP 256     // hyper hidden
#define H4 4096      // 4*H
#define HH4 1024     // 4*HHYP
#define NOUT 128
#define MODN 12288   // 8*H (sc) + 4*H (badj)
#define NREC 5120    // 4096 main rows + 1024 hyper rows
#define RECK 1280    // state length = H + HHYP
#define EPSLN 1e-3f

#define G_ 304       // launched CTAs (GB300: 152 SMs x 2); residency-oblivious
#define NT_ 256

// phase tiling (BM=128, BN=64; K processed in 32-wide chunks)
#define P1_HYPT 128            // 16 n-tiles * 8 k-splits (K=1024, 128/ticket)
#define P1_MAINT 128           // 64 n-tiles * 2 k-splits (K=1024, 512/ticket)
#define P1_TILES (P1_HYPT + P1_MAINT)
#define HYPS 8                 // hyper slabs
#define MAINS 2                // main slabs
#define P3_MODT 192            // 192 n-tiles, K=256 whole  (1 slab)
#define P3_RHHT 16             // 16 n-tiles, K=256 whole
#define P3_TILES (P3_MODT + P3_RHHT)
#define NPH 4

#define KP 40   // smem row pitch (bf16 elems); rows stride 20 banks -> LDSM conflict-free

// ---------------------------------------------------------------------------
// Device scratch
// ---------------------------------------------------------------------------
__device__ alignas(16) float g_XW[(size_t)T_ * B_ * H4];     // 1 GiB
__device__ alignas(16) float g_hypX[(size_t)T_ * B_ * HH4];  // 256 MiB
__device__ alignas(16) float g_Mcat[(size_t)HHYP * MODN];
__device__ alignas(16) float g_csc[8 * H_];
__device__ alignas(16) float g_state[B_ * RECK];             // fp32 [h | hyp]
__device__ alignas(16) float g_c[B_ * H_];
__device__ alignas(16) float g_ch[B_ * HHYP];
__device__ alignas(16) float g_recP1[(size_t)MAINS * B_ * H4];  // main slabs
__device__ alignas(16) float g_recHyp[(size_t)HYPS * B_ * HH4]; // hyper slabs
__device__ alignas(16) float g_modS[(size_t)B_ * MODN];      // single slab
__device__ alignas(16) float g_recHH[2 * B_ * HH4];          // parity double buffer

// bf16 hi/lo planes
__device__ alignas(16) __nv_bfloat16 g_sthi[B_ * RECK];
__device__ alignas(16) __nv_bfloat16 g_stlo[B_ * RECK];
__device__ alignas(16) __nv_bfloat16 g_W1hi[(size_t)NREC * H_];   // [n][k] packed Wh | hypWx_h
__device__ alignas(16) __nv_bfloat16 g_W1lo[(size_t)NREC * H_];
__device__ alignas(16) __nv_bfloat16 g_WHhi[(size_t)HH4 * HHYP];  // hypWh [n][k]
__device__ alignas(16) __nv_bfloat16 g_WHlo[(size_t)HH4 * HHYP];
__device__ alignas(16) __nv_bfloat16 g_Mthi[(size_t)MODN * HHYP]; // Mcat^T [n][k]
__device__ alignas(16) __nv_bfloat16 g_Mtlo[(size_t)MODN * HHYP];
__device__ alignas(16) __nv_bfloat16 g_xhi[(size_t)T_ * B_ * D_]; // x planes
__device__ alignas(16) __nv_bfloat16 g_xlo[(size_t)T_ * B_ * D_];
__device__ alignas(16) __nv_bfloat16 g_W0hi[(size_t)NREC * D_];   // [n][k] packed Wx | hypWx_x
__device__ alignas(16) __nv_bfloat16 g_W0lo[(size_t)NREC * D_];

// dataflow state
__device__ unsigned g_tix[T_ * NPH + 1];
__device__ unsigned g_done[T_ * NPH + 1];
__device__ unsigned g_doneH[T_];      // P1 hyper-tile completion (gates P2 early)

// ---------------------------------------------------------------------------
// Setup: split helper
// ---------------------------------------------------------------------------
__device__ __forceinline__ void split_bf16(float x, __nv_bfloat16& h, __nv_bfloat16& l)
{
    h = __float2bfloat16(x);
    l = __float2bfloat16(x - __bfloat162float(h));
}

// launch #1: zero state + counters
__global__ void init_k()
{
    size_t i = (size_t)blockIdx.x * 256 + threadIdx.x;
    if (i < (size_t)B_ * RECK) {
        g_state[i] = 0.f;
        g_sthi[i] = __float2bfloat16(0.f);
        g_stlo[i] = __float2bfloat16(0.f);
    }
    if (i < (size_t)B_ * H_)   g_c[i] = 0.f;
    if (i < (size_t)B_ * HHYP) g_ch[i] = 0.f;
    if (i < (size_t)2 * B_ * HH4) g_recHH[i] = 0.f;
    if (i < (size_t)(T_ * NPH + 1)) { g_tix[i] = 0u; g_done[i] = 0u; }
    if (i < (size_t)T_) g_doneH[i] = 0u;
}

// launch #2: all input conversions + csc, fused (all independent)
__global__ void setupAll_k(const float* __restrict__ x,
                           const float* __restrict__ Wx,
                           const float* __restrict__ Wh,
                           const float* __restrict__ hypWx,
                           const float* __restrict__ hypWh,
                           const float* __restrict__ zw_b,
                           const float* __restrict__ alpha)
{
    size_t i = (size_t)blockIdx.x * 256 + threadIdx.x;
    if (i < (size_t)T_ * B_ * D_)
        split_bf16(x[i], g_xhi[i], g_xlo[i]);
    if (i < (size_t)NREC * H_) {
        int n = (int)(i / H_), k = (int)(i % H_);
        float v = (n < H4) ? Wh[(size_t)n * H_ + k]
                           : hypWx[(size_t)(n - H4) * (D_ + H_) + D_ + k];
        split_bf16(v, g_W1hi[i], g_W1lo[i]);
    }
    if (i < (size_t)NREC * D_) {
        int n = (int)(i / D_), k = (int)(i % D_);
        float v = (n < H4) ? Wx[(size_t)n * D_ + k]
                           : hypWx[(size_t)(n - H4) * (D_ + H_) + k];
        split_bf16(v, g_W0hi[i], g_W0lo[i]);
    }
    if (i < (size_t)HH4 * HHYP)
        split_bf16(hypWh[i], g_WHhi[i], g_WHlo[i]);
    if (i < (size_t)(8 * H_)) {
        int k = (int)(i / H_), h = (int)(i % H_);
        float s = 0.f;
        const float* zb = zw_b + (size_t)k * HHYP;
        const float* al = alpha + (size_t)k * HHYP * H_;
        for (int p = 0; p < HHYP; p++) s = fmaf(zb[p], al[(size_t)p * H_ + h], s);
        g_csc[i] = s;
    }
}

// launch #3: Mcat = 12 fused GEMMs (256 x 1024 x 256) NN, z = which GEMM
__global__ __launch_bounds__(256) void gemmAll_k(
    const float* __restrict__ zw_w, const float* __restrict__ zb,
    const float* __restrict__ alpha, const float* __restrict__ zbeta)
{
    const int s = blockIdx.z;
    const float* A = (s < 8) ? zw_w + (size_t)s * HHYP * HHYP
                             : zb + (size_t)(s - 8) * HHYP * HHYP;
    const float* Bm = (s < 8) ? alpha + (size_t)s * HHYP * H_
                              : zbeta + (size_t)(s - 8) * HHYP * H_;
    float* C = g_Mcat + s * H_;
    const int lda = HHYP, ldb = H_, ldc = MODN;

    const int n0 = blockIdx.x * 64;
    const int m0 = blockIdx.y * 128;
    A += (size_t)m0 * lda;
    Bm += n0;
    C += (size_t)m0 * ldc + n0;

    __shared__ float As[16][132];
    __shared__ float Bs[16][68];
    const int tid = threadIdx.x;
    const int tx = tid % 16;
    const int ty = tid / 16;

    float acc[8][4];
#pragma unroll
    for (int i = 0; i < 8; i++)
#pragma unroll
        for (int j = 0; j < 4; j++) acc[i][j] = 0.f;

    for (int kt = 0; kt < HHYP; kt += 16) {
#pragma unroll
        for (int l = 0; l < 2; l++) {
            int idx = tid + l * 256;
            int r = idx / 4;
            int c4 = idx % 4;
            float4 v = *(const float4*)(A + (size_t)r * lda + c4 * 4);
            As[c4 * 4 + 0][r] = v.x; As[c4 * 4 + 1][r] = v.y;
            As[c4 * 4 + 2][r] = v.z; As[c4 * 4 + 3][r] = v.w;
        }
        {
            int r = tid / 16;
            int c4 = tid % 16;
            float4 v = *(const float4*)(Bm + (size_t)r * ldb + c4 * 4);
            *(float4*)&Bs[r][c4 * 4] = v;
        }
        __syncthreads();
#pragma unroll
        for (int k = 0; k < 16; k++) {
            float a[8], bv[4];
#pragma unroll
            for (int i = 0; i < 8; i += 4) {
                float4 v = *(const float4*)&As[k][ty * 8 + i];
                a[i] = v.x; a[i + 1] = v.y; a[i + 2] = v.z; a[i + 3] = v.w;
            }
            float4 vb = *(const float4*)&Bs[k][tx * 4];
            bv[0] = vb.x; bv[1] = vb.y; bv[2] = vb.z; bv[3] = vb.w;
#pragma unroll
            for (int i = 0; i < 8; i++)
#pragma unroll
                for (int j = 0; j < 4; j++)
                    acc[i][j] = fmaf(a[i], bv[j], acc[i][j]);
        }
        __syncthreads();
        A += 16;
        Bm += (size_t)16 * ldb;
    }
#pragma unroll
    for (int i = 0; i < 8; i++) {
        float4 o; o.x = acc[i][0]; o.y = acc[i][1]; o.z = acc[i][2]; o.w = acc[i][3];
        *(float4*)(C + (size_t)(ty * 8 + i) * ldc + tx * 4) = o;
    }
}

// launch #5: transpose Mcat -> [n][k] hi/lo planes
__global__ void convMt_k()
{
    size_t idx = (size_t)blockIdx.x * 256 + threadIdx.x;
    if (idx >= (size_t)MODN * HHYP) return;
    int n = (int)(idx / HHYP), k = (int)(idx % HHYP);
    split_bf16(g_Mcat[(size_t)k * MODN + n], g_Mthi[idx], g_Mtlo[idx]);
}

// ---------------------------------------------------------------------------
// Shared helpers
// ---------------------------------------------------------------------------
__device__ __forceinline__ float sigf(float x) { return 1.f / (1.f + expf(-x)); }

__device__ __forceinline__ float block_sum256(float v, float* sbuf)
{
    const int tid = threadIdx.x;
#pragma unroll
    for (int o = 16; o > 0; o >>= 1) v += __shfl_xor_sync(0xffffffffu, v, o);
    const int warp = tid >> 5, lane = tid & 31;
    if (lane == 0) sbuf[warp] = v;
    __syncthreads();
    float s = (tid < 8) ? sbuf[tid] : 0.f;
    if (warp == 0) {
#pragma unroll
        for (int o = 4; o > 0; o >>= 1) s += __shfl_xor_sync(0xffffffffu, s, o);
        if (lane == 0) sbuf[0] = s;
    }
    __syncthreads();
    float r = sbuf[0];
    __syncthreads();
    return r;
}

__device__ __forceinline__ int grab(unsigned* ctr, unsigned limit, unsigned* s_tile)
{
    __syncthreads();
    if (threadIdx.x == 0) *s_tile = atomicAdd(ctr, 1u);
    __syncthreads();
    unsigned k = *s_tile;
    return (k < limit) ? (int)k : -1;
}

__device__ __forceinline__ void mark(unsigned* cnt)
{
    __threadfence();
    __syncthreads();
    if (threadIdx.x == 0) atomicAdd(cnt, 1u);
}

__device__ __forceinline__ void gate(const unsigned* cnt, unsigned target)
{
    if (threadIdx.x == 0) {
        while (*(volatile const unsigned*)cnt < target) __nanosleep(64);
        __threadfence();
    }
    __syncthreads();
}

__device__ __forceinline__ void mma16816(float* d, const uint32_t* a, const uint32_t* b)
{
    asm volatile(
        "mma.sync.aligned.m16n8k16.row.col.f32.bf16.bf16.f32 "
        "{%0,%1,%2,%3}, {%4,%5,%6,%7}, {%8,%9}, {%0,%1,%2,%3};\n"
        : "+f"(d[0]), "+f"(d[1]), "+f"(d[2]), "+f"(d[3])
        : "r"(a[0]), "r"(a[1]), "r"(a[2]), "r"(a[3]), "r"(b[0]), "r"(b[1]));
}

__device__ __forceinline__ void ldsm_x4(uint32_t* r, uint32_t addr)
{
    asm volatile("ldmatrix.sync.aligned.m8n8.x4.shared.b16 {%0,%1,%2,%3}, [%4];"
                 : "=r"(r[0]), "=r"(r[1]), "=r"(r[2]), "=r"(r[3]) : "r"(addr));
}

// ---------------------------------------------------------------------------
// Tensor GEMM tile: C[128,64] = A[128,K] * B[64,K]^T, bf16 hi/lo x3 MMA.
// All fragments (A and B) loaded via ldmatrix.x4; the 8 LDSMs of each k-half
// are hoisted ahead of its 24 MMAs so loads overlap tensor work.
// K = nchunk*32; register-prefetch pipelined gmem->smem.
// ---------------------------------------------------------------------------
__device__ void ttile(
    __nv_bfloat16 (*sAh)[KP], __nv_bfloat16 (*sAl)[KP],
    __nv_bfloat16 (*sBh)[KP], __nv_bfloat16 (*sBl)[KP],
    const __nv_bfloat16* gAh, const __nv_bfloat16* gAl, int lda,
    const __nv_bfloat16* gBh, const __nv_bfloat16* gBl, int ldbk,
    float* C, int ldc, int nchunk)
{
    const int tid = threadIdx.x;
    const int lane = tid & 31, w = tid >> 5;
    const int wm = w & 3, wn = w >> 2;          // 4 warps M x 2 warps N
    const int g = lane >> 2, tig = lane & 3;

    const int ar = tid >> 2;            // A rows ar and ar+64 (gmem staging)
    const int ac = (tid & 3) * 8;       // col within 32-wide chunk
    const __nv_bfloat16* pAh0 = gAh + (size_t)ar * lda + ac;
    const __nv_bfloat16* pAh1 = gAh + (size_t)(ar + 64) * lda + ac;
    const __nv_bfloat16* pAl0 = gAl + (size_t)ar * lda + ac;
    const __nv_bfloat16* pAl1 = gAl + (size_t)(ar + 64) * lda + ac;
    const __nv_bfloat16* pBh  = gBh + (size_t)ar * ldbk + ac;   // B rows 0..63
    const __nv_bfloat16* pBl  = gBl + (size_t)ar * ldbk + ac;

    // A x4 lane map: row = wm*32 + ms*16 + (lane&15), col8 = (lane>>4)*8
    //   -> r0..r3 = a0..a3 of mma.m16n8k16
    const uint32_t aOff = ((wm * 32 + (lane & 15)) * KP + (lane >> 4) * 8) * 2;
    const uint32_t aAddrH = (uint32_t)__cvta_generic_to_shared(&sAh[0][0]) + aOff;
    const uint32_t aAddrL = (uint32_t)__cvta_generic_to_shared(&sAl[0][0]) + aOff;
    // B x4 lane map: row = wn*32 + nsPair*16 + ((lane>>4)&1)*8 + (lane&7),
    //   col8 = ((lane>>3)&1)*8  ->  r0,r1 = (ns even) b0,b1; r2,r3 = (ns odd)
    const uint32_t bOff = ((wn * 32 + ((lane >> 4) & 1) * 8 + (lane & 7)) * KP
                          + ((lane >> 3) & 1) * 8) * 2;
    const uint32_t bAddrH = (uint32_t)__cvta_generic_to_shared(&sBh[0][0]) + bOff;
    const uint32_t bAddrL = (uint32_t)__cvta_generic_to_shared(&sBl[0][0]) + bOff;

    float acc[2][4][4];
#pragma unroll
    for (int ms = 0; ms < 2; ms++)
#pragma unroll
        for (int ns = 0; ns < 4; ns++)
#pragma unroll
            for (int q = 0; q < 4; q++) acc[ms][ns][q] = 0.f;

    uint4 ra_h0 = __ldcg((const uint4*)pAh0);
    uint4 ra_h1 = __ldcg((const uint4*)pAh1);
    uint4 ra_l0 = __ldcg((const uint4*)pAl0);
    uint4 ra_l1 = __ldcg((const uint4*)pAl1);
    uint4 rb_h  = *(const uint4*)pBh;
    uint4 rb_l  = *(const uint4*)pBl;

    for (int ch = 0; ch < nchunk; ch++) {
        *(uint4*)&sAh[ar][ac]      = ra_h0;
        *(uint4*)&sAh[ar + 64][ac] = ra_h1;
        *(uint4*)&sAl[ar][ac]      = ra_l0;
        *(uint4*)&sAl[ar + 64][ac] = ra_l1;
        *(uint4*)&sBh[ar][ac]      = rb_h;
        *(uint4*)&sBl[ar][ac]      = rb_l;
        __syncthreads();

        if (ch + 1 < nchunk) {
            int kb = (ch + 1) * 32;
            ra_h0 = __ldcg((const uint4*)(pAh0 + kb));
            ra_h1 = __ldcg((const uint4*)(pAh1 + kb));
            ra_l0 = __ldcg((const uint4*)(pAl0 + kb));
            ra_l1 = __ldcg((const uint4*)(pAl1 + kb));
            rb_h  = *(const uint4*)(pBh + kb);
            rb_l  = *(const uint4*)(pBl + kb);
        }

#pragma unroll
        for (int kk = 0; kk < 2; kk++) {
            const uint32_t kOff = kk * 16 * 2;   // 16 bf16 = 32 bytes
            // ---- hoisted fragment loads: 8 independent LDSM.x4 ----
            uint32_t ah[2][4], al[2][4], bh2[2][4], bl2[2][4];
#pragma unroll
            for (int ms = 0; ms < 2; ms++) {
                const uint32_t rOff = ms * 16 * KP * 2;
                ldsm_x4(ah[ms], aAddrH + rOff + kOff);
                ldsm_x4(al[ms], aAddrL + rOff + kOff);
            }
#pragma unroll
            for (int np = 0; np < 2; np++) {
                const uint32_t rOff = np * 16 * KP * 2;
                ldsm_x4(bh2[np], bAddrH + rOff + kOff);
                ldsm_x4(bl2[np], bAddrL + rOff + kOff);
            }
            // ---- 24 MMAs ----
#pragma unroll
            for (int np = 0; np < 2; np++) {
#pragma unroll
                for (int h2 = 0; h2 < 2; h2++) {
                    const int ns = np * 2 + h2;
                    const uint32_t* bhp = &bh2[np][h2 * 2];
                    const uint32_t* blp = &bl2[np][h2 * 2];
#pragma unroll
                    for (int ms = 0; ms < 2; ms++) {
                        mma16816(acc[ms][ns], ah[ms], bhp);
                        mma16816(acc[ms][ns], ah[ms], blp);
                        mma16816(acc[ms][ns], al[ms], bhp);
                    }
                }
            }
        }
        __syncthreads();
    }

#pragma unroll
    for (int ms = 0; ms < 2; ms++) {
#pragma unroll
        for (int ns = 0; ns < 4; ns++) {
            int row0 = wm * 32 + ms * 16 + g;
            int col = wn * 32 + ns * 8 + tig * 2;
            float2 v0; v0.x = acc[ms][ns][0]; v0.y = acc[ms][ns][1];
            float2 v1; v1.x = acc[ms][ns][2]; v1.y = acc[ms][ns][3];
            *(float2*)&C[(size_t)row0 * ldc + col] = v0;
            *(float2*)&C[(size_t)(row0 + 8) * ldc + col] = v1;
        }
    }
}

// launch #4: [XW | hypX] = x @ W0^T  (M=65536, N=5120, K=256)
__global__ __launch_bounds__(NT_) void xw_tensor_k()
{
    __shared__ __align__(16) __nv_bfloat16 sAh[128][KP];
    __shared__ __align__(16) __nv_bfloat16 sAl[128][KP];
    __shared__ __align__(16) __nv_bfloat16 sBh[64][KP];
    __shared__ __align__(16) __nv_bfloat16 sBl[64][KP];

    const int n0 = blockIdx.x * 64;
    const size_t m0 = (size_t)blockIdx.y * 128;
    float* C;
    int ldc;
    if (n0 < H4) { C = g_XW + m0 * H4 + n0; ldc = H4; }
    else         { C = g_hypX + m0 * HH4 + (n0 - H4); ldc = HH4; }
    ttile(sAh, sAl, sBh, sBl,
          g_xhi + m0 * D_, g_xlo + m0 * D_, D_,
          g_W0hi + (size_t)n0 * D_, g_W0lo + (size_t)n0 * D_, D_,
          C, ldc, 8);
}

// ---------------------------------------------------------------------------
// launch #6: persistent kernel — whole T=512 recurrence + final FC.
// ---------------------------------------------------------------------------
__global__ __launch_bounds__(NT_, 2) void hyperlstm_persist(
    const float* __restrict__ hypbx, const float* __restrict__ hypbh,
    const float* __restrict__ hlnag, const float* __restrict__ hlnab,
    const float* __restrict__ hlng, const float* __restrict__ hlnb,
    const float* __restrict__ bias,
    const float* __restrict__ lnag, const float* __restrict__ lnab,
    const float* __restrict__ lng, const float* __restrict__ lnb,
    const float* __restrict__ fcW, const float* __restrict__ fcb,
    float* __restrict__ out)
{
    __shared__ __align__(16) __nv_bfloat16 sAh[128][KP];
    __shared__ __align__(16) __nv_bfloat16 sAl[128][KP];
    __shared__ __align__(16) __nv_bfloat16 sBh[64][KP];
    __shared__ __align__(16) __nv_bfloat16 sBl[64][KP];
    __shared__ float sred[32];
    __shared__ unsigned s_tile;

    const int tid = threadIdx.x;

    for (int t = 0; t < T_; t++) {
        unsigned* tixP1 = &g_tix[t * NPH + 0];
        unsigned* tixP2 = &g_tix[t * NPH + 1];
        unsigned* tixP3 = &g_tix[t * NPH + 2];
        unsigned* tixP4 = &g_tix[t * NPH + 3];
        unsigned* donP1 = &g_done[t * NPH + 0];
        unsigned* donP2 = &g_done[t * NPH + 1];
        unsigned* donP3 = &g_done[t * NPH + 2];
        unsigned* donP4 = &g_done[t * NPH + 3];

        // ----- P1: rec GEMM from h (hyper tiles first, K=128 each) -----
        if (t > 0) gate(&g_done[(t - 1) * NPH + 3], B_);
        for (;;) {
            int k = grab(tixP1, P1_TILES, &s_tile);
            if (k < 0) break;
            bool hyp_tile = (k < P1_HYPT);
            if (hyp_tile) {
                int nt = k >> 3, ks = k & 7;
                int n0 = nt * 64, kb = ks * 128;
                ttile(sAh, sAl, sBh, sBl,
                      g_sthi + kb, g_stlo + kb, RECK,
                      g_W1hi + (size_t)(H4 + n0) * H_ + kb,
                      g_W1lo + (size_t)(H4 + n0) * H_ + kb, H_,
                      g_recHyp + (size_t)ks * (B_ * HH4) + n0, HH4, 4);
            } else {
                int k2 = k - P1_HYPT;
                int nt = k2 >> 1, ks = k2 & 1;
                int n0 = nt * 64, kb = ks * 512;
                ttile(sAh, sAl, sBh, sBl,
                      g_sthi + kb, g_stlo + kb, RECK,
                      g_W1hi + (size_t)n0 * H_ + kb,
                      g_W1lo + (size_t)n0 * H_ + kb, H_,
                      g_recP1 + (size_t)ks * (B_ * H4) + n0, H4, 16);
            }
            __threadfence();
            __syncthreads();
            if (tid == 0) {
                atomicAdd(donP1, 1u);
                if (hyp_tile) atomicAdd(&g_doneH[t], 1u);
            }
        }

        // ----- P2: hyper cell (gates only on the 128 hyper tiles) -----
        gate(&g_doneH[t], P1_HYPT);
        for (;;) {
            int b = grab(tixP2, B_, &s_tile);
            if (b < 0) break;
            const int j = tid;
            const int par = t & 1;
            const float* hx = g_hypX + ((size_t)t * B_ + b) * HH4;
            float v[4];
#pragma unroll
            for (int gk = 0; gk < 4; gk++) {
                int n = gk * HHYP + j;
                float s = hx[n] + hypbx[n] + hypbh[n];
#pragma unroll
                for (int sl = 0; sl < HYPS; sl++)
                    s += __ldcg(&g_recHyp[(size_t)sl * (B_ * HH4) + (size_t)b * HH4 + n]);
                s += __ldcg(&g_recHH[(size_t)par * (B_ * HH4) + (size_t)b * HH4 + n]);
                v[gk] = s;
            }
            float nv[4];
#pragma unroll
            for (int gk = 0; gk < 4; gk++) {
                float m = block_sum256(v[gk], sred) * (1.f / 256.f);
                float xs = v[gk] - m;
                float var = block_sum256(xs * xs, sred) * (1.f / 256.f);
                int n = gk * HHYP + j;
                nv[gk] = hlnag[n] * (xs * rsqrtf(var + EPSLN)) + hlnab[n];
            }
            float ch = __ldcg(&g_ch[b * HHYP + j]);
            float chn = sigf(nv[1]) * ch + sigf(nv[0]) * tanhf(nv[2]);
            float m = block_sum256(chn, sred) * (1.f / 256.f);
            float xs = chn - m;
            float var = block_sum256(xs * xs, sred) * (1.f / 256.f);
            float hn = hlng[j] * (xs * rsqrtf(var + EPSLN)) + hlnb[j];
            float hyp = sigf(nv[3]) * tanhf(hn);
            g_ch[b * HHYP + j] = chn;
            size_t sidx = (size_t)b * RECK + H_ + j;
            g_state[sidx] = hyp;
            __nv_bfloat16 hh, hl; split_bf16(hyp, hh, hl);
            g_sthi[sidx] = hh; g_stlo[sidx] = hl;
            mark(donP2);
        }
        gate(donP2, B_);

        // ----- P3: mod GEMM (K=256 whole) + next-step rec-hh -----
        {
            const int parN = (t + 1) & 1;
            for (;;) {
                int k = grab(tixP3, P3_TILES, &s_tile);
                if (k < 0) break;
                if (k < P3_MODT) {
                    int n0 = k * 64;
                    ttile(sAh, sAl, sBh, sBl,
                          g_sthi + H_, g_stlo + H_, RECK,
                          g_Mthi + (size_t)n0 * HHYP, g_Mtlo + (size_t)n0 * HHYP, HHYP,
                          g_modS + n0, MODN, 8);
                } else {
                    int n0 = (k - P3_MODT) * 64;
                    ttile(sAh, sAl, sBh, sBl,
                          g_sthi + H_, g_stlo + H_, RECK,
                          g_WHhi + (size_t)n0 * HHYP, g_WHlo + (size_t)n0 * HHYP, HHYP,
                          g_recHH + (size_t)parN * (B_ * HH4) + n0, HH4, 8);
                }
                mark(donP3);
            }
        }
        gate(donP3, P3_TILES);
        gate(donP1, P1_TILES);   // P4 needs the main-row slabs too

        // ----- P4: main cell -----
        for (;;) {
            int b = grab(tixP4, B_, &s_tile);
            if (b < 0) break;
            const int j = tid;
            const float* xw = g_XW + ((size_t)t * B_ + b) * H4;
            const float* mp = g_modS + (size_t)b * MODN;
            float pre[4][4];
#pragma unroll
            for (int gk = 0; gk < 4; gk++) {
#pragma unroll
                for (int q = 0; q < 4; q++) {
                    int n = gk * H_ + q * 256 + j;
                    float hg = __ldcg(&g_recP1[(size_t)b * H4 + n])
                             + __ldcg(&g_recP1[(size_t)(B_ * H4) + (size_t)b * H4 + n]);
                    float sx = __ldcg(&mp[n]) + g_csc[n];
                    float sh = __ldcg(&mp[4 * H_ + n]) + g_csc[4 * H_ + n];
                    float ba = __ldcg(&mp[8 * H_ + n]);
                    pre[gk][q] = fmaf(sx, xw[n], fmaf(sh, hg, bias[n] + ba));
                }
            }
            float nv[4][4];
#pragma unroll
            for (int gk = 0; gk < 4; gk++) {
                float p = pre[gk][0] + pre[gk][1] + pre[gk][2] + pre[gk][3];
                float m = block_sum256(p, sred) * (1.f / 1024.f);
                float vs = 0.f;
#pragma unroll
                for (int q = 0; q < 4; q++) { float d = pre[gk][q] - m; vs += d * d; }
                float var = block_sum256(vs, sred) * (1.f / 1024.f);
                float rs = rsqrtf(var + EPSLN);
#pragma unroll
                for (int q = 0; q < 4; q++) {
                    int n = gk * H_ + q * 256 + j;
                    nv[gk][q] = lnag[n] * ((pre[gk][q] - m) * rs) + lnab[n];
                }
            }
            float cn[4];
            float psum = 0.f;
#pragma unroll
            for (int q = 0; q < 4; q++) {
                int idx = q * 256 + j;
                float c = __ldcg(&g_c[b * H_ + idx]);
                cn[q] = sigf(nv[2][q]) * c + sigf(nv[0][q]) * tanhf(nv[1][q]);
                g_c[b * H_ + idx] = cn[q];
                psum += cn[q];
            }
            float m = block_sum256(psum, sred) * (1.f / 1024.f);
            float vs = 0.f;
#pragma unroll
            for (int q = 0; q < 4; q++) { float d = cn[q] - m; vs += d * d; }
            float var = block_sum256(vs, sred) * (1.f / 1024.f);
            float rs = rsqrtf(var + EPSLN);
#pragma unroll
            for (int q = 0; q < 4; q++) {
                int idx = q * 256 + j;
                float lc = lng[idx] * ((cn[q] - m) * rs) + lnb[idx];
                float h = sigf(nv[3][q]) * tanhf(lc);
                size_t sidx = (size_t)b * RECK + idx;
                g_state[sidx] = h;
                __nv_bfloat16 hh, hl; split_bf16(h, hh, hl);
                g_sthi[sidx] = hh; g_stlo[sidx] = hl;
            }
            mark(donP4);
        }
    }

    // ----- final FC: out = h @ fcW^T + fcb -----
    gate(&g_done[(T_ - 1) * NPH + 3], B_);
    for (;;) {
        int b = grab(&g_tix[T_ * NPH], B_, &s_tile);
        if (b < 0) break;
        float* sh = (float*)&sAh[0][0];   // 1024 floats fit in 10240-byte buffer
        float* sp = (float*)&sBh[0][0];   // 256 floats fit in 5120-byte buffer
        for (int i = tid; i < H_; i += NT_) sh[i] = __ldcg(&g_state[(size_t)b * RECK + i]);
        __syncthreads();
        int o = tid & 127, half = tid >> 7;
        const float* w = fcW + (size_t)o * H_ + half * 512;
        const float* hv = sh + half * 512;
        float s = 0.f;
        for (int k = 0; k < 512; k++) s = fmaf(hv[k], w[k], s);
        sp[tid] = s;
        __syncthreads();
        if (tid < NOUT)
            out[(size_t)b * NOUT + tid] = sp[tid] + sp[128 + tid] + fcb[tid];
        __syncthreads();
    }
}

// ---------------------------------------------------------------------------
// Launch: exactly 6 launches so ncu (-s 5 -c 1) profiles the persistent kernel
// ---------------------------------------------------------------------------
extern "C" void kernel_launch(void* const* d_in, const int* in_sizes, int n_in,
                              void* d_out, int out_size)
{
    const float* x      = (const float*)d_in[0];
    const float* Wx     = (const float*)d_in[1];
    const float* Wh     = (const float*)d_in[2];
    const float* bias   = (const float*)d_in[3];
    const float* lnag   = (const float*)d_in[4];
    const float* lnab   = (const float*)d_in[5];
    const float* lng    = (const float*)d_in[6];
    const float* lnb    = (const float*)d_in[7];
    const float* zb     = (const float*)d_in[8];
    const float* zbeta  = (const float*)d_in[9];
    const float* zw_w   = (const float*)d_in[10];
    const float* zw_b   = (const float*)d_in[11];
    const float* alpha  = (const float*)d_in[12];
    const float* hypWx  = (const float*)d_in[13];
    const float* hypbx  = (const float*)d_in[14];
    const float* hypWh  = (const float*)d_in[15];
    const float* hypbh  = (const float*)d_in[16];
    const float* hlnag  = (const float*)d_in[17];
    const float* hlnab  = (const float*)d_in[18];
    const float* hlng   = (const float*)d_in[19];
    const float* hlnb   = (const float*)d_in[20];
    const float* fc_W   = (const float*)d_in[21];
    const float* fc_b   = (const float*)d_in[22];
    float* out = (float*)d_out;

    // #1 init
    init_k<<<(2 * B_ * HH4 + 255) / 256, 256>>>();
    // #2 all conversions + csc (largest range: T*B*D)
    setupAll_k<<<(int)(((size_t)T_ * B_ * D_ + 255) / 256), 256>>>(
        x, Wx, Wh, hypWx, hypWh, zw_b, alpha);
    // #3 Mcat (12 GEMMs fused via blockIdx.z)
    gemmAll_k<<<dim3(16, 2, 12), 256>>>(zw_w, zb, alpha, zbeta);
    // #4 [XW | hypX] = x @ W0^T on tensor cores
    xw_tensor_k<<<dim3(NREC / 64, (T_ * B_) / 128), NT_>>>();
    // #5 Mcat transpose to bf16 planes
    convMt_k<<<(int)(((size_t)MODN * HHYP + 255) / 256), 256>>>();
    // #6 persistent recurrence + final FC
    hyperlstm_persist<<<G_, NT_>>>(
        hypbx, hypbh, hlnag, hlnab, hlng, hlnb,
        bias, lnag, lnab, lng, lnb, fc_W, fc_b, out);
}